// round 1
// baseline (speedup 1.0000x reference)
#include <cuda_runtime.h>
#include <math.h>

#define EMB 1024
#define SEQ 2048
#define BATCH 2
#define ROWS (BATCH*SEQ)   /* 4096 */
#define DFF (4*EMB)        /* 4096 */
#define NHEADS 16
#define HD 64
#define BQ 64
#define BKV 32

// ---------------- scratch (device globals: no allocation allowed) ----------------
__device__ float g_ln1[ROWS*EMB];
__device__ float g_q  [ROWS*EMB];
__device__ float g_k  [ROWS*EMB];
__device__ float g_v  [ROWS*EMB];
__device__ float g_ctx[ROWS*EMB];
__device__ float g_h  [ROWS*EMB];
__device__ float g_y  [ROWS*EMB];
__device__ float g_ff [ROWS*DFF];

// ---------------- layernorm ----------------
__global__ __launch_bounds__(256) void ln_kernel(const float* __restrict__ x,
    const float* __restrict__ g, const float* __restrict__ s, float* __restrict__ o)
{
    __shared__ float red[16];
    int row = blockIdx.x;
    int t = threadIdx.x;
    const float4* xr = reinterpret_cast<const float4*>(x + (size_t)row*EMB);
    float4 v = xr[t];
    float sum = v.x+v.y+v.z+v.w;
    float sq  = v.x*v.x+v.y*v.y+v.z*v.z+v.w*v.w;
    #pragma unroll
    for (int off = 16; off > 0; off >>= 1) {
        sum += __shfl_xor_sync(0xffffffffu, sum, off);
        sq  += __shfl_xor_sync(0xffffffffu, sq,  off);
    }
    int warp = t >> 5, lane = t & 31;
    if (lane == 0) { red[warp] = sum; red[warp+8] = sq; }
    __syncthreads();
    if (t < 32) {
        float a  = (lane < 8) ? red[lane]   : 0.0f;
        float b2 = (lane < 8) ? red[lane+8] : 0.0f;
        #pragma unroll
        for (int off = 4; off > 0; off >>= 1) {
            a  += __shfl_xor_sync(0xffffffffu, a,  off);
            b2 += __shfl_xor_sync(0xffffffffu, b2, off);
        }
        if (lane == 0) { red[0] = a; red[1] = b2; }
    }
    __syncthreads();
    float mean = red[0] * (1.0f/EMB);
    float var  = red[1] * (1.0f/EMB) - mean*mean;
    float inv  = rsqrtf(var + 1e-5f);
    float4 gv = reinterpret_cast<const float4*>(g)[t];
    float4 sv = reinterpret_cast<const float4*>(s)[t];
    float4 ov;
    ov.x = (v.x - mean)*inv*gv.x + sv.x;
    ov.y = (v.y - mean)*inv*gv.y + sv.y;
    ov.z = (v.z - mean)*inv*gv.z + sv.z;
    ov.w = (v.w - mean)*inv*gv.w + sv.w;
    reinterpret_cast<float4*>(o + (size_t)row*EMB)[t] = ov;
}

// ---------------- gelu ----------------
__device__ __forceinline__ float gelu_f(float x)
{
    float u = 0.7978845608028654f * (x + 0.044715f * x * x * x);
    return 0.5f * x * (1.0f + tanhf(u));
}

// ---------------- SGEMM: C[M,N] = A[M,K] @ B[K,N] (+bias)(gelu)(+res) ----------------
__global__ __launch_bounds__(256) void sgemm_kernel(
    const float* __restrict__ A, const float* __restrict__ B,
    const float* __restrict__ bias, const float* __restrict__ res,
    float* __restrict__ C, int M, int N, int K, int dogelu)
{
    __shared__ float As[16][128];
    __shared__ float Bs[16][128];
    int t  = threadIdx.x;
    int tx = t & 15, ty = t >> 4;
    int bx = blockIdx.x, by = blockIdx.y;

    const float* Ab = A + (size_t)(by*128)*K;
    const float* Bb = B + (size_t)(bx*128);

    int arow = t >> 2,  ac = (t & 3)  << 2;   // A: 128 rows x 16 cols
    int brow = t >> 5,  bc = (t & 31) << 2;   // B: 16 rows x 128 cols

    float acc[8][8];
    #pragma unroll
    for (int i = 0; i < 8; i++)
        #pragma unroll
        for (int j = 0; j < 8; j++) acc[i][j] = 0.0f;

    for (int kt = 0; kt < K; kt += 16) {
        float4 a0 = *(const float4*)(Ab + (size_t)arow*K      + kt + ac);
        float4 a1 = *(const float4*)(Ab + (size_t)(arow+64)*K + kt + ac);
        float4 b0 = *(const float4*)(Bb + (size_t)(kt+brow)*N   + bc);
        float4 b1 = *(const float4*)(Bb + (size_t)(kt+brow+8)*N + bc);
        As[ac+0][arow] = a0.x; As[ac+1][arow] = a0.y; As[ac+2][arow] = a0.z; As[ac+3][arow] = a0.w;
        As[ac+0][arow+64] = a1.x; As[ac+1][arow+64] = a1.y; As[ac+2][arow+64] = a1.z; As[ac+3][arow+64] = a1.w;
        *(float4*)&Bs[brow  ][bc] = b0;
        *(float4*)&Bs[brow+8][bc] = b1;
        __syncthreads();
        #pragma unroll
        for (int k = 0; k < 16; k++) {
            float a[8], b[8];
            *(float4*)&a[0] = *(const float4*)&As[k][ty*4];
            *(float4*)&a[4] = *(const float4*)&As[k][64 + ty*4];
            *(float4*)&b[0] = *(const float4*)&Bs[k][tx*4];
            *(float4*)&b[4] = *(const float4*)&Bs[k][64 + tx*4];
            #pragma unroll
            for (int i = 0; i < 8; i++)
                #pragma unroll
                for (int j = 0; j < 8; j++)
                    acc[i][j] = fmaf(a[i], b[j], acc[i][j]);
        }
        __syncthreads();
    }

    #pragma unroll
    for (int i = 0; i < 8; i++) {
        int row = by*128 + ((i < 4) ? (ty*4 + i) : (64 + ty*4 + i - 4));
        #pragma unroll
        for (int half = 0; half < 2; half++) {
            int col = bx*128 + half*64 + tx*4;
            float4 r;
            r.x = acc[i][half*4+0]; r.y = acc[i][half*4+1];
            r.z = acc[i][half*4+2]; r.w = acc[i][half*4+3];
            if (bias) {
                float4 bb = *(const float4*)(bias + col);
                r.x += bb.x; r.y += bb.y; r.z += bb.z; r.w += bb.w;
            }
            if (dogelu) {
                r.x = gelu_f(r.x); r.y = gelu_f(r.y);
                r.z = gelu_f(r.z); r.w = gelu_f(r.w);
            }
            if (res) {
                float4 rr = *(const float4*)(res + (size_t)row*N + col);
                r.x += rr.x; r.y += rr.y; r.z += rr.z; r.w += rr.w;
            }
            *(float4*)(C + (size_t)row*N + col) = r;
        }
    }
}

// ---------------- causal flash attention (fp32) ----------------
// Q,K,V laid out [b, s, d] with head h occupying cols h*64..h*64+63.
// Grid: (SEQ/BQ, BATCH*NHEADS). Block: 256 threads.
__global__ __launch_bounds__(256) void attn_kernel(
    const float* __restrict__ Qg, const float* __restrict__ Kg,
    const float* __restrict__ Vg, float* __restrict__ Og)
{
    __shared__ float QsT[64][68];   // [d][r]
    __shared__ float KsT[64][34];   // [d][k]
    __shared__ float Vs [32][64];   // [k][d]
    __shared__ float Ss [64][33];   // [r][k] scores -> probs
    __shared__ float rowScale[64];
    __shared__ float rowLinv [64];

    int t = threadIdx.x;
    int qt = blockIdx.x, bh = blockIdx.y;
    int b = bh >> 4, h = bh & 15;
    size_t base = ((size_t)b*SEQ)*EMB + (size_t)h*HD;
    int q0 = qt * BQ;

    int tx = t & 15, ty = t >> 4;   // S-gemm (rows ty*4.., cols tx*2..) & O (rows ty*4.., cols tx*4..)
    int warp = t >> 5, lane = t & 31;

    // load Q tile transposed
    #pragma unroll
    for (int i = 0; i < 4; i++) {
        int fid = t + 256*i;
        int r = fid >> 4, d4 = (fid & 15) << 2;
        float4 qv = *(const float4*)(Qg + base + (size_t)(q0 + r)*EMB + d4);
        QsT[d4+0][r] = qv.x; QsT[d4+1][r] = qv.y;
        QsT[d4+2][r] = qv.z; QsT[d4+3][r] = qv.w;
    }

    float m[8], l[8];
    #pragma unroll
    for (int i = 0; i < 8; i++) { m[i] = -1e30f; l[i] = 0.0f; }
    float acc[4][4];
    #pragma unroll
    for (int i = 0; i < 4; i++)
        #pragma unroll
        for (int j = 0; j < 4; j++) acc[i][j] = 0.0f;

    int nkt = 2*qt + 2;
    for (int kt = 0; kt < nkt; kt++) {
        int k0 = kt * BKV;
        // load K (transposed) and V tiles
        #pragma unroll
        for (int i = 0; i < 2; i++) {
            int fid = t + 256*i;
            int kk = fid >> 4, d4 = (fid & 15) << 2;
            float4 kv = *(const float4*)(Kg + base + (size_t)(k0 + kk)*EMB + d4);
            KsT[d4+0][kk] = kv.x; KsT[d4+1][kk] = kv.y;
            KsT[d4+2][kk] = kv.z; KsT[d4+3][kk] = kv.w;
            float4 vv = *(const float4*)(Vg + base + (size_t)(k0 + kk)*EMB + d4);
            *(float4*)&Vs[kk][d4] = vv;
        }
        __syncthreads();

        // S = Q @ K^T : each thread 4 rows x 2 cols
        {
            float s[4][2];
            #pragma unroll
            for (int i = 0; i < 4; i++) { s[i][0] = 0.0f; s[i][1] = 0.0f; }
            #pragma unroll 4
            for (int d = 0; d < 64; d++) {
                float4 a = *(const float4*)&QsT[d][ty*4];
                float2 bb = *(const float2*)&KsT[d][tx*2];
                s[0][0] = fmaf(a.x, bb.x, s[0][0]); s[0][1] = fmaf(a.x, bb.y, s[0][1]);
                s[1][0] = fmaf(a.y, bb.x, s[1][0]); s[1][1] = fmaf(a.y, bb.y, s[1][1]);
                s[2][0] = fmaf(a.z, bb.x, s[2][0]); s[2][1] = fmaf(a.z, bb.y, s[2][1]);
                s[3][0] = fmaf(a.w, bb.x, s[3][0]); s[3][1] = fmaf(a.w, bb.y, s[3][1]);
            }
            #pragma unroll
            for (int i = 0; i < 4; i++) {
                Ss[ty*4+i][tx*2+0] = s[i][0];
                Ss[ty*4+i][tx*2+1] = s[i][1];
            }
        }
        __syncthreads();

        // online softmax: warp w owns rows w*8 .. w*8+7; lane = key index
        #pragma unroll
        for (int i = 0; i < 8; i++) {
            int r  = warp*8 + i;
            int qg = q0 + r;
            int kg = k0 + lane;
            float sv = Ss[r][lane] * 0.125f;   // 1/sqrt(64)
            if (kg > qg) sv = -1e30f;
            float rmax = sv;
            #pragma unroll
            for (int off = 16; off > 0; off >>= 1)
                rmax = fmaxf(rmax, __shfl_xor_sync(0xffffffffu, rmax, off));
            float mn = fmaxf(m[i], rmax);
            float p  = __expf(sv - mn);
            float rs = p;
            #pragma unroll
            for (int off = 16; off > 0; off >>= 1)
                rs += __shfl_xor_sync(0xffffffffu, rs, off);
            float alpha = __expf(m[i] - mn);
            l[i] = l[i]*alpha + rs;
            m[i] = mn;
            Ss[r][lane] = p;
            if (lane == 0) rowScale[r] = alpha;
        }
        __syncthreads();

        // O += P @ V : each thread 4 rows x 4 cols
        #pragma unroll
        for (int i = 0; i < 4; i++) {
            float sc = rowScale[ty*4+i];
            #pragma unroll
            for (int j = 0; j < 4; j++) acc[i][j] *= sc;
        }
        #pragma unroll 4
        for (int kk = 0; kk < 32; kk++) {
            float4 vv = *(const float4*)&Vs[kk][tx*4];
            #pragma unroll
            for (int i = 0; i < 4; i++) {
                float p = Ss[ty*4+i][kk];
                acc[i][0] = fmaf(p, vv.x, acc[i][0]);
                acc[i][1] = fmaf(p, vv.y, acc[i][1]);
                acc[i][2] = fmaf(p, vv.z, acc[i][2]);
                acc[i][3] = fmaf(p, vv.w, acc[i][3]);
            }
        }
        __syncthreads();
    }

    if (lane == 0) {
        #pragma unroll
        for (int i = 0; i < 8; i++) rowLinv[warp*8 + i] = 1.0f / l[i];
    }
    __syncthreads();

    #pragma unroll
    for (int i = 0; i < 4; i++) {
        int r = ty*4 + i;
        float linv = rowLinv[r];
        float4 o;
        o.x = acc[i][0]*linv; o.y = acc[i][1]*linv;
        o.z = acc[i][2]*linv; o.w = acc[i][3]*linv;
        *(float4*)(Og + base + (size_t)(q0 + r)*EMB + tx*4) = o;
    }
}

// ---------------- launch ----------------
extern "C" void kernel_launch(void* const* d_in, const int* in_sizes, int n_in,
                              void* d_out, int out_size)
{
    const float* x  = (const float*)d_in[0];
    const float* Wq = (const float*)d_in[1];
    const float* Wk = (const float*)d_in[2];
    const float* Wv = (const float*)d_in[3];
    const float* Wo = (const float*)d_in[4];
    const float* bo = (const float*)d_in[5];
    const float* W1 = (const float*)d_in[6];
    const float* b1 = (const float*)d_in[7];
    const float* W2 = (const float*)d_in[8];
    const float* b2 = (const float*)d_in[9];
    const float* g1 = (const float*)d_in[10];
    const float* s1 = (const float*)d_in[11];
    const float* g2 = (const float*)d_in[12];
    const float* s2 = (const float*)d_in[13];
    float* out = (float*)d_out;

    float *ln1, *q, *k, *v, *ctx, *h, *y, *ff;
    cudaGetSymbolAddress((void**)&ln1, g_ln1);
    cudaGetSymbolAddress((void**)&q,   g_q);
    cudaGetSymbolAddress((void**)&k,   g_k);
    cudaGetSymbolAddress((void**)&v,   g_v);
    cudaGetSymbolAddress((void**)&ctx, g_ctx);
    cudaGetSymbolAddress((void**)&h,   g_h);
    cudaGetSymbolAddress((void**)&y,   g_y);
    cudaGetSymbolAddress((void**)&ff,  g_ff);

    dim3 blk(256);
    dim3 gEmb(EMB/128, ROWS/128);   // (8, 32)
    dim3 gFF (DFF/128, ROWS/128);   // (32, 32)

    // ln1 = LN(x)
    ln_kernel<<<ROWS, blk>>>(x, g1, s1, ln1);
    // q/k/v = ln1 @ W{q,k,v}
    sgemm_kernel<<<gEmb, blk>>>(ln1, Wq, nullptr, nullptr, q, ROWS, EMB, EMB, 0);
    sgemm_kernel<<<gEmb, blk>>>(ln1, Wk, nullptr, nullptr, k, ROWS, EMB, EMB, 0);
    sgemm_kernel<<<gEmb, blk>>>(ln1, Wv, nullptr, nullptr, v, ROWS, EMB, EMB, 0);
    // ctx = causal softmax(qk^T/8) v
    attn_kernel<<<dim3(SEQ/BQ, BATCH*NHEADS), blk>>>(q, k, v, ctx);
    // h = x + ctx @ Wo + bo
    sgemm_kernel<<<gEmb, blk>>>(ctx, Wo, bo, x, h, ROWS, EMB, EMB, 0);
    // y = LN(h)
    ln_kernel<<<ROWS, blk>>>(h, g2, s2, y);
    // ff = gelu(y @ W1 + b1)
    sgemm_kernel<<<gFF, blk>>>(y, W1, b1, nullptr, ff, ROWS, DFF, EMB, 1);
    // out = h + ff @ W2 + b2
    sgemm_kernel<<<gEmb, blk>>>(ff, W2, b2, h, out, ROWS, EMB, DFF, 0);
}

// round 3
// speedup vs baseline: 1.6976x; 1.6976x over previous
#include <cuda_runtime.h>
#include <cuda_bf16.h>
#include <math.h>
#include <stdint.h>

#define EMB 1024
#define SEQ 2048
#define BATCH 2
#define ROWS (BATCH*SEQ)   /* 4096 */
#define DFF (4*EMB)        /* 4096 */
#define NHEADS 16
#define HD 64
#define BQ 64
#define BKV 32
#define QKV_STR (3*EMB)    /* 3072 */

// ---------------- scratch (device globals: no allocation allowed) ----------------
__device__ float g_ln1[ROWS*EMB];
__device__ float g_qkv[(size_t)ROWS*QKV_STR];
__device__ float g_ctx[ROWS*EMB];
__device__ float g_h  [ROWS*EMB];
__device__ float g_y  [ROWS*EMB];
__device__ float g_ff [ROWS*DFF];
// transposed + hi/lo-split weights (bf16): [0 .. N*K) = hi, [N*K .. 2*N*K) = lo
__device__ __nv_bfloat16 g_wqkvt[2*3*EMB*EMB];
__device__ __nv_bfloat16 g_wot[2*EMB*EMB];
__device__ __nv_bfloat16 g_w1t[2*EMB*DFF];
__device__ __nv_bfloat16 g_w2t[2*DFF*EMB];

// ---------------- helpers ----------------
__device__ __forceinline__ uint32_t smem_to_u32(const void* p) {
    uint32_t a;
    asm("{ .reg .u64 t; cvta.to.shared.u64 t, %1; cvt.u32.u64 %0, t; }" : "=r"(a) : "l"(p));
    return a;
}
#define SWZ(off) ((off) ^ (((off) >> 3) & 0x70))

__device__ __forceinline__ void ldsm4(uint32_t* r, uint32_t addr) {
    asm volatile("ldmatrix.sync.aligned.m8n8.x4.shared.b16 {%0,%1,%2,%3}, [%4];"
        : "=r"(r[0]), "=r"(r[1]), "=r"(r[2]), "=r"(r[3]) : "r"(addr));
}
__device__ __forceinline__ void mma_bf16(float* d, const uint32_t* a, const uint32_t* b) {
    asm volatile("mma.sync.aligned.m16n8k16.row.col.f32.bf16.bf16.f32 "
        "{%0,%1,%2,%3}, {%4,%5,%6,%7}, {%8,%9}, {%0,%1,%2,%3};"
        : "+f"(d[0]), "+f"(d[1]), "+f"(d[2]), "+f"(d[3])
        : "r"(a[0]), "r"(a[1]), "r"(a[2]), "r"(a[3]), "r"(b[0]), "r"(b[1]));
}
__device__ __forceinline__ uint32_t pack_bf16(__nv_bfloat16 a, __nv_bfloat16 b) {
    return (uint32_t)__bfloat16_as_ushort(a) | ((uint32_t)__bfloat16_as_ushort(b) << 16);
}
__device__ __forceinline__ float gelu_f(float x)
{
    float u = 0.7978845608028654f * (x + 0.044715f * x * x * x);
    return 0.5f * x * (1.0f + tanhf(u));
}

// ---------------- layernorm ----------------
__global__ __launch_bounds__(256) void ln_kernel(const float* __restrict__ x,
    const float* __restrict__ g, const float* __restrict__ s, float* __restrict__ o)
{
    __shared__ float red[16];
    int row = blockIdx.x;
    int t = threadIdx.x;
    const float4* xr = reinterpret_cast<const float4*>(x + (size_t)row*EMB);
    float4 v = xr[t];
    float sum = v.x+v.y+v.z+v.w;
    float sq  = v.x*v.x+v.y*v.y+v.z*v.z+v.w*v.w;
    #pragma unroll
    for (int off = 16; off > 0; off >>= 1) {
        sum += __shfl_xor_sync(0xffffffffu, sum, off);
        sq  += __shfl_xor_sync(0xffffffffu, sq,  off);
    }
    int warp = t >> 5, lane = t & 31;
    if (lane == 0) { red[warp] = sum; red[warp+8] = sq; }
    __syncthreads();
    if (t < 32) {
        float a  = (lane < 8) ? red[lane]   : 0.0f;
        float b2 = (lane < 8) ? red[lane+8] : 0.0f;
        #pragma unroll
        for (int off = 4; off > 0; off >>= 1) {
            a  += __shfl_xor_sync(0xffffffffu, a,  off);
            b2 += __shfl_xor_sync(0xffffffffu, b2, off);
        }
        if (lane == 0) { red[0] = a; red[1] = b2; }
    }
    __syncthreads();
    float mean = red[0] * (1.0f/EMB);
    float var  = red[1] * (1.0f/EMB) - mean*mean;
    float inv  = rsqrtf(var + 1e-5f);
    float4 gv = reinterpret_cast<const float4*>(g)[t];
    float4 sv = reinterpret_cast<const float4*>(s)[t];
    float4 ov;
    ov.x = (v.x - mean)*inv*gv.x + sv.x;
    ov.y = (v.y - mean)*inv*gv.y + sv.y;
    ov.z = (v.z - mean)*inv*gv.z + sv.z;
    ov.w = (v.w - mean)*inv*gv.w + sv.w;
    reinterpret_cast<float4*>(o + (size_t)row*EMB)[t] = ov;
}

// ---------------- weight transpose + bf16 hi/lo split: W[K,N] -> Wt[hi][N,K], lo at +loOff ----------------
__global__ __launch_bounds__(256) void wconv_kernel(const float* __restrict__ W,
    __nv_bfloat16* __restrict__ O, int K, int N, size_t loOff)
{
    __shared__ float tile[32][33];
    int n0 = blockIdx.x*32, k0 = blockIdx.y*32;
    int tx = threadIdx.x & 31, ty = threadIdx.x >> 5;   // 32 x 8
    #pragma unroll
    for (int i = 0; i < 4; i++)
        tile[ty + 8*i][tx] = W[(size_t)(k0 + ty + 8*i)*N + n0 + tx];
    __syncthreads();
    __nv_bfloat16* hi = O;
    __nv_bfloat16* lo = O + loOff;
    #pragma unroll
    for (int i = 0; i < 4; i++) {
        float x = tile[tx][ty + 8*i];
        __nv_bfloat16 h = __float2bfloat16_rn(x);
        __nv_bfloat16 l = __float2bfloat16_rn(x - __bfloat162float(h));
        size_t idx = (size_t)(n0 + ty + 8*i)*K + k0 + tx;
        hi[idx] = h; lo[idx] = l;
    }
}

// ---------------- mma.sync bf16 GEMM (3-pass hi/lo split) ----------------
// C[M,N] = A[M,K](fp32) @ Bt[N,K](bf16 hi, lo at +N*K)^T, 128x128 tile, KC=64, double-buffered.
#define KC 64
#define SMEM_GEMM (8*16384)
__global__ __launch_bounds__(256) void gemm_mma(
    const float* __restrict__ A, const __nv_bfloat16* __restrict__ Bt,
    const float* __restrict__ bias, const float* __restrict__ res,
    float* __restrict__ C, int M, int N, int K, int dogelu)
{
    extern __shared__ char smem[];
    uint32_t sb = smem_to_u32(smem);
    int t = threadIdx.x, w = t >> 5, lane = t & 31;
    int wm = w >> 2, wn = w & 3;               // warp grid 2(m) x 4(n)
    int bx = blockIdx.x, by = blockIdx.y;
    int m0 = by*128, n0 = bx*128;
    const __nv_bfloat16* BtLo = Bt + (size_t)N*K;

    // smem regions: off(region, buf) = region*32768 + buf*16384; regions: AH=0, AL=1, BH=2, BL=3
    float4 aReg[8];
    uint4 bhReg[4], blReg[4];

    // staging indices
    int ar = t >> 4, ac4 = (t & 15) << 2;      // A: row f>>4, col (f&15)*4 with f = t+256*i
    int br = t >> 3, bc8 = (t & 7) << 3;       // B: row f>>3, col (f&7)*8

    float acc[4][4][4];
    #pragma unroll
    for (int mt = 0; mt < 4; mt++)
        #pragma unroll
        for (int nt = 0; nt < 4; nt++)
            #pragma unroll
            for (int e = 0; e < 4; e++) acc[mt][nt][e] = 0.0f;

    int nc = K / KC;

    // ---- prologue: load chunk 0 ----
    {
        const float* Ab = A + (size_t)m0*K;
        #pragma unroll
        for (int i = 0; i < 8; i++)
            aReg[i] = *(const float4*)(Ab + (size_t)(ar + 16*i)*K + ac4);
        const __nv_bfloat16* Bh = Bt   + (size_t)n0*K;
        const __nv_bfloat16* Bl = BtLo + (size_t)n0*K;
        #pragma unroll
        for (int i = 0; i < 4; i++) {
            bhReg[i] = *(const uint4*)(Bh + (size_t)(br + 32*i)*K + bc8);
            blReg[i] = *(const uint4*)(Bl + (size_t)(br + 32*i)*K + bc8);
        }
    }

    for (int c = 0; c < nc; c++) {
        int buf = c & 1;
        // ---- store staged chunk into smem buf ----
        {
            char* ah = smem + buf*16384;
            char* al = smem + 32768 + buf*16384;
            #pragma unroll
            for (int i = 0; i < 8; i++) {
                float4 v = aReg[i];
                __nv_bfloat16 h0 = __float2bfloat16_rn(v.x);
                __nv_bfloat16 h1 = __float2bfloat16_rn(v.y);
                __nv_bfloat16 h2 = __float2bfloat16_rn(v.z);
                __nv_bfloat16 h3 = __float2bfloat16_rn(v.w);
                __nv_bfloat16 l0 = __float2bfloat16_rn(v.x - __bfloat162float(h0));
                __nv_bfloat16 l1 = __float2bfloat16_rn(v.y - __bfloat162float(h1));
                __nv_bfloat16 l2 = __float2bfloat16_rn(v.z - __bfloat162float(h2));
                __nv_bfloat16 l3 = __float2bfloat16_rn(v.w - __bfloat162float(h3));
                uint32_t off = SWZ((uint32_t)((ar + 16*i)*128 + ac4*2));
                *(uint2*)(ah + off) = make_uint2(pack_bf16(h0,h1), pack_bf16(h2,h3));
                *(uint2*)(al + off) = make_uint2(pack_bf16(l0,l1), pack_bf16(l2,l3));
            }
            char* bh = smem + 65536 + buf*16384;
            char* bl = smem + 98304 + buf*16384;
            #pragma unroll
            for (int i = 0; i < 4; i++) {
                uint32_t off = SWZ((uint32_t)((br + 32*i)*128 + bc8*2));
                *(uint4*)(bh + off) = bhReg[i];
                *(uint4*)(bl + off) = blReg[i];
            }
        }
        __syncthreads();

        // ---- start loading next chunk ----
        if (c + 1 < nc) {
            const float* Ab = A + (size_t)m0*K + (size_t)(c+1)*KC;
            #pragma unroll
            for (int i = 0; i < 8; i++)
                aReg[i] = *(const float4*)(Ab + (size_t)(ar + 16*i)*K + ac4);
            const __nv_bfloat16* Bh = Bt   + (size_t)n0*K + (size_t)(c+1)*KC;
            const __nv_bfloat16* Bl = BtLo + (size_t)n0*K + (size_t)(c+1)*KC;
            #pragma unroll
            for (int i = 0; i < 4; i++) {
                bhReg[i] = *(const uint4*)(Bh + (size_t)(br + 32*i)*K + bc8);
                blReg[i] = *(const uint4*)(Bl + (size_t)(br + 32*i)*K + bc8);
            }
        }

        // ---- compute on buf ----
        {
            uint32_t ahB = sb + buf*16384;
            uint32_t alB = sb + 32768 + buf*16384;
            uint32_t bhB = sb + 65536 + buf*16384;
            uint32_t blB = sb + 98304 + buf*16384;
            int arow = lane & 15;
            int acol = (lane >> 4) << 4;               // byte offset within row
            int brow = ((lane >> 4) << 3) + (lane & 7);
            int bcol = ((lane >> 3) & 1) << 4;
            #pragma unroll
            for (int ks = 0; ks < 4; ks++) {
                int kb = ks * 32;                       // 16 bf16 = 32 bytes
                uint32_t ah[4][4], al[4][4], bh[4][2], bl[4][2];
                #pragma unroll
                for (int mt = 0; mt < 4; mt++) {
                    uint32_t off = SWZ((uint32_t)((wm*64 + mt*16 + arow)*128 + kb + acol));
                    ldsm4(ah[mt], ahB + off);
                    ldsm4(al[mt], alB + off);
                }
                #pragma unroll
                for (int nh = 0; nh < 2; nh++) {
                    uint32_t off = SWZ((uint32_t)((wn*32 + nh*16 + brow)*128 + kb + bcol));
                    uint32_t r[4];
                    ldsm4(r, bhB + off);
                    bh[nh*2][0] = r[0]; bh[nh*2][1] = r[1];
                    bh[nh*2+1][0] = r[2]; bh[nh*2+1][1] = r[3];
                    ldsm4(r, blB + off);
                    bl[nh*2][0] = r[0]; bl[nh*2][1] = r[1];
                    bl[nh*2+1][0] = r[2]; bl[nh*2+1][1] = r[3];
                }
                #pragma unroll
                for (int mt = 0; mt < 4; mt++)
                    #pragma unroll
                    for (int nt = 0; nt < 4; nt++) {
                        mma_bf16(acc[mt][nt], ah[mt], bh[nt]);
                        mma_bf16(acc[mt][nt], ah[mt], bl[nt]);
                        mma_bf16(acc[mt][nt], al[mt], bh[nt]);
                    }
            }
        }
        __syncthreads();
    }

    // ---- epilogue ----
    int mBase = m0 + wm*64;
    int nBase = n0 + wn*32;
    #pragma unroll
    for (int mt = 0; mt < 4; mt++) {
        #pragma unroll
        for (int nt = 0; nt < 4; nt++) {
            int row = mBase + mt*16 + (lane >> 2);
            int col = nBase + nt*8 + ((lane & 3) << 1);
            float v0 = acc[mt][nt][0], v1 = acc[mt][nt][1];
            float v2 = acc[mt][nt][2], v3 = acc[mt][nt][3];
            if (bias) {
                float2 bb = *(const float2*)(bias + col);
                v0 += bb.x; v1 += bb.y; v2 += bb.x; v3 += bb.y;
            }
            if (dogelu) {
                v0 = gelu_f(v0); v1 = gelu_f(v1);
                v2 = gelu_f(v2); v3 = gelu_f(v3);
            }
            if (res) {
                float2 r0 = *(const float2*)(res + (size_t)row*N + col);
                float2 r1 = *(const float2*)(res + (size_t)(row+8)*N + col);
                v0 += r0.x; v1 += r0.y; v2 += r1.x; v3 += r1.y;
            }
            *(float2*)(C + (size_t)row*N + col) = make_float2(v0, v1);
            *(float2*)(C + (size_t)(row+8)*N + col) = make_float2(v2, v3);
        }
    }
}

// ---------------- causal flash attention (fp32; QKV packed rows of 3072) ----------------
__global__ __launch_bounds__(256) void attn_kernel(
    const float* __restrict__ QKV, float* __restrict__ Og)
{
    __shared__ float QsT[64][68];
    __shared__ float KsT[64][34];
    __shared__ float Vs [32][64];
    __shared__ float Ss [64][33];
    __shared__ float rowScale[64];
    __shared__ float rowLinv [64];

    int t = threadIdx.x;
    int qt = blockIdx.x, bh = blockIdx.y;
    int b = bh >> 4, h = bh & 15;
    size_t baseQ = ((size_t)b*SEQ)*QKV_STR + (size_t)h*HD;
    size_t baseO = ((size_t)b*SEQ)*EMB + (size_t)h*HD;
    int q0 = qt * BQ;

    int tx = t & 15, ty = t >> 4;
    int warp = t >> 5, lane = t & 31;

    #pragma unroll
    for (int i = 0; i < 4; i++) {
        int fid = t + 256*i;
        int r = fid >> 4, d4 = (fid & 15) << 2;
        float4 qv = *(const float4*)(QKV + baseQ + (size_t)(q0 + r)*QKV_STR + d4);
        QsT[d4+0][r] = qv.x; QsT[d4+1][r] = qv.y;
        QsT[d4+2][r] = qv.z; QsT[d4+3][r] = qv.w;
    }

    float m[8], l[8];
    #pragma unroll
    for (int i = 0; i < 8; i++) { m[i] = -1e30f; l[i] = 0.0f; }
    float acc[4][4];
    #pragma unroll
    for (int i = 0; i < 4; i++)
        #pragma unroll
        for (int j = 0; j < 4; j++) acc[i][j] = 0.0f;

    int nkt = 2*qt + 2;
    for (int kt = 0; kt < nkt; kt++) {
        int k0 = kt * BKV;
        #pragma unroll
        for (int i = 0; i < 2; i++) {
            int fid = t + 256*i;
            int kk = fid >> 4, d4 = (fid & 15) << 2;
            float4 kv = *(const float4*)(QKV + baseQ + EMB + (size_t)(k0 + kk)*QKV_STR + d4);
            KsT[d4+0][kk] = kv.x; KsT[d4+1][kk] = kv.y;
            KsT[d4+2][kk] = kv.z; KsT[d4+3][kk] = kv.w;
            float4 vv = *(const float4*)(QKV + baseQ + 2*EMB + (size_t)(k0 + kk)*QKV_STR + d4);
            *(float4*)&Vs[kk][d4] = vv;
        }
        __syncthreads();

        {
            float s[4][2];
            #pragma unroll
            for (int i = 0; i < 4; i++) { s[i][0] = 0.0f; s[i][1] = 0.0f; }
            #pragma unroll 4
            for (int d = 0; d < 64; d++) {
                float4 a = *(const float4*)&QsT[d][ty*4];
                float2 bb = *(const float2*)&KsT[d][tx*2];
                s[0][0] = fmaf(a.x, bb.x, s[0][0]); s[0][1] = fmaf(a.x, bb.y, s[0][1]);
                s[1][0] = fmaf(a.y, bb.x, s[1][0]); s[1][1] = fmaf(a.y, bb.y, s[1][1]);
                s[2][0] = fmaf(a.z, bb.x, s[2][0]); s[2][1] = fmaf(a.z, bb.y, s[2][1]);
                s[3][0] = fmaf(a.w, bb.x, s[3][0]); s[3][1] = fmaf(a.w, bb.y, s[3][1]);
            }
            #pragma unroll
            for (int i = 0; i < 4; i++) {
                Ss[ty*4+i][tx*2+0] = s[i][0];
                Ss[ty*4+i][tx*2+1] = s[i][1];
            }
        }
        __syncthreads();

        #pragma unroll
        for (int i = 0; i < 8; i++) {
            int r  = warp*8 + i;
            int qg = q0 + r;
            int kg = k0 + lane;
            float sv = Ss[r][lane] * 0.125f;
            if (kg > qg) sv = -1e30f;
            float rmax = sv;
            #pragma unroll
            for (int off = 16; off > 0; off >>= 1)
                rmax = fmaxf(rmax, __shfl_xor_sync(0xffffffffu, rmax, off));
            float mn = fmaxf(m[i], rmax);
            float p  = __expf(sv - mn);
            float rs = p;
            #pragma unroll
            for (int off = 16; off > 0; off >>= 1)
                rs += __shfl_xor_sync(0xffffffffu, rs, off);
            float alpha = __expf(m[i] - mn);
            l[i] = l[i]*alpha + rs;
            m[i] = mn;
            Ss[r][lane] = p;
            if (lane == 0) rowScale[r] = alpha;
        }
        __syncthreads();

        #pragma unroll
        for (int i = 0; i < 4; i++) {
            float sc = rowScale[ty*4+i];
            #pragma unroll
            for (int j = 0; j < 4; j++) acc[i][j] *= sc;
        }
        #pragma unroll 4
        for (int kk = 0; kk < 32; kk++) {
            float4 vv = *(const float4*)&Vs[kk][tx*4];
            #pragma unroll
            for (int i = 0; i < 4; i++) {
                float p = Ss[ty*4+i][kk];
                acc[i][0] = fmaf(p, vv.x, acc[i][0]);
                acc[i][1] = fmaf(p, vv.y, acc[i][1]);
                acc[i][2] = fmaf(p, vv.z, acc[i][2]);
                acc[i][3] = fmaf(p, vv.w, acc[i][3]);
            }
        }
        __syncthreads();
    }

    if (lane == 0) {
        #pragma unroll
        for (int i = 0; i < 8; i++) rowLinv[warp*8 + i] = 1.0f / l[i];
    }
    __syncthreads();

    #pragma unroll
    for (int i = 0; i < 4; i++) {
        int r = ty*4 + i;
        float linv = rowLinv[r];
        float4 o;
        o.x = acc[i][0]*linv; o.y = acc[i][1]*linv;
        o.z = acc[i][2]*linv; o.w = acc[i][3]*linv;
        *(float4*)(Og + baseO + (size_t)(q0 + r)*EMB + tx*4) = o;
    }
}

// ---------------- launch ----------------
extern "C" void kernel_launch(void* const* d_in, const int* in_sizes, int n_in,
                              void* d_out, int out_size)
{
    const float* x  = (const float*)d_in[0];
    const float* Wq = (const float*)d_in[1];
    const float* Wk = (const float*)d_in[2];
    const float* Wv = (const float*)d_in[3];
    const float* Wo = (const float*)d_in[4];
    const float* bo = (const float*)d_in[5];
    const float* W1 = (const float*)d_in[6];
    const float* b1 = (const float*)d_in[7];
    const float* W2 = (const float*)d_in[8];
    const float* b2 = (const float*)d_in[9];
    const float* g1 = (const float*)d_in[10];
    const float* s1 = (const float*)d_in[11];
    const float* g2 = (const float*)d_in[12];
    const float* s2 = (const float*)d_in[13];
    float* out = (float*)d_out;

    float *ln1, *qkv, *ctx, *h, *y, *ff;
    __nv_bfloat16 *wqkvt, *wot, *w1t, *w2t;
    cudaGetSymbolAddress((void**)&ln1,  g_ln1);
    cudaGetSymbolAddress((void**)&qkv,  g_qkv);
    cudaGetSymbolAddress((void**)&ctx,  g_ctx);
    cudaGetSymbolAddress((void**)&h,    g_h);
    cudaGetSymbolAddress((void**)&y,    g_y);
    cudaGetSymbolAddress((void**)&ff,   g_ff);
    cudaGetSymbolAddress((void**)&wqkvt, g_wqkvt);
    cudaGetSymbolAddress((void**)&wot,  g_wot);
    cudaGetSymbolAddress((void**)&w1t,  g_w1t);
    cudaGetSymbolAddress((void**)&w2t,  g_w2t);

    cudaFuncSetAttribute(gemm_mma, cudaFuncAttributeMaxDynamicSharedMemorySize, SMEM_GEMM);

    dim3 blk(256);
    size_t qkvLo = (size_t)QKV_STR*EMB;   // lo region offset inside packed qkv weights

    // weight transpose + bf16 hi/lo split
    wconv_kernel<<<dim3(EMB/32, EMB/32), blk>>>(Wq, wqkvt,                         EMB, EMB, qkvLo);
    wconv_kernel<<<dim3(EMB/32, EMB/32), blk>>>(Wk, wqkvt + (size_t)EMB*EMB,       EMB, EMB, qkvLo);
    wconv_kernel<<<dim3(EMB/32, EMB/32), blk>>>(Wv, wqkvt + (size_t)2*EMB*EMB,     EMB, EMB, qkvLo);
    wconv_kernel<<<dim3(EMB/32, EMB/32), blk>>>(Wo, wot, EMB, EMB, (size_t)EMB*EMB);
    wconv_kernel<<<dim3(DFF/32, EMB/32), blk>>>(W1, w1t, EMB, DFF, (size_t)EMB*DFF);
    wconv_kernel<<<dim3(EMB/32, DFF/32), blk>>>(W2, w2t, DFF, EMB, (size_t)DFF*EMB);

    // ln1 = LN(x)
    ln_kernel<<<ROWS, blk>>>(x, g1, s1, ln1);
    // qkv = ln1 @ [Wq|Wk|Wv]
    gemm_mma<<<dim3(QKV_STR/128, ROWS/128), blk, SMEM_GEMM>>>(ln1, wqkvt, nullptr, nullptr, qkv, ROWS, QKV_STR, EMB, 0);
    // ctx = causal softmax(qk^T/8) v
    attn_kernel<<<dim3(SEQ/BQ, BATCH*NHEADS), blk>>>(qkv, ctx);
    // h = x + ctx @ Wo + bo
    gemm_mma<<<dim3(EMB/128, ROWS/128), blk, SMEM_GEMM>>>(ctx, wot, bo, x, h, ROWS, EMB, EMB, 0);
    // y = LN(h)
    ln_kernel<<<ROWS, blk>>>(h, g2, s2, y);
    // ff = gelu(y @ W1 + b1)
    gemm_mma<<<dim3(DFF/128, ROWS/128), blk, SMEM_GEMM>>>(y, w1t, b1, nullptr, ff, ROWS, DFF, EMB, 1);
    // out = h + ff @ W2 + b2
    gemm_mma<<<dim3(EMB/128, ROWS/128), blk, SMEM_GEMM>>>(ff, w2t, b2, h, out, ROWS, EMB, DFF, 0);
}

// round 4
// speedup vs baseline: 1.9412x; 1.1435x over previous
#include <cuda_runtime.h>
#include <cuda_bf16.h>
#include <math.h>
#include <stdint.h>

#define EMB 1024
#define SEQ 2048
#define BATCH 2
#define ROWS (BATCH*SEQ)   /* 4096 */
#define DFF (4*EMB)        /* 4096 */
#define NHEADS 16
#define HD 64
#define QKV_STR (3*EMB)    /* 3072 */

// ---------------- scratch (device globals: no allocation allowed) ----------------
__device__ __nv_bfloat16 g_ln1h[ROWS*EMB];
__device__ __nv_bfloat16 g_ln1l[ROWS*EMB];
__device__ __nv_bfloat16 g_qkvh[(size_t)ROWS*QKV_STR];
__device__ __nv_bfloat16 g_qkvl[(size_t)ROWS*QKV_STR];
__device__ __nv_bfloat16 g_ctxh[ROWS*EMB];
__device__ __nv_bfloat16 g_ctxl[ROWS*EMB];
__device__ float         g_h   [ROWS*EMB];
__device__ __nv_bfloat16 g_yh  [ROWS*EMB];
__device__ __nv_bfloat16 g_yl  [ROWS*EMB];
__device__ __nv_bfloat16 g_ffh [(size_t)ROWS*DFF];
__device__ __nv_bfloat16 g_ffl [(size_t)ROWS*DFF];
// transposed + hi/lo-split weights (bf16): [0 .. N*K) = hi, [N*K .. 2*N*K) = lo
__device__ __nv_bfloat16 g_wqkvt[2*3*EMB*EMB];
__device__ __nv_bfloat16 g_wot[2*EMB*EMB];
__device__ __nv_bfloat16 g_w1t[2*EMB*DFF];
__device__ __nv_bfloat16 g_w2t[2*DFF*EMB];

// ---------------- helpers ----------------
__device__ __forceinline__ uint32_t smem_to_u32(const void* p) {
    uint32_t a;
    asm("{ .reg .u64 t; cvta.to.shared.u64 t, %1; cvt.u32.u64 %0, t; }" : "=r"(a) : "l"(p));
    return a;
}
#define SWZ(off) ((off) ^ (((off) >> 3) & 0x70))

__device__ __forceinline__ void ldsm4(uint32_t* r, uint32_t addr) {
    asm volatile("ldmatrix.sync.aligned.m8n8.x4.shared.b16 {%0,%1,%2,%3}, [%4];"
        : "=r"(r[0]), "=r"(r[1]), "=r"(r[2]), "=r"(r[3]) : "r"(addr));
}
__device__ __forceinline__ void ldsm4t(uint32_t* r, uint32_t addr) {
    asm volatile("ldmatrix.sync.aligned.m8n8.x4.trans.shared.b16 {%0,%1,%2,%3}, [%4];"
        : "=r"(r[0]), "=r"(r[1]), "=r"(r[2]), "=r"(r[3]) : "r"(addr));
}
__device__ __forceinline__ void mma_bf16(float* d, const uint32_t* a, const uint32_t* b) {
    asm volatile("mma.sync.aligned.m16n8k16.row.col.f32.bf16.bf16.f32 "
        "{%0,%1,%2,%3}, {%4,%5,%6,%7}, {%8,%9}, {%0,%1,%2,%3};"
        : "+f"(d[0]), "+f"(d[1]), "+f"(d[2]), "+f"(d[3])
        : "r"(a[0]), "r"(a[1]), "r"(a[2]), "r"(a[3]), "r"(b[0]), "r"(b[1]));
}
__device__ __forceinline__ void cp16(uint32_t s, const void* g) {
    asm volatile("cp.async.cg.shared.global [%0], [%1], 16;" :: "r"(s), "l"(g));
}
#define CP_COMMIT() asm volatile("cp.async.commit_group;" ::: "memory")
#define CP_WAIT(n)  asm volatile("cp.async.wait_group %0;" :: "n"(n) : "memory")

__device__ __forceinline__ uint32_t pack_bf16(__nv_bfloat16 a, __nv_bfloat16 b) {
    return (uint32_t)__bfloat16_as_ushort(a) | ((uint32_t)__bfloat16_as_ushort(b) << 16);
}
// pair fp32 -> packed bf16 hi + packed bf16 lo
__device__ __forceinline__ uint32_t cvt2(float a, float b, uint32_t& lo) {
    __nv_bfloat16 ha = __float2bfloat16_rn(a), hb = __float2bfloat16_rn(b);
    __nv_bfloat16 la = __float2bfloat16_rn(a - __bfloat162float(ha));
    __nv_bfloat16 lb = __float2bfloat16_rn(b - __bfloat162float(hb));
    lo = pack_bf16(la, lb);
    return pack_bf16(ha, hb);
}
__device__ __forceinline__ float gelu_f(float x)
{
    float u = 0.7978845608028654f * (x + 0.044715f * x * x * x);
    return 0.5f * x * (1.0f + tanhf(u));
}

// ---------------- layernorm: fp32 in -> bf16 hi/lo out ----------------
__global__ __launch_bounds__(256) void ln_kernel(const float* __restrict__ x,
    const float* __restrict__ g, const float* __restrict__ s,
    __nv_bfloat16* __restrict__ oh, __nv_bfloat16* __restrict__ ol)
{
    __shared__ float red[16];
    int row = blockIdx.x;
    int t = threadIdx.x;
    const float4* xr = reinterpret_cast<const float4*>(x + (size_t)row*EMB);
    float4 v = xr[t];
    float sum = v.x+v.y+v.z+v.w;
    float sq  = v.x*v.x+v.y*v.y+v.z*v.z+v.w*v.w;
    #pragma unroll
    for (int off = 16; off > 0; off >>= 1) {
        sum += __shfl_xor_sync(0xffffffffu, sum, off);
        sq  += __shfl_xor_sync(0xffffffffu, sq,  off);
    }
    int warp = t >> 5, lane = t & 31;
    if (lane == 0) { red[warp] = sum; red[warp+8] = sq; }
    __syncthreads();
    if (t < 32) {
        float a  = (lane < 8) ? red[lane]   : 0.0f;
        float b2 = (lane < 8) ? red[lane+8] : 0.0f;
        #pragma unroll
        for (int off = 4; off > 0; off >>= 1) {
            a  += __shfl_xor_sync(0xffffffffu, a,  off);
            b2 += __shfl_xor_sync(0xffffffffu, b2, off);
        }
        if (lane == 0) { red[0] = a; red[1] = b2; }
    }
    __syncthreads();
    float mean = red[0] * (1.0f/EMB);
    float var  = red[1] * (1.0f/EMB) - mean*mean;
    float inv  = rsqrtf(var + 1e-5f);
    float4 gv = reinterpret_cast<const float4*>(g)[t];
    float4 sv = reinterpret_cast<const float4*>(s)[t];
    float o0 = (v.x - mean)*inv*gv.x + sv.x;
    float o1 = (v.y - mean)*inv*gv.y + sv.y;
    float o2 = (v.z - mean)*inv*gv.z + sv.z;
    float o3 = (v.w - mean)*inv*gv.w + sv.w;
    uint32_t l01, l23;
    uint32_t h01 = cvt2(o0, o1, l01);
    uint32_t h23 = cvt2(o2, o3, l23);
    *(uint2*)(oh + (size_t)row*EMB + t*4) = make_uint2(h01, h23);
    *(uint2*)(ol + (size_t)row*EMB + t*4) = make_uint2(l01, l23);
}

// ---------------- weight transpose + bf16 hi/lo split: W[K,N] -> Wt[hi][N,K], lo at +loOff ----------------
__global__ __launch_bounds__(256) void wconv_kernel(const float* __restrict__ W,
    __nv_bfloat16* __restrict__ O, int K, int N, size_t loOff)
{
    __shared__ float tile[32][33];
    int n0 = blockIdx.x*32, k0 = blockIdx.y*32;
    int tx = threadIdx.x & 31, ty = threadIdx.x >> 5;   // 32 x 8
    #pragma unroll
    for (int i = 0; i < 4; i++)
        tile[ty + 8*i][tx] = W[(size_t)(k0 + ty + 8*i)*N + n0 + tx];
    __syncthreads();
    __nv_bfloat16* hi = O;
    __nv_bfloat16* lo = O + loOff;
    #pragma unroll
    for (int i = 0; i < 4; i++) {
        float x = tile[tx][ty + 8*i];
        __nv_bfloat16 h = __float2bfloat16_rn(x);
        __nv_bfloat16 l = __float2bfloat16_rn(x - __bfloat162float(h));
        size_t idx = (size_t)(n0 + ty + 8*i)*K + k0 + tx;
        hi[idx] = h; lo[idx] = l;
    }
}

// ---------------- mma.sync bf16 GEMM (3-pass hi/lo, cp.async double-buffer) ----------------
// C = A(hi+lo)[M,K] @ Bt(hi+lo)[N,K]^T. outF != null -> fp32 out (+res); else bf16 hi/lo out.
#define KC 64
#define SMEM_GEMM (2*4*16384)
__global__ __launch_bounds__(256) void gemm_mma(
    const __nv_bfloat16* __restrict__ Ah, const __nv_bfloat16* __restrict__ Al,
    const __nv_bfloat16* __restrict__ Bt,
    const float* __restrict__ bias, const float* __restrict__ res,
    float* __restrict__ outF, __nv_bfloat16* __restrict__ outH, __nv_bfloat16* __restrict__ outL,
    int M, int N, int K, int dogelu)
{
    extern __shared__ char smem[];
    uint32_t sb = smem_to_u32(smem);
    int t = threadIdx.x, w = t >> 5, lane = t & 31;
    int wm = w >> 2, wn = w & 3;               // warp grid 2(m) x 4(n)
    int m0 = blockIdx.y*128, n0 = blockIdx.x*128;
    const __nv_bfloat16* BtLo = Bt + (size_t)N*K;

    // cp.async staging: 4096 16B chunks/stage; id -> arr(0..3: AH,AL,BH,BL), row, c16
    const __nv_bfloat16* src[4] = { Ah + (size_t)m0*K, Al + (size_t)m0*K,
                                    Bt + (size_t)n0*K, BtLo + (size_t)n0*K };

    float acc[4][4][4];
    #pragma unroll
    for (int mt = 0; mt < 4; mt++)
        #pragma unroll
        for (int nt = 0; nt < 4; nt++)
            #pragma unroll
            for (int e = 0; e < 4; e++) acc[mt][nt][e] = 0.0f;

    int nc = K / KC;

    // issue stage for chunk c into buffer buf
    auto issue = [&](int c, int buf) {
        uint32_t stb = sb + buf*65536;
        #pragma unroll
        for (int i = 0; i < 16; i++) {
            int id  = t + 256*i;
            int arr = id >> 10;
            int cid = id & 1023;
            int row = cid >> 3, c16 = cid & 7;
            const __nv_bfloat16* gp = src[arr] + (size_t)row*K + c*KC + c16*8;
            cp16(stb + arr*16384 + SWZ((uint32_t)(row*128 + c16*16)), gp);
        }
    };

    issue(0, 0);
    CP_COMMIT();

    for (int c = 0; c < nc; c++) {
        int buf = c & 1;
        if (c + 1 < nc) { issue(c+1, buf^1); }
        CP_COMMIT();
        if (c + 1 < nc) { CP_WAIT(1); } else { CP_WAIT(0); }
        __syncthreads();

        {
            uint32_t ahB = sb + buf*65536;
            uint32_t alB = ahB + 16384;
            uint32_t bhB = ahB + 32768;
            uint32_t blB = ahB + 49152;
            int arow = lane & 15;
            int acol = (lane >> 4) << 4;
            int brow = ((lane >> 4) << 3) + (lane & 7);
            int bcol = ((lane >> 3) & 1) << 4;
            #pragma unroll
            for (int ks = 0; ks < 4; ks++) {
                int kb = ks * 32;
                uint32_t ah[4][4], al[4][4], bh[4][2], bl[4][2];
                #pragma unroll
                for (int mt = 0; mt < 4; mt++) {
                    uint32_t off = SWZ((uint32_t)((wm*64 + mt*16 + arow)*128 + kb + acol));
                    ldsm4(ah[mt], ahB + off);
                    ldsm4(al[mt], alB + off);
                }
                #pragma unroll
                for (int nh = 0; nh < 2; nh++) {
                    uint32_t off = SWZ((uint32_t)((wn*32 + nh*16 + brow)*128 + kb + bcol));
                    uint32_t r[4];
                    ldsm4(r, bhB + off);
                    bh[nh*2][0] = r[0]; bh[nh*2][1] = r[1];
                    bh[nh*2+1][0] = r[2]; bh[nh*2+1][1] = r[3];
                    ldsm4(r, blB + off);
                    bl[nh*2][0] = r[0]; bl[nh*2][1] = r[1];
                    bl[nh*2+1][0] = r[2]; bl[nh*2+1][1] = r[3];
                }
                #pragma unroll
                for (int mt = 0; mt < 4; mt++)
                    #pragma unroll
                    for (int nt = 0; nt < 4; nt++) {
                        mma_bf16(acc[mt][nt], ah[mt], bh[nt]);
                        mma_bf16(acc[mt][nt], ah[mt], bl[nt]);
                        mma_bf16(acc[mt][nt], al[mt], bh[nt]);
                    }
            }
        }
        __syncthreads();
    }

    // ---- epilogue ----
    int mBase = m0 + wm*64;
    int nBase = n0 + wn*32;
    #pragma unroll
    for (int mt = 0; mt < 4; mt++) {
        #pragma unroll
        for (int nt = 0; nt < 4; nt++) {
            int row = mBase + mt*16 + (lane >> 2);
            int col = nBase + nt*8 + ((lane & 3) << 1);
            float v0 = acc[mt][nt][0], v1 = acc[mt][nt][1];
            float v2 = acc[mt][nt][2], v3 = acc[mt][nt][3];
            if (bias) {
                float2 bb = *(const float2*)(bias + col);
                v0 += bb.x; v1 += bb.y; v2 += bb.x; v3 += bb.y;
            }
            if (dogelu) {
                v0 = gelu_f(v0); v1 = gelu_f(v1);
                v2 = gelu_f(v2); v3 = gelu_f(v3);
            }
            if (outF) {
                if (res) {
                    float2 r0 = *(const float2*)(res + (size_t)row*N + col);
                    float2 r1 = *(const float2*)(res + (size_t)(row+8)*N + col);
                    v0 += r0.x; v1 += r0.y; v2 += r1.x; v3 += r1.y;
                }
                *(float2*)(outF + (size_t)row*N + col) = make_float2(v0, v1);
                *(float2*)(outF + (size_t)(row+8)*N + col) = make_float2(v2, v3);
            } else {
                uint32_t lo0, lo1;
                uint32_t hi0 = cvt2(v0, v1, lo0);
                uint32_t hi1 = cvt2(v2, v3, lo1);
                *(uint32_t*)(outH + (size_t)row*N + col) = hi0;
                *(uint32_t*)(outL + (size_t)row*N + col) = lo0;
                *(uint32_t*)(outH + (size_t)(row+8)*N + col) = hi1;
                *(uint32_t*)(outL + (size_t)(row+8)*N + col) = lo1;
            }
        }
    }
}

// ---------------- causal flash attention, bf16 mma with hi/lo 3-pass ----------------
// QKV packed bf16 hi/lo [ROWS, 3072]; out ctx bf16 hi/lo [ROWS, 1024].
// Block: 256 thr (8 warps), q-tile 128 (warp w owns rows w*16..+15), kv-tile 64.
#define SMEM_ATTN (32768 + 2*32768)
__global__ __launch_bounds__(256) void attn_kernel(
    const __nv_bfloat16* __restrict__ Qh, const __nv_bfloat16* __restrict__ Ql,
    __nv_bfloat16* __restrict__ Ch, __nv_bfloat16* __restrict__ Cl)
{
    extern __shared__ char smem[];
    uint32_t sb = smem_to_u32(smem);
    int t = threadIdx.x, w = t >> 5, lane = t & 31;
    int qt = blockIdx.x, bh_ = blockIdx.y;
    int h = bh_ & 15;
    size_t rowOff = (size_t)(bh_ >> 4) * SEQ;      // batch row offset
    int q0 = qt * 128;
    int colQ = h*64, colK = 1024 + h*64, colV = 2048 + h*64;

    // ---- async load Q (hi/lo) ----
    #pragma unroll
    for (int i = 0; i < 8; i++) {
        int id = t + 256*i;
        int arr = id >> 10;              // 0 = hi, 1 = lo
        int cid = id & 1023;
        int row = cid >> 3, c16 = cid & 7;
        const __nv_bfloat16* gp = (arr ? Ql : Qh) + (rowOff + q0 + row)*QKV_STR + colQ + c16*8;
        cp16(sb + arr*16384 + SWZ((uint32_t)(row*128 + c16*16)), gp);
    }
    CP_COMMIT();

    int nkt = 2*qt + 2;

    // issue K/V stage
    auto issue = [&](int kt, int buf) {
        uint32_t stb = sb + 32768 + buf*32768;
        int k0 = kt*64;
        #pragma unroll
        for (int i = 0; i < 8; i++) {
            int id = t + 256*i;
            int arr = id >> 9;           // 0 KH, 1 KL, 2 VH, 3 VL
            int cid = id & 511;
            int row = cid >> 3, c16 = cid & 7;
            const __nv_bfloat16* base = (arr & 1) ? Ql : Qh;
            int col = (arr < 2) ? colK : colV;
            const __nv_bfloat16* gp = base + (rowOff + k0 + row)*QKV_STR + col + c16*8;
            cp16(stb + arr*8192 + SWZ((uint32_t)(row*128 + c16*16)), gp);
        }
    };
    issue(0, 0);
    CP_COMMIT();
    CP_WAIT(1);          // Q ready
    __syncthreads();

    // ---- Q fragments to registers ----
    uint32_t qh[4][4], ql[4][4];
    {
        int arow = lane & 15;
        int acol = (lane >> 4) << 4;
        #pragma unroll
        for (int kf = 0; kf < 4; kf++) {
            uint32_t off = SWZ((uint32_t)((w*16 + arow)*128 + kf*32 + acol));
            ldsm4(qh[kf], sb + off);
            ldsm4(ql[kf], sb + 16384 + off);
        }
    }

    float o[8][4];
    #pragma unroll
    for (int nt = 0; nt < 8; nt++)
        #pragma unroll
        for (int e = 0; e < 4; e++) o[nt][e] = 0.0f;
    float mst0 = -1e30f, mst1 = -1e30f, lst0 = 0.0f, lst1 = 0.0f;

    int r0g = q0 + w*16 + (lane >> 2);
    int r1g = r0g + 8;

    for (int kt = 0; kt < nkt; kt++) {
        int buf = kt & 1;
        if (kt + 1 < nkt) issue(kt+1, buf^1);
        CP_COMMIT();
        if (kt + 1 < nkt) { CP_WAIT(1); } else { CP_WAIT(0); }
        __syncthreads();

        int k0 = kt*64;
        if (k0 <= q0 + w*16 + 15) {     // at least one unmasked element for this warp
            uint32_t stb = sb + 32768 + buf*32768;
            uint32_t khB = stb, klB = stb + 8192, vhB = stb + 16384, vlB = stb + 24576;

            // ---- S = Q @ K^T (3 passes) ----
            float s[8][4];
            #pragma unroll
            for (int nt = 0; nt < 8; nt++)
                #pragma unroll
                for (int e = 0; e < 4; e++) s[nt][e] = 0.0f;
            {
                int brow = ((lane >> 4) << 3) + (lane & 7);
                int bcol = ((lane >> 3) & 1) << 4;
                #pragma unroll
                for (int ks = 0; ks < 4; ks++) {
                    int kb = ks*32;
                    uint32_t bh[8][2], bl[8][2];
                    #pragma unroll
                    for (int nh = 0; nh < 4; nh++) {
                        uint32_t off = SWZ((uint32_t)((nh*16 + brow)*128 + kb + bcol));
                        uint32_t r[4];
                        ldsm4(r, khB + off);
                        bh[nh*2][0] = r[0]; bh[nh*2][1] = r[1];
                        bh[nh*2+1][0] = r[2]; bh[nh*2+1][1] = r[3];
                        ldsm4(r, klB + off);
                        bl[nh*2][0] = r[0]; bl[nh*2][1] = r[1];
                        bl[nh*2+1][0] = r[2]; bl[nh*2+1][1] = r[3];
                    }
                    #pragma unroll
                    for (int nt = 0; nt < 8; nt++) {
                        mma_bf16(s[nt], qh[ks], bh[nt]);
                        mma_bf16(s[nt], qh[ks], bl[nt]);
                        mma_bf16(s[nt], ql[ks], bh[nt]);
                    }
                }
            }

            // ---- scale + causal mask + online softmax ----
            float mx0 = -1e30f, mx1 = -1e30f;
            #pragma unroll
            for (int nt = 0; nt < 8; nt++) {
                int kgBase = k0 + nt*8 + ((lane & 3) << 1);
                #pragma unroll
                for (int e = 0; e < 4; e++) {
                    float v = s[nt][e] * 0.125f;
                    int kg = kgBase + (e & 1);
                    int qg = (e < 2) ? r0g : r1g;
                    v = (kg <= qg) ? v : -1e30f;
                    s[nt][e] = v;
                    if (e < 2) mx0 = fmaxf(mx0, v); else mx1 = fmaxf(mx1, v);
                }
            }
            mx0 = fmaxf(mx0, __shfl_xor_sync(0xffffffffu, mx0, 1));
            mx0 = fmaxf(mx0, __shfl_xor_sync(0xffffffffu, mx0, 2));
            mx1 = fmaxf(mx1, __shfl_xor_sync(0xffffffffu, mx1, 1));
            mx1 = fmaxf(mx1, __shfl_xor_sync(0xffffffffu, mx1, 2));
            float mn0 = fmaxf(mst0, mx0), mn1 = fmaxf(mst1, mx1);
            float a0 = __expf(mst0 - mn0), a1 = __expf(mst1 - mn1);
            mst0 = mn0; mst1 = mn1;
            float s0 = 0.0f, s1 = 0.0f;
            #pragma unroll
            for (int nt = 0; nt < 8; nt++) {
                float p0 = __expf(s[nt][0] - mn0);
                float p1 = __expf(s[nt][1] - mn0);
                float p2 = __expf(s[nt][2] - mn1);
                float p3 = __expf(s[nt][3] - mn1);
                s[nt][0] = p0; s[nt][1] = p1; s[nt][2] = p2; s[nt][3] = p3;
                s0 += p0 + p1; s1 += p2 + p3;
            }
            s0 += __shfl_xor_sync(0xffffffffu, s0, 1);
            s0 += __shfl_xor_sync(0xffffffffu, s0, 2);
            s1 += __shfl_xor_sync(0xffffffffu, s1, 1);
            s1 += __shfl_xor_sync(0xffffffffu, s1, 2);
            lst0 = lst0*a0 + s0;
            lst1 = lst1*a1 + s1;
            #pragma unroll
            for (int nt = 0; nt < 8; nt++) {
                o[nt][0] *= a0; o[nt][1] *= a0;
                o[nt][2] *= a1; o[nt][3] *= a1;
            }

            // ---- O += P @ V (3 passes) ----
            #pragma unroll
            for (int kk = 0; kk < 4; kk++) {
                uint32_t ph[4], pl[4];
                ph[0] = cvt2(s[2*kk][0],   s[2*kk][1],   pl[0]);
                ph[1] = cvt2(s[2*kk][2],   s[2*kk][3],   pl[1]);
                ph[2] = cvt2(s[2*kk+1][0], s[2*kk+1][1], pl[2]);
                ph[3] = cvt2(s[2*kk+1][2], s[2*kk+1][3], pl[3]);
                #pragma unroll
                for (int nv = 0; nv < 4; nv++) {
                    uint32_t off = SWZ((uint32_t)((kk*16 + (lane & 15))*128 + (nv*16 + 8*(lane >> 4))*2));
                    uint32_t rh[4], rl[4];
                    ldsm4t(rh, vhB + off);
                    ldsm4t(rl, vlB + off);
                    uint32_t b0h[2] = { rh[0], rh[1] }, b1h[2] = { rh[2], rh[3] };
                    uint32_t b0l[2] = { rl[0], rl[1] }, b1l[2] = { rl[2], rl[3] };
                    mma_bf16(o[2*nv],   ph, b0h);
                    mma_bf16(o[2*nv],   pl, b0h);
                    mma_bf16(o[2*nv],   ph, b0l);
                    mma_bf16(o[2*nv+1], ph, b1h);
                    mma_bf16(o[2*nv+1], pl, b1h);
                    mma_bf16(o[2*nv+1], ph, b1l);
                }
            }
        }
        __syncthreads();
    }

    // ---- epilogue: O/l -> bf16 hi/lo ctx ----
    float li0 = 1.0f / lst0, li1 = 1.0f / lst1;
    int colB = h*64 + ((lane & 3) << 1);
    size_t row0 = rowOff + r0g, row1 = rowOff + r1g;
    #pragma unroll
    for (int nt = 0; nt < 8; nt++) {
        int col = colB + nt*8;
        uint32_t lo0, lo1;
        uint32_t hi0 = cvt2(o[nt][0]*li0, o[nt][1]*li0, lo0);
        uint32_t hi1 = cvt2(o[nt][2]*li1, o[nt][3]*li1, lo1);
        *(uint32_t*)(Ch + row0*EMB + col) = hi0;
        *(uint32_t*)(Cl + row0*EMB + col) = lo0;
        *(uint32_t*)(Ch + row1*EMB + col) = hi1;
        *(uint32_t*)(Cl + row1*EMB + col) = lo1;
    }
}

// ---------------- launch ----------------
extern "C" void kernel_launch(void* const* d_in, const int* in_sizes, int n_in,
                              void* d_out, int out_size)
{
    const float* x  = (const float*)d_in[0];
    const float* Wq = (const float*)d_in[1];
    const float* Wk = (const float*)d_in[2];
    const float* Wv = (const float*)d_in[3];
    const float* Wo = (const float*)d_in[4];
    const float* bo = (const float*)d_in[5];
    const float* W1 = (const float*)d_in[6];
    const float* b1 = (const float*)d_in[7];
    const float* W2 = (const float*)d_in[8];
    const float* b2 = (const float*)d_in[9];
    const float* g1 = (const float*)d_in[10];
    const float* s1 = (const float*)d_in[11];
    const float* g2 = (const float*)d_in[12];
    const float* s2 = (const float*)d_in[13];
    float* out = (float*)d_out;

    __nv_bfloat16 *ln1h, *ln1l, *qkvh, *qkvl, *ctxh, *ctxl, *yh, *yl, *ffh, *ffl;
    __nv_bfloat16 *wqkvt, *wot, *w1t, *w2t;
    float *h;
    cudaGetSymbolAddress((void**)&ln1h, g_ln1h);
    cudaGetSymbolAddress((void**)&ln1l, g_ln1l);
    cudaGetSymbolAddress((void**)&qkvh, g_qkvh);
    cudaGetSymbolAddress((void**)&qkvl, g_qkvl);
    cudaGetSymbolAddress((void**)&ctxh, g_ctxh);
    cudaGetSymbolAddress((void**)&ctxl, g_ctxl);
    cudaGetSymbolAddress((void**)&h,    g_h);
    cudaGetSymbolAddress((void**)&yh,   g_yh);
    cudaGetSymbolAddress((void**)&yl,   g_yl);
    cudaGetSymbolAddress((void**)&ffh,  g_ffh);
    cudaGetSymbolAddress((void**)&ffl,  g_ffl);
    cudaGetSymbolAddress((void**)&wqkvt, g_wqkvt);
    cudaGetSymbolAddress((void**)&wot,  g_wot);
    cudaGetSymbolAddress((void**)&w1t,  g_w1t);
    cudaGetSymbolAddress((void**)&w2t,  g_w2t);

    cudaFuncSetAttribute(gemm_mma, cudaFuncAttributeMaxDynamicSharedMemorySize, SMEM_GEMM);
    cudaFuncSetAttribute(attn_kernel, cudaFuncAttributeMaxDynamicSharedMemorySize, SMEM_ATTN);

    dim3 blk(256);
    size_t qkvLo = (size_t)QKV_STR*EMB;

    // weight transpose + bf16 hi/lo split
    wconv_kernel<<<dim3(EMB/32, EMB/32), blk>>>(Wq, wqkvt,                     EMB, EMB, qkvLo);
    wconv_kernel<<<dim3(EMB/32, EMB/32), blk>>>(Wk, wqkvt + (size_t)EMB*EMB,   EMB, EMB, qkvLo);
    wconv_kernel<<<dim3(EMB/32, EMB/32), blk>>>(Wv, wqkvt + (size_t)2*EMB*EMB, EMB, EMB, qkvLo);
    wconv_kernel<<<dim3(EMB/32, EMB/32), blk>>>(Wo, wot, EMB, EMB, (size_t)EMB*EMB);
    wconv_kernel<<<dim3(DFF/32, EMB/32), blk>>>(W1, w1t, EMB, DFF, (size_t)EMB*DFF);
    wconv_kernel<<<dim3(EMB/32, DFF/32), blk>>>(W2, w2t, DFF, EMB, (size_t)DFF*EMB);

    // ln1 = LN(x) -> bf16 hi/lo
    ln_kernel<<<ROWS, blk>>>(x, g1, s1, ln1h, ln1l);
    // qkv = ln1 @ [Wq|Wk|Wv] -> bf16 hi/lo
    gemm_mma<<<dim3(QKV_STR/128, ROWS/128), blk, SMEM_GEMM>>>(
        ln1h, ln1l, wqkvt, nullptr, nullptr, nullptr, qkvh, qkvl, ROWS, QKV_STR, EMB, 0);
    // ctx = causal softmax(qk^T/8) v -> bf16 hi/lo
    attn_kernel<<<dim3(SEQ/128, BATCH*NHEADS), blk, SMEM_ATTN>>>(qkvh, qkvl, ctxh, ctxl);
    // h = x + ctx @ Wo + bo (fp32)
    gemm_mma<<<dim3(EMB/128, ROWS/128), blk, SMEM_GEMM>>>(
        ctxh, ctxl, wot, bo, x, h, nullptr, nullptr, ROWS, EMB, EMB, 0);
    // y = LN(h) -> bf16 hi/lo
    ln_kernel<<<ROWS, blk>>>(h, g2, s2, yh, yl);
    // ff = gelu(y @ W1 + b1) -> bf16 hi/lo
    gemm_mma<<<dim3(DFF/128, ROWS/128), blk, SMEM_GEMM>>>(
        yh, yl, w1t, b1, nullptr, nullptr, ffh, ffl, ROWS, DFF, EMB, 1);
    // out = h + ff @ W2 + b2 (fp32)
    gemm_mma<<<dim3(EMB/128, ROWS/128), blk, SMEM_GEMM>>>(
        ffh, ffl, w2t, b2, h, out, nullptr, nullptr, ROWS, EMB, DFF, 0);
}

// round 5
// speedup vs baseline: 1.9484x; 1.0037x over previous
#include <cuda_runtime.h>
#include <cuda_bf16.h>
#include <math.h>
#include <stdint.h>

#define EMB 1024
#define SEQ 2048
#define BATCH 2
#define ROWS (BATCH*SEQ)   /* 4096 */
#define DFF (4*EMB)        /* 4096 */
#define NHEADS 16
#define HD 64
#define QKV_STR (3*EMB)    /* 3072 */

// ---------------- scratch (device globals: no allocation allowed) ----------------
__device__ __nv_bfloat16 g_ln1h[ROWS*EMB];
__device__ __nv_bfloat16 g_ln1l[ROWS*EMB];
__device__ __nv_bfloat16 g_qkvh[(size_t)ROWS*QKV_STR];
__device__ __nv_bfloat16 g_qkvl[(size_t)ROWS*QKV_STR];
__device__ __nv_bfloat16 g_ctxh[ROWS*EMB];
__device__ __nv_bfloat16 g_ctxl[ROWS*EMB];
__device__ float         g_h   [ROWS*EMB];
__device__ __nv_bfloat16 g_yh  [ROWS*EMB];
__device__ __nv_bfloat16 g_yl  [ROWS*EMB];
__device__ __nv_bfloat16 g_ffh [(size_t)ROWS*DFF];
__device__ __nv_bfloat16 g_ffl [(size_t)ROWS*DFF];
// transposed + hi/lo-split weights (bf16): [0 .. N*K) = hi, [N*K .. 2*N*K) = lo
__device__ __nv_bfloat16 g_wqkvt[2*3*EMB*EMB];
__device__ __nv_bfloat16 g_wot[2*EMB*EMB];
__device__ __nv_bfloat16 g_w1t[2*EMB*DFF];
__device__ __nv_bfloat16 g_w2t[2*DFF*EMB];

// ---------------- helpers ----------------
__device__ __forceinline__ uint32_t smem_to_u32(const void* p) {
    uint32_t a;
    asm("{ .reg .u64 t; cvta.to.shared.u64 t, %1; cvt.u32.u64 %0, t; }" : "=r"(a) : "l"(p));
    return a;
}
#define SWZ(off) ((off) ^ (((off) >> 3) & 0x70))

__device__ __forceinline__ void ldsm4(uint32_t* r, uint32_t addr) {
    asm volatile("ldmatrix.sync.aligned.m8n8.x4.shared.b16 {%0,%1,%2,%3}, [%4];"
        : "=r"(r[0]), "=r"(r[1]), "=r"(r[2]), "=r"(r[3]) : "r"(addr));
}
__device__ __forceinline__ void ldsm4t(uint32_t* r, uint32_t addr) {
    asm volatile("ldmatrix.sync.aligned.m8n8.x4.trans.shared.b16 {%0,%1,%2,%3}, [%4];"
        : "=r"(r[0]), "=r"(r[1]), "=r"(r[2]), "=r"(r[3]) : "r"(addr));
}
__device__ __forceinline__ void mma_bf16(float* d, const uint32_t* a, const uint32_t* b) {
    asm volatile("mma.sync.aligned.m16n8k16.row.col.f32.bf16.bf16.f32 "
        "{%0,%1,%2,%3}, {%4,%5,%6,%7}, {%8,%9}, {%0,%1,%2,%3};"
        : "+f"(d[0]), "+f"(d[1]), "+f"(d[2]), "+f"(d[3])
        : "r"(a[0]), "r"(a[1]), "r"(a[2]), "r"(a[3]), "r"(b[0]), "r"(b[1]));
}
__device__ __forceinline__ void cp16(uint32_t s, const void* g) {
    asm volatile("cp.async.cg.shared.global [%0], [%1], 16;" :: "r"(s), "l"(g));
}
#define CP_COMMIT() asm volatile("cp.async.commit_group;" ::: "memory")
#define CP_WAIT(n)  asm volatile("cp.async.wait_group %0;" :: "n"(n) : "memory")

__device__ __forceinline__ uint32_t pack_bf16(__nv_bfloat16 a, __nv_bfloat16 b) {
    return (uint32_t)__bfloat16_as_ushort(a) | ((uint32_t)__bfloat16_as_ushort(b) << 16);
}
// pair fp32 -> packed bf16 hi + packed bf16 lo
__device__ __forceinline__ uint32_t cvt2(float a, float b, uint32_t& lo) {
    __nv_bfloat16 ha = __float2bfloat16_rn(a), hb = __float2bfloat16_rn(b);
    __nv_bfloat16 la = __float2bfloat16_rn(a - __bfloat162float(ha));
    __nv_bfloat16 lb = __float2bfloat16_rn(b - __bfloat162float(hb));
    lo = pack_bf16(la, lb);
    return pack_bf16(ha, hb);
}
__device__ __forceinline__ float gelu_f(float x)
{
    float u = 0.7978845608028654f * (x + 0.044715f * x * x * x);
    return 0.5f * x * (1.0f + tanhf(u));
}

// ---------------- layernorm: fp32 in -> bf16 hi/lo out ----------------
__global__ __launch_bounds__(256) void ln_kernel(const float* __restrict__ x,
    const float* __restrict__ g, const float* __restrict__ s,
    __nv_bfloat16* __restrict__ oh, __nv_bfloat16* __restrict__ ol)
{
    __shared__ float red[16];
    int row = blockIdx.x;
    int t = threadIdx.x;
    const float4* xr = reinterpret_cast<const float4*>(x + (size_t)row*EMB);
    float4 v = xr[t];
    float sum = v.x+v.y+v.z+v.w;
    float sq  = v.x*v.x+v.y*v.y+v.z*v.z+v.w*v.w;
    #pragma unroll
    for (int off = 16; off > 0; off >>= 1) {
        sum += __shfl_xor_sync(0xffffffffu, sum, off);
        sq  += __shfl_xor_sync(0xffffffffu, sq,  off);
    }
    int warp = t >> 5, lane = t & 31;
    if (lane == 0) { red[warp] = sum; red[warp+8] = sq; }
    __syncthreads();
    if (t < 32) {
        float a  = (lane < 8) ? red[lane]   : 0.0f;
        float b2 = (lane < 8) ? red[lane+8] : 0.0f;
        #pragma unroll
        for (int off = 4; off > 0; off >>= 1) {
            a  += __shfl_xor_sync(0xffffffffu, a,  off);
            b2 += __shfl_xor_sync(0xffffffffu, b2, off);
        }
        if (lane == 0) { red[0] = a; red[1] = b2; }
    }
    __syncthreads();
    float mean = red[0] * (1.0f/EMB);
    float var  = red[1] * (1.0f/EMB) - mean*mean;
    float inv  = rsqrtf(var + 1e-5f);
    float4 gv = reinterpret_cast<const float4*>(g)[t];
    float4 sv = reinterpret_cast<const float4*>(s)[t];
    float o0 = (v.x - mean)*inv*gv.x + sv.x;
    float o1 = (v.y - mean)*inv*gv.y + sv.y;
    float o2 = (v.z - mean)*inv*gv.z + sv.z;
    float o3 = (v.w - mean)*inv*gv.w + sv.w;
    uint32_t l01, l23;
    uint32_t h01 = cvt2(o0, o1, l01);
    uint32_t h23 = cvt2(o2, o3, l23);
    *(uint2*)(oh + (size_t)row*EMB + t*4) = make_uint2(h01, h23);
    *(uint2*)(ol + (size_t)row*EMB + t*4) = make_uint2(l01, l23);
}

// ---------------- weight transpose + bf16 hi/lo split: W[K,N] -> Wt[hi][N,K], lo at +loOff ----------------
__global__ __launch_bounds__(256) void wconv_kernel(const float* __restrict__ W,
    __nv_bfloat16* __restrict__ O, int K, int N, size_t loOff)
{
    __shared__ float tile[32][33];
    int n0 = blockIdx.x*32, k0 = blockIdx.y*32;
    int tx = threadIdx.x & 31, ty = threadIdx.x >> 5;   // 32 x 8
    #pragma unroll
    for (int i = 0; i < 4; i++)
        tile[ty + 8*i][tx] = W[(size_t)(k0 + ty + 8*i)*N + n0 + tx];
    __syncthreads();
    __nv_bfloat16* hi = O;
    __nv_bfloat16* lo = O + loOff;
    #pragma unroll
    for (int i = 0; i < 4; i++) {
        float x = tile[tx][ty + 8*i];
        __nv_bfloat16 h = __float2bfloat16_rn(x);
        __nv_bfloat16 l = __float2bfloat16_rn(x - __bfloat162float(h));
        size_t idx = (size_t)(n0 + ty + 8*i)*K + k0 + tx;
        hi[idx] = h; lo[idx] = l;
    }
}

// ---------------- mma.sync bf16 GEMM (3-pass hi/lo, cp.async double-buffer) ----------------
// Tile 128(M) x 256(N), KC=64. Warp grid 2m x 4n -> 64x64 warp tile.
// C = A(hi+lo)[M,K] @ Bt(hi+lo)[N,K]^T. outF != null -> fp32 out (+res); else bf16 hi/lo out.
#define KC 64
#define STAGE 98304
#define SMEM_GEMM (2*STAGE)
__global__ __launch_bounds__(256) void gemm_mma(
    const __nv_bfloat16* __restrict__ Ah, const __nv_bfloat16* __restrict__ Al,
    const __nv_bfloat16* __restrict__ Bt,
    const float* __restrict__ bias, const float* __restrict__ res,
    float* __restrict__ outF, __nv_bfloat16* __restrict__ outH, __nv_bfloat16* __restrict__ outL,
    int M, int N, int K, int dogelu)
{
    extern __shared__ char smem[];
    uint32_t sb = smem_to_u32(smem);
    int t = threadIdx.x, w = t >> 5, lane = t & 31;
    int wm = w >> 2, wn = w & 3;               // warp grid 2(m) x 4(n)
    int m0 = blockIdx.y*128, n0 = blockIdx.x*256;
    const __nv_bfloat16* BtLo = Bt + (size_t)N*K;

    const __nv_bfloat16* srcA[2] = { Ah + (size_t)m0*K, Al + (size_t)m0*K };
    const __nv_bfloat16* srcB[2] = { Bt + (size_t)n0*K, BtLo + (size_t)n0*K };

    float acc[4][8][4];
    #pragma unroll
    for (int mt = 0; mt < 4; mt++)
        #pragma unroll
        for (int nt = 0; nt < 8; nt++)
            #pragma unroll
            for (int e = 0; e < 4; e++) acc[mt][nt][e] = 0.0f;

    int nc = K / KC;

    // stage layout: AH 0 (16KB), AL 16384, BH 32768 (32KB), BL 65536 (32KB)
    auto issue = [&](int c, int buf) {
        uint32_t stb = sb + buf*STAGE;
        #pragma unroll
        for (int i = 0; i < 24; i++) {
            int id = t + 256*i;
            if (id < 2048) {           // A: 2 arrays x 1024 chunks
                int arr = id >> 10, cid = id & 1023;
                int row = cid >> 3, c16 = cid & 7;
                const __nv_bfloat16* gp = srcA[arr] + (size_t)row*K + c*KC + c16*8;
                cp16(stb + arr*16384 + SWZ((uint32_t)(row*128 + c16*16)), gp);
            } else {                   // B: 2 arrays x 2048 chunks
                int id2 = id - 2048;
                int arr = id2 >> 11, cid = id2 & 2047;
                int row = cid >> 3, c16 = cid & 7;
                const __nv_bfloat16* gp = srcB[arr] + (size_t)row*K + c*KC + c16*8;
                cp16(stb + 32768 + arr*32768 + SWZ((uint32_t)(row*128 + c16*16)), gp);
            }
        }
    };

    issue(0, 0);
    CP_COMMIT();

    int arow = lane & 15;
    int acol = (lane >> 4) << 4;
    int brow = ((lane >> 4) << 3) + (lane & 7);
    int bcol = ((lane >> 3) & 1) << 4;

    for (int c = 0; c < nc; c++) {
        int buf = c & 1;
        if (c + 1 < nc) { issue(c+1, buf^1); }
        CP_COMMIT();
        if (c + 1 < nc) { CP_WAIT(1); } else { CP_WAIT(0); }
        __syncthreads();

        {
            uint32_t ahB = sb + buf*STAGE;
            uint32_t alB = ahB + 16384;
            uint32_t bhB = ahB + 32768;
            uint32_t blB = ahB + 65536;
            #pragma unroll
            for (int ks = 0; ks < 4; ks++) {
                int kb = ks * 32;
                uint32_t ah[4][4], al[4][4];
                #pragma unroll
                for (int mt = 0; mt < 4; mt++) {
                    uint32_t off = SWZ((uint32_t)((wm*64 + mt*16 + arow)*128 + kb + acol));
                    ldsm4(ah[mt], ahB + off);
                    ldsm4(al[mt], alB + off);
                }
                #pragma unroll
                for (int nh = 0; nh < 4; nh++) {
                    uint32_t off = SWZ((uint32_t)((wn*64 + nh*16 + brow)*128 + kb + bcol));
                    uint32_t rh[4], rl[4];
                    ldsm4(rh, bhB + off);
                    ldsm4(rl, blB + off);
                    uint32_t b0h[2] = { rh[0], rh[1] }, b1h[2] = { rh[2], rh[3] };
                    uint32_t b0l[2] = { rl[0], rl[1] }, b1l[2] = { rl[2], rl[3] };
                    #pragma unroll
                    for (int mt = 0; mt < 4; mt++) {
                        mma_bf16(acc[mt][2*nh],   ah[mt], b0h);
                        mma_bf16(acc[mt][2*nh],   ah[mt], b0l);
                        mma_bf16(acc[mt][2*nh],   al[mt], b0h);
                        mma_bf16(acc[mt][2*nh+1], ah[mt], b1h);
                        mma_bf16(acc[mt][2*nh+1], ah[mt], b1l);
                        mma_bf16(acc[mt][2*nh+1], al[mt], b1h);
                    }
                }
            }
        }
        __syncthreads();
    }

    // ---- epilogue ----
    int mBase = m0 + wm*64;
    int nBase = n0 + wn*64;
    #pragma unroll
    for (int mt = 0; mt < 4; mt++) {
        #pragma unroll
        for (int nt = 0; nt < 8; nt++) {
            int row = mBase + mt*16 + (lane >> 2);
            int col = nBase + nt*8 + ((lane & 3) << 1);
            float v0 = acc[mt][nt][0], v1 = acc[mt][nt][1];
            float v2 = acc[mt][nt][2], v3 = acc[mt][nt][3];
            if (bias) {
                float2 bb = *(const float2*)(bias + col);
                v0 += bb.x; v1 += bb.y; v2 += bb.x; v3 += bb.y;
            }
            if (dogelu) {
                v0 = gelu_f(v0); v1 = gelu_f(v1);
                v2 = gelu_f(v2); v3 = gelu_f(v3);
            }
            if (outF) {
                if (res) {
                    float2 r0 = *(const float2*)(res + (size_t)row*N + col);
                    float2 r1 = *(const float2*)(res + (size_t)(row+8)*N + col);
                    v0 += r0.x; v1 += r0.y; v2 += r1.x; v3 += r1.y;
                }
                *(float2*)(outF + (size_t)row*N + col) = make_float2(v0, v1);
                *(float2*)(outF + (size_t)(row+8)*N + col) = make_float2(v2, v3);
            } else {
                uint32_t lo0, lo1;
                uint32_t hi0 = cvt2(v0, v1, lo0);
                uint32_t hi1 = cvt2(v2, v3, lo1);
                *(uint32_t*)(outH + (size_t)row*N + col) = hi0;
                *(uint32_t*)(outL + (size_t)row*N + col) = lo0;
                *(uint32_t*)(outH + (size_t)(row+8)*N + col) = hi1;
                *(uint32_t*)(outL + (size_t)(row+8)*N + col) = lo1;
            }
        }
    }
}

// ---------------- causal flash attention, bf16 mma with hi/lo 3-pass ----------------
// QKV packed bf16 hi/lo [ROWS, 3072]; out ctx bf16 hi/lo [ROWS, 1024].
// Block: 256 thr (8 warps), q-tile 128 (warp w owns rows w*16..+15), kv-tile 64.
// qt reversed: longest (largest qt) blocks launch first for wave packing.
#define SMEM_ATTN (32768 + 2*32768)
__global__ __launch_bounds__(256) void attn_kernel(
    const __nv_bfloat16* __restrict__ Qh, const __nv_bfloat16* __restrict__ Ql,
    __nv_bfloat16* __restrict__ Ch, __nv_bfloat16* __restrict__ Cl)
{
    extern __shared__ char smem[];
    uint32_t sb = smem_to_u32(smem);
    int t = threadIdx.x, w = t >> 5, lane = t & 31;
    int qt = gridDim.x - 1 - blockIdx.x;
    int bh_ = blockIdx.y;
    int h = bh_ & 15;
    size_t rowOff = (size_t)(bh_ >> 4) * SEQ;      // batch row offset
    int q0 = qt * 128;
    int colQ = h*64, colK = 1024 + h*64, colV = 2048 + h*64;

    // ---- async load Q (hi/lo) ----
    #pragma unroll
    for (int i = 0; i < 8; i++) {
        int id = t + 256*i;
        int arr = id >> 10;              // 0 = hi, 1 = lo
        int cid = id & 1023;
        int row = cid >> 3, c16 = cid & 7;
        const __nv_bfloat16* gp = (arr ? Ql : Qh) + (rowOff + q0 + row)*QKV_STR + colQ + c16*8;
        cp16(sb + arr*16384 + SWZ((uint32_t)(row*128 + c16*16)), gp);
    }
    CP_COMMIT();

    int nkt = 2*qt + 2;

    // issue K/V stage
    auto issue = [&](int kt, int buf) {
        uint32_t stb = sb + 32768 + buf*32768;
        int k0 = kt*64;
        #pragma unroll
        for (int i = 0; i < 8; i++) {
            int id = t + 256*i;
            int arr = id >> 9;           // 0 KH, 1 KL, 2 VH, 3 VL
            int cid = id & 511;
            int row = cid >> 3, c16 = cid & 7;
            const __nv_bfloat16* base = (arr & 1) ? Ql : Qh;
            int col = (arr < 2) ? colK : colV;
            const __nv_bfloat16* gp = base + (rowOff + k0 + row)*QKV_STR + col + c16*8;
            cp16(stb + arr*8192 + SWZ((uint32_t)(row*128 + c16*16)), gp);
        }
    };
    issue(0, 0);
    CP_COMMIT();
    CP_WAIT(1);          // Q ready
    __syncthreads();

    // ---- Q fragments to registers ----
    uint32_t qh[4][4], ql[4][4];
    {
        int arow = lane & 15;
        int acol = (lane >> 4) << 4;
        #pragma unroll
        for (int kf = 0; kf < 4; kf++) {
            uint32_t off = SWZ((uint32_t)((w*16 + arow)*128 + kf*32 + acol));
            ldsm4(qh[kf], sb + off);
            ldsm4(ql[kf], sb + 16384 + off);
        }
    }

    float o[8][4];
    #pragma unroll
    for (int nt = 0; nt < 8; nt++)
        #pragma unroll
        for (int e = 0; e < 4; e++) o[nt][e] = 0.0f;
    float mst0 = -1e30f, mst1 = -1e30f, lst0 = 0.0f, lst1 = 0.0f;

    int r0g = q0 + w*16 + (lane >> 2);
    int r1g = r0g + 8;

    for (int kt = 0; kt < nkt; kt++) {
        int buf = kt & 1;
        if (kt + 1 < nkt) issue(kt+1, buf^1);
        CP_COMMIT();
        if (kt + 1 < nkt) { CP_WAIT(1); } else { CP_WAIT(0); }
        __syncthreads();

        int k0 = kt*64;
        if (k0 <= q0 + w*16 + 15) {     // at least one unmasked element for this warp
            uint32_t stb = sb + 32768 + buf*32768;
            uint32_t khB = stb, klB = stb + 8192, vhB = stb + 16384, vlB = stb + 24576;

            // ---- S = Q @ K^T (3 passes) ----
            float s[8][4];
            #pragma unroll
            for (int nt = 0; nt < 8; nt++)
                #pragma unroll
                for (int e = 0; e < 4; e++) s[nt][e] = 0.0f;
            {
                int brow = ((lane >> 4) << 3) + (lane & 7);
                int bcol = ((lane >> 3) & 1) << 4;
                #pragma unroll
                for (int ks = 0; ks < 4; ks++) {
                    int kb = ks*32;
                    uint32_t bh[8][2], bl[8][2];
                    #pragma unroll
                    for (int nh = 0; nh < 4; nh++) {
                        uint32_t off = SWZ((uint32_t)((nh*16 + brow)*128 + kb + bcol));
                        uint32_t r[4];
                        ldsm4(r, khB + off);
                        bh[nh*2][0] = r[0]; bh[nh*2][1] = r[1];
                        bh[nh*2+1][0] = r[2]; bh[nh*2+1][1] = r[3];
                        ldsm4(r, klB + off);
                        bl[nh*2][0] = r[0]; bl[nh*2][1] = r[1];
                        bl[nh*2+1][0] = r[2]; bl[nh*2+1][1] = r[3];
                    }
                    #pragma unroll
                    for (int nt = 0; nt < 8; nt++) {
                        mma_bf16(s[nt], qh[ks], bh[nt]);
                        mma_bf16(s[nt], qh[ks], bl[nt]);
                        mma_bf16(s[nt], ql[ks], bh[nt]);
                    }
                }
            }

            // ---- scale + causal mask + online softmax ----
            float mx0 = -1e30f, mx1 = -1e30f;
            #pragma unroll
            for (int nt = 0; nt < 8; nt++) {
                int kgBase = k0 + nt*8 + ((lane & 3) << 1);
                #pragma unroll
                for (int e = 0; e < 4; e++) {
                    float v = s[nt][e] * 0.125f;
                    int kg = kgBase + (e & 1);
                    int qg = (e < 2) ? r0g : r1g;
                    v = (kg <= qg) ? v : -1e30f;
                    s[nt][e] = v;
                    if (e < 2) mx0 = fmaxf(mx0, v); else mx1 = fmaxf(mx1, v);
                }
            }
            mx0 = fmaxf(mx0, __shfl_xor_sync(0xffffffffu, mx0, 1));
            mx0 = fmaxf(mx0, __shfl_xor_sync(0xffffffffu, mx0, 2));
            mx1 = fmaxf(mx1, __shfl_xor_sync(0xffffffffu, mx1, 1));
            mx1 = fmaxf(mx1, __shfl_xor_sync(0xffffffffu, mx1, 2));
            float mn0 = fmaxf(mst0, mx0), mn1 = fmaxf(mst1, mx1);
            float a0 = __expf(mst0 - mn0), a1 = __expf(mst1 - mn1);
            mst0 = mn0; mst1 = mn1;
            float s0 = 0.0f, s1 = 0.0f;
            #pragma unroll
            for (int nt = 0; nt < 8; nt++) {
                float p0 = __expf(s[nt][0] - mn0);
                float p1 = __expf(s[nt][1] - mn0);
                float p2 = __expf(s[nt][2] - mn1);
                float p3 = __expf(s[nt][3] - mn1);
                s[nt][0] = p0; s[nt][1] = p1; s[nt][2] = p2; s[nt][3] = p3;
                s0 += p0 + p1; s1 += p2 + p3;
            }
            s0 += __shfl_xor_sync(0xffffffffu, s0, 1);
            s0 += __shfl_xor_sync(0xffffffffu, s0, 2);
            s1 += __shfl_xor_sync(0xffffffffu, s1, 1);
            s1 += __shfl_xor_sync(0xffffffffu, s1, 2);
            lst0 = lst0*a0 + s0;
            lst1 = lst1*a1 + s1;
            #pragma unroll
            for (int nt = 0; nt < 8; nt++) {
                o[nt][0] *= a0; o[nt][1] *= a0;
                o[nt][2] *= a1; o[nt][3] *= a1;
            }

            // ---- O += P @ V (3 passes) ----
            #pragma unroll
            for (int kk = 0; kk < 4; kk++) {
                uint32_t ph[4], pl[4];
                ph[0] = cvt2(s[2*kk][0],   s[2*kk][1],   pl[0]);
                ph[1] = cvt2(s[2*kk][2],   s[2*kk][3],   pl[1]);
                ph[2] = cvt2(s[2*kk+1][0], s[2*kk+1][1], pl[2]);
                ph[3] = cvt2(s[2*kk+1][2], s[2*kk+1][3], pl[3]);
                #pragma unroll
                for (int nv = 0; nv < 4; nv++) {
                    uint32_t off = SWZ((uint32_t)((kk*16 + (lane & 15))*128 + (nv*16 + 8*(lane >> 4))*2));
                    uint32_t rh[4], rl[4];
                    ldsm4t(rh, vhB + off);
                    ldsm4t(rl, vlB + off);
                    uint32_t b0h[2] = { rh[0], rh[1] }, b1h[2] = { rh[2], rh[3] };
                    uint32_t b0l[2] = { rl[0], rl[1] }, b1l[2] = { rl[2], rl[3] };
                    mma_bf16(o[2*nv],   ph, b0h);
                    mma_bf16(o[2*nv],   pl, b0h);
                    mma_bf16(o[2*nv],   ph, b0l);
                    mma_bf16(o[2*nv+1], ph, b1h);
                    mma_bf16(o[2*nv+1], pl, b1h);
                    mma_bf16(o[2*nv+1], ph, b1l);
                }
            }
        }
        __syncthreads();
    }

    // ---- epilogue: O/l -> bf16 hi/lo ctx ----
    float li0 = 1.0f / lst0, li1 = 1.0f / lst1;
    int colB = h*64 + ((lane & 3) << 1);
    size_t row0 = rowOff + r0g, row1 = rowOff + r1g;
    #pragma unroll
    for (int nt = 0; nt < 8; nt++) {
        int col = colB + nt*8;
        uint32_t lo0, lo1;
        uint32_t hi0 = cvt2(o[nt][0]*li0, o[nt][1]*li0, lo0);
        uint32_t hi1 = cvt2(o[nt][2]*li1, o[nt][3]*li1, lo1);
        *(uint32_t*)(Ch + row0*EMB + col) = hi0;
        *(uint32_t*)(Cl + row0*EMB + col) = lo0;
        *(uint32_t*)(Ch + row1*EMB + col) = hi1;
        *(uint32_t*)(Cl + row1*EMB + col) = lo1;
    }
}

// ---------------- launch ----------------
extern "C" void kernel_launch(void* const* d_in, const int* in_sizes, int n_in,
                              void* d_out, int out_size)
{
    const float* x  = (const float*)d_in[0];
    const float* Wq = (const float*)d_in[1];
    const float* Wk = (const float*)d_in[2];
    const float* Wv = (const float*)d_in[3];
    const float* Wo = (const float*)d_in[4];
    const float* bo = (const float*)d_in[5];
    const float* W1 = (const float*)d_in[6];
    const float* b1 = (const float*)d_in[7];
    const float* W2 = (const float*)d_in[8];
    const float* b2 = (const float*)d_in[9];
    const float* g1 = (const float*)d_in[10];
    const float* s1 = (const float*)d_in[11];
    const float* g2 = (const float*)d_in[12];
    const float* s2 = (const float*)d_in[13];
    float* out = (float*)d_out;

    __nv_bfloat16 *ln1h, *ln1l, *qkvh, *qkvl, *ctxh, *ctxl, *yh, *yl, *ffh, *ffl;
    __nv_bfloat16 *wqkvt, *wot, *w1t, *w2t;
    float *h;
    cudaGetSymbolAddress((void**)&ln1h, g_ln1h);
    cudaGetSymbolAddress((void**)&ln1l, g_ln1l);
    cudaGetSymbolAddress((void**)&qkvh, g_qkvh);
    cudaGetSymbolAddress((void**)&qkvl, g_qkvl);
    cudaGetSymbolAddress((void**)&ctxh, g_ctxh);
    cudaGetSymbolAddress((void**)&ctxl, g_ctxl);
    cudaGetSymbolAddress((void**)&h,    g_h);
    cudaGetSymbolAddress((void**)&yh,   g_yh);
    cudaGetSymbolAddress((void**)&yl,   g_yl);
    cudaGetSymbolAddress((void**)&ffh,  g_ffh);
    cudaGetSymbolAddress((void**)&ffl,  g_ffl);
    cudaGetSymbolAddress((void**)&wqkvt, g_wqkvt);
    cudaGetSymbolAddress((void**)&wot,  g_wot);
    cudaGetSymbolAddress((void**)&w1t,  g_w1t);
    cudaGetSymbolAddress((void**)&w2t,  g_w2t);

    cudaFuncSetAttribute(gemm_mma, cudaFuncAttributeMaxDynamicSharedMemorySize, SMEM_GEMM);
    cudaFuncSetAttribute(attn_kernel, cudaFuncAttributeMaxDynamicSharedMemorySize, SMEM_ATTN);

    dim3 blk(256);
    size_t qkvLo = (size_t)QKV_STR*EMB;

    // weight transpose + bf16 hi/lo split
    wconv_kernel<<<dim3(EMB/32, EMB/32), blk>>>(Wq, wqkvt,                     EMB, EMB, qkvLo);
    wconv_kernel<<<dim3(EMB/32, EMB/32), blk>>>(Wk, wqkvt + (size_t)EMB*EMB,   EMB, EMB, qkvLo);
    wconv_kernel<<<dim3(EMB/32, EMB/32), blk>>>(Wv, wqkvt + (size_t)2*EMB*EMB, EMB, EMB, qkvLo);
    wconv_kernel<<<dim3(EMB/32, EMB/32), blk>>>(Wo, wot, EMB, EMB, (size_t)EMB*EMB);
    wconv_kernel<<<dim3(DFF/32, EMB/32), blk>>>(W1, w1t, EMB, DFF, (size_t)EMB*DFF);
    wconv_kernel<<<dim3(EMB/32, DFF/32), blk>>>(W2, w2t, DFF, EMB, (size_t)DFF*EMB);

    // ln1 = LN(x) -> bf16 hi/lo
    ln_kernel<<<ROWS, blk>>>(x, g1, s1, ln1h, ln1l);
    // qkv = ln1 @ [Wq|Wk|Wv] -> bf16 hi/lo
    gemm_mma<<<dim3(QKV_STR/256, ROWS/128), blk, SMEM_GEMM>>>(
        ln1h, ln1l, wqkvt, nullptr, nullptr, nullptr, qkvh, qkvl, ROWS, QKV_STR, EMB, 0);
    // ctx = causal softmax(qk^T/8) v -> bf16 hi/lo
    attn_kernel<<<dim3(SEQ/128, BATCH*NHEADS), blk, SMEM_ATTN>>>(qkvh, qkvl, ctxh, ctxl);
    // h = x + ctx @ Wo + bo (fp32)
    gemm_mma<<<dim3(EMB/256, ROWS/128), blk, SMEM_GEMM>>>(
        ctxh, ctxl, wot, bo, x, h, nullptr, nullptr, ROWS, EMB, EMB, 0);
    // y = LN(h) -> bf16 hi/lo
    ln_kernel<<<ROWS, blk>>>(h, g2, s2, yh, yl);
    // ff = gelu(y @ W1 + b1) -> bf16 hi/lo
    gemm_mma<<<dim3(DFF/256, ROWS/128), blk, SMEM_GEMM>>>(
        yh, yl, w1t, b1, nullptr, nullptr, ffh, ffl, ROWS, DFF, EMB, 1);
    // out = h + ff @ W2 + b2 (fp32)
    gemm_mma<<<dim3(EMB/256, ROWS/128), blk, SMEM_GEMM>>>(
        ffh, ffl, w2t, b2, h, out, nullptr, nullptr, ROWS, EMB, DFF, 0);
}

// round 6
// speedup vs baseline: 4.1134x; 2.1111x over previous
#include <cuda_runtime.h>
#include <cuda_bf16.h>
#include <cuda_fp16.h>
#include <math.h>
#include <stdint.h>

#define EMB 1024
#define SEQ 2048
#define BATCH 2
#define ROWS (BATCH*SEQ)   /* 4096 */
#define DFF (4*EMB)        /* 4096 */
#define NHEADS 16
#define HD 64
#define QKV_STR (3*EMB)    /* 3072 */

// ---------------- scratch (device globals: no allocation allowed) ----------------
__device__ __half g_ln1h[ROWS*EMB];
__device__ __half g_ln1l[ROWS*EMB];
__device__ __half g_qkvh[(size_t)ROWS*QKV_STR];
__device__ __half g_qkvl[(size_t)ROWS*QKV_STR];
__device__ __half g_ctxh[ROWS*EMB];
__device__ __half g_ctxl[ROWS*EMB];
__device__ float  g_h   [ROWS*EMB];
__device__ __half g_yh  [ROWS*EMB];
__device__ __half g_yl  [ROWS*EMB];
__device__ __half g_ffh [(size_t)ROWS*DFF];
__device__ __half g_ffl [(size_t)ROWS*DFF];
// transposed fp16 weights: Wt[N,K]
__device__ __half g_wqkvt[3*EMB*EMB];
__device__ __half g_wot[EMB*EMB];
__device__ __half g_w1t[EMB*DFF];
__device__ __half g_w2t[DFF*EMB];

// ---------------- helpers ----------------
__device__ __forceinline__ uint32_t smem_to_u32(const void* p) {
    uint32_t a;
    asm("{ .reg .u64 t; cvta.to.shared.u64 t, %1; cvt.u32.u64 %0, t; }" : "=r"(a) : "l"(p));
    return a;
}
#define SWZ(off) ((off) ^ (((off) >> 3) & 0x70))

__device__ __forceinline__ void ldsm4(uint32_t* r, uint32_t addr) {
    asm volatile("ldmatrix.sync.aligned.m8n8.x4.shared.b16 {%0,%1,%2,%3}, [%4];"
        : "=r"(r[0]), "=r"(r[1]), "=r"(r[2]), "=r"(r[3]) : "r"(addr));
}
__device__ __forceinline__ void ldsm4t(uint32_t* r, uint32_t addr) {
    asm volatile("ldmatrix.sync.aligned.m8n8.x4.trans.shared.b16 {%0,%1,%2,%3}, [%4];"
        : "=r"(r[0]), "=r"(r[1]), "=r"(r[2]), "=r"(r[3]) : "r"(addr));
}
__device__ __forceinline__ void mma_f16(float* d, const uint32_t* a, const uint32_t* b) {
    asm volatile("mma.sync.aligned.m16n8k16.row.col.f32.f16.f16.f32 "
        "{%0,%1,%2,%3}, {%4,%5,%6,%7}, {%8,%9}, {%0,%1,%2,%3};"
        : "+f"(d[0]), "+f"(d[1]), "+f"(d[2]), "+f"(d[3])
        : "r"(a[0]), "r"(a[1]), "r"(a[2]), "r"(a[3]), "r"(b[0]), "r"(b[1]));
}
__device__ __forceinline__ void cp16(uint32_t s, const void* g) {
    asm volatile("cp.async.cg.shared.global [%0], [%1], 16;" :: "r"(s), "l"(g));
}
#define CP_COMMIT() asm volatile("cp.async.commit_group;" ::: "memory")
#define CP_WAIT(n)  asm volatile("cp.async.wait_group %0;" :: "n"(n) : "memory")

__device__ __forceinline__ uint32_t pack_h(__half a, __half b) {
    return (uint32_t)__half_as_ushort(a) | ((uint32_t)__half_as_ushort(b) << 16);
}
// pair fp32 -> packed fp16 hi + packed fp16 lo
__device__ __forceinline__ uint32_t cvt2h(float a, float b, uint32_t& lo) {
    __half ha = __float2half_rn(a), hb = __float2half_rn(b);
    __half la = __float2half_rn(a - __half2float(ha));
    __half lb = __float2half_rn(b - __half2float(hb));
    lo = pack_h(la, lb);
    return pack_h(ha, hb);
}
__device__ __forceinline__ float gelu_f(float x)
{
    float u = 0.7978845608028654f * (x + 0.044715f * x * x * x);
    return 0.5f * x * (1.0f + tanhf(u));
}

// ---------------- layernorm: fp32 in -> fp16 hi/lo out ----------------
__global__ __launch_bounds__(256) void ln_kernel(const float* __restrict__ x,
    const float* __restrict__ g, const float* __restrict__ s,
    __half* __restrict__ oh, __half* __restrict__ ol)
{
    __shared__ float red[16];
    int row = blockIdx.x;
    int t = threadIdx.x;
    const float4* xr = reinterpret_cast<const float4*>(x + (size_t)row*EMB);
    float4 v = xr[t];
    float sum = v.x+v.y+v.z+v.w;
    float sq  = v.x*v.x+v.y*v.y+v.z*v.z+v.w*v.w;
    #pragma unroll
    for (int off = 16; off > 0; off >>= 1) {
        sum += __shfl_xor_sync(0xffffffffu, sum, off);
        sq  += __shfl_xor_sync(0xffffffffu, sq,  off);
    }
    int warp = t >> 5, lane = t & 31;
    if (lane == 0) { red[warp] = sum; red[warp+8] = sq; }
    __syncthreads();
    if (t < 32) {
        float a  = (lane < 8) ? red[lane]   : 0.0f;
        float b2 = (lane < 8) ? red[lane+8] : 0.0f;
        #pragma unroll
        for (int off = 4; off > 0; off >>= 1) {
            a  += __shfl_xor_sync(0xffffffffu, a,  off);
            b2 += __shfl_xor_sync(0xffffffffu, b2, off);
        }
        if (lane == 0) { red[0] = a; red[1] = b2; }
    }
    __syncthreads();
    float mean = red[0] * (1.0f/EMB);
    float var  = red[1] * (1.0f/EMB) - mean*mean;
    float inv  = rsqrtf(var + 1e-5f);
    float4 gv = reinterpret_cast<const float4*>(g)[t];
    float4 sv = reinterpret_cast<const float4*>(s)[t];
    float o0 = (v.x - mean)*inv*gv.x + sv.x;
    float o1 = (v.y - mean)*inv*gv.y + sv.y;
    float o2 = (v.z - mean)*inv*gv.z + sv.z;
    float o3 = (v.w - mean)*inv*gv.w + sv.w;
    uint32_t l01, l23;
    uint32_t h01 = cvt2h(o0, o1, l01);
    uint32_t h23 = cvt2h(o2, o3, l23);
    *(uint2*)(oh + (size_t)row*EMB + t*4) = make_uint2(h01, h23);
    *(uint2*)(ol + (size_t)row*EMB + t*4) = make_uint2(l01, l23);
}

// ---------------- weight transpose: W[K,N] fp32 -> Wt[N,K] fp16 ----------------
__global__ __launch_bounds__(256) void wconv_kernel(const float* __restrict__ W,
    __half* __restrict__ O, int K, int N)
{
    __shared__ float tile[32][33];
    int n0 = blockIdx.x*32, k0 = blockIdx.y*32;
    int tx = threadIdx.x & 31, ty = threadIdx.x >> 5;   // 32 x 8
    #pragma unroll
    for (int i = 0; i < 4; i++)
        tile[ty + 8*i][tx] = W[(size_t)(k0 + ty + 8*i)*N + n0 + tx];
    __syncthreads();
    #pragma unroll
    for (int i = 0; i < 4; i++) {
        float x = tile[tx][ty + 8*i];
        O[(size_t)(n0 + ty + 8*i)*K + k0 + tx] = __float2half_rn(x);
    }
}

// ---------------- mma.sync fp16 GEMM (2-pass A hi/lo, 3-stage cp.async) ----------------
// Tile 128(M) x 256(N), KC=64. Warp grid 2m x 4n -> 64x64 warp tile.
// C = (Ahi+Alo)[M,K] @ Bt[N,K]^T. outF != null -> fp32 out (+res); else fp16 hi/lo out.
#define KC 64
#define STAGE 65536
#define SMEM_GEMM (3*STAGE)
__global__ __launch_bounds__(256) void gemm_mma(
    const __half* __restrict__ Ah, const __half* __restrict__ Al,
    const __half* __restrict__ Bt,
    const float* __restrict__ bias, const float* __restrict__ res,
    float* __restrict__ outF, __half* __restrict__ outH, __half* __restrict__ outL,
    int M, int N, int K, int dogelu)
{
    extern __shared__ char smem[];
    uint32_t sb = smem_to_u32(smem);
    int t = threadIdx.x, w = t >> 5, lane = t & 31;
    int wm = w >> 2, wn = w & 3;               // warp grid 2(m) x 4(n)
    int m0 = blockIdx.y*128, n0 = blockIdx.x*256;

    const __half* srcA[2] = { Ah + (size_t)m0*K, Al + (size_t)m0*K };
    const __half* srcB = Bt + (size_t)n0*K;

    float acc[4][8][4];
    #pragma unroll
    for (int mt = 0; mt < 4; mt++)
        #pragma unroll
        for (int nt = 0; nt < 8; nt++)
            #pragma unroll
            for (int e = 0; e < 4; e++) acc[mt][nt][e] = 0.0f;

    int nc = K / KC;

    // stage layout: AH @0 (16KB), AL @16384, B @32768 (32KB)
    auto issue = [&](int c, int buf) {
        uint32_t stb = sb + buf*STAGE;
        #pragma unroll
        for (int i = 0; i < 16; i++) {
            int id = t + 256*i;
            if (id < 2048) {           // A: 2 arrays x 1024 chunks
                int arr = id >> 10, cid = id & 1023;
                int row = cid >> 3, c16 = cid & 7;
                const __half* gp = srcA[arr] + (size_t)row*K + c*KC + c16*8;
                cp16(stb + arr*16384 + SWZ((uint32_t)(row*128 + c16*16)), gp);
            } else {                   // B: 2048 chunks
                int cid = id - 2048;
                int row = cid >> 3, c16 = cid & 7;
                const __half* gp = srcB + (size_t)row*K + c*KC + c16*8;
                cp16(stb + 32768 + SWZ((uint32_t)(row*128 + c16*16)), gp);
            }
        }
    };

    issue(0, 0);
    CP_COMMIT();
    if (nc > 1) { issue(1, 1); CP_COMMIT(); }

    int arow = lane & 15;
    int acol = (lane >> 4) << 4;
    int brow = ((lane >> 4) << 3) + (lane & 7);
    int bcol = ((lane >> 3) & 1) << 4;

    for (int c = 0; c < nc; c++) {
        int buf = c % 3;
        if (c + 2 < nc) { issue(c+2, (c+2) % 3); CP_COMMIT(); CP_WAIT(2); }
        else if (c + 1 < nc) { CP_WAIT(1); }
        else { CP_WAIT(0); }
        __syncthreads();

        {
            uint32_t ahB = sb + buf*STAGE;
            uint32_t alB = ahB + 16384;
            uint32_t bB  = ahB + 32768;
            #pragma unroll
            for (int ks = 0; ks < 4; ks++) {
                int kb = ks * 32;
                uint32_t ah[4][4], al[4][4];
                #pragma unroll
                for (int mt = 0; mt < 4; mt++) {
                    uint32_t off = SWZ((uint32_t)((wm*64 + mt*16 + arow)*128 + kb + acol));
                    ldsm4(ah[mt], ahB + off);
                    ldsm4(al[mt], alB + off);
                }
                #pragma unroll
                for (int nh = 0; nh < 4; nh++) {
                    uint32_t off = SWZ((uint32_t)((wn*64 + nh*16 + brow)*128 + kb + bcol));
                    uint32_t rb[4];
                    ldsm4(rb, bB + off);
                    uint32_t b0[2] = { rb[0], rb[1] }, b1[2] = { rb[2], rb[3] };
                    #pragma unroll
                    for (int mt = 0; mt < 4; mt++) {
                        mma_f16(acc[mt][2*nh],   ah[mt], b0);
                        mma_f16(acc[mt][2*nh],   al[mt], b0);
                        mma_f16(acc[mt][2*nh+1], ah[mt], b1);
                        mma_f16(acc[mt][2*nh+1], al[mt], b1);
                    }
                }
            }
        }
        __syncthreads();
    }

    // ---- epilogue ----
    int mBase = m0 + wm*64;
    int nBase = n0 + wn*64;
    #pragma unroll
    for (int mt = 0; mt < 4; mt++) {
        #pragma unroll
        for (int nt = 0; nt < 8; nt++) {
            int row = mBase + mt*16 + (lane >> 2);
            int col = nBase + nt*8 + ((lane & 3) << 1);
            float v0 = acc[mt][nt][0], v1 = acc[mt][nt][1];
            float v2 = acc[mt][nt][2], v3 = acc[mt][nt][3];
            if (bias) {
                float2 bb = *(const float2*)(bias + col);
                v0 += bb.x; v1 += bb.y; v2 += bb.x; v3 += bb.y;
            }
            if (dogelu) {
                v0 = gelu_f(v0); v1 = gelu_f(v1);
                v2 = gelu_f(v2); v3 = gelu_f(v3);
            }
            if (outF) {
                if (res) {
                    float2 r0 = *(const float2*)(res + (size_t)row*N + col);
                    float2 r1 = *(const float2*)(res + (size_t)(row+8)*N + col);
                    v0 += r0.x; v1 += r0.y; v2 += r1.x; v3 += r1.y;
                }
                *(float2*)(outF + (size_t)row*N + col) = make_float2(v0, v1);
                *(float2*)(outF + (size_t)(row+8)*N + col) = make_float2(v2, v3);
            } else {
                uint32_t lo0, lo1;
                uint32_t hi0 = cvt2h(v0, v1, lo0);
                uint32_t hi1 = cvt2h(v2, v3, lo1);
                *(uint32_t*)(outH + (size_t)row*N + col) = hi0;
                *(uint32_t*)(outL + (size_t)row*N + col) = lo0;
                *(uint32_t*)(outH + (size_t)(row+8)*N + col) = hi1;
                *(uint32_t*)(outL + (size_t)(row+8)*N + col) = lo1;
            }
        }
    }
}

// ---------------- causal flash attention, fp16 mma 2-pass ----------------
// QKV packed fp16 hi/lo [ROWS, 3072]; out ctx fp16 hi/lo [ROWS, 1024].
// Block: 256 thr (8 warps), q-tile 128 (warp w owns rows w*16..+15), kv-tile 64.
// S = Qhi K + Qlo K (K = hi only). PV: P(single fp16) x (Vhi + Vlo).
#define STAGE_ATT 24576
#define SMEM_ATTN (32768 + 2*STAGE_ATT)
__global__ __launch_bounds__(256) void attn_kernel(
    const __half* __restrict__ Qh, const __half* __restrict__ Ql,
    __half* __restrict__ Ch, __half* __restrict__ Cl)
{
    extern __shared__ char smem[];
    uint32_t sb = smem_to_u32(smem);
    int t = threadIdx.x, w = t >> 5, lane = t & 31;
    int qt = gridDim.x - 1 - blockIdx.x;
    int bh_ = blockIdx.y;
    int h = bh_ & 15;
    size_t rowOff = (size_t)(bh_ >> 4) * SEQ;      // batch row offset
    int q0 = qt * 128;
    int colQ = h*64, colK = 1024 + h*64, colV = 2048 + h*64;

    // ---- async load Q (hi/lo) ----
    #pragma unroll
    for (int i = 0; i < 8; i++) {
        int id = t + 256*i;
        int arr = id >> 10;              // 0 = hi, 1 = lo
        int cid = id & 1023;
        int row = cid >> 3, c16 = cid & 7;
        const __half* gp = (arr ? Ql : Qh) + (rowOff + q0 + row)*QKV_STR + colQ + c16*8;
        cp16(sb + arr*16384 + SWZ((uint32_t)(row*128 + c16*16)), gp);
    }
    CP_COMMIT();

    int nkt = 2*qt + 2;

    // issue K/V stage: KH @0, VH @8192, VL @16384
    auto issue = [&](int kt, int buf) {
        uint32_t stb = sb + 32768 + buf*STAGE_ATT;
        int k0 = kt*64;
        #pragma unroll
        for (int i = 0; i < 6; i++) {
            int id = t + 256*i;
            int arr = id >> 9;           // 0 KH, 1 VH, 2 VL
            int cid = id & 511;
            int row = cid >> 3, c16 = cid & 7;
            const __half* base = (arr == 2) ? Ql : Qh;
            int col = (arr == 0) ? colK : colV;
            const __half* gp = base + (rowOff + k0 + row)*QKV_STR + col + c16*8;
            cp16(stb + arr*8192 + SWZ((uint32_t)(row*128 + c16*16)), gp);
        }
    };
    issue(0, 0);
    CP_COMMIT();
    CP_WAIT(1);          // Q ready
    __syncthreads();

    // ---- Q fragments to registers ----
    uint32_t qh[4][4], ql[4][4];
    {
        int arow = lane & 15;
        int acol = (lane >> 4) << 4;
        #pragma unroll
        for (int kf = 0; kf < 4; kf++) {
            uint32_t off = SWZ((uint32_t)((w*16 + arow)*128 + kf*32 + acol));
            ldsm4(qh[kf], sb + off);
            ldsm4(ql[kf], sb + 16384 + off);
        }
    }

    float o[8][4];
    #pragma unroll
    for (int nt = 0; nt < 8; nt++)
        #pragma unroll
        for (int e = 0; e < 4; e++) o[nt][e] = 0.0f;
    float mst0 = -1e30f, mst1 = -1e30f, lst0 = 0.0f, lst1 = 0.0f;

    int r0g = q0 + w*16 + (lane >> 2);
    int r1g = r0g + 8;

    for (int kt = 0; kt < nkt; kt++) {
        int buf = kt & 1;
        if (kt + 1 < nkt) issue(kt+1, buf^1);
        CP_COMMIT();
        if (kt + 1 < nkt) { CP_WAIT(1); } else { CP_WAIT(0); }
        __syncthreads();

        int k0 = kt*64;
        if (k0 <= q0 + w*16 + 15) {     // at least one unmasked element for this warp
            uint32_t stb = sb + 32768 + buf*STAGE_ATT;
            uint32_t khB = stb, vhB = stb + 8192, vlB = stb + 16384;

            // ---- S = Q @ K^T (2 passes) ----
            float s[8][4];
            #pragma unroll
            for (int nt = 0; nt < 8; nt++)
                #pragma unroll
                for (int e = 0; e < 4; e++) s[nt][e] = 0.0f;
            {
                int brow = ((lane >> 4) << 3) + (lane & 7);
                int bcol = ((lane >> 3) & 1) << 4;
                #pragma unroll
                for (int ks = 0; ks < 4; ks++) {
                    int kb = ks*32;
                    #pragma unroll
                    for (int nh = 0; nh < 4; nh++) {
                        uint32_t off = SWZ((uint32_t)((nh*16 + brow)*128 + kb + bcol));
                        uint32_t rb[4];
                        ldsm4(rb, khB + off);
                        uint32_t b0[2] = { rb[0], rb[1] }, b1[2] = { rb[2], rb[3] };
                        mma_f16(s[2*nh],   qh[ks], b0);
                        mma_f16(s[2*nh],   ql[ks], b0);
                        mma_f16(s[2*nh+1], qh[ks], b1);
                        mma_f16(s[2*nh+1], ql[ks], b1);
                    }
                }
            }

            // ---- scale + causal mask + online softmax ----
            float mx0 = -1e30f, mx1 = -1e30f;
            #pragma unroll
            for (int nt = 0; nt < 8; nt++) {
                int kgBase = k0 + nt*8 + ((lane & 3) << 1);
                #pragma unroll
                for (int e = 0; e < 4; e++) {
                    float v = s[nt][e] * 0.125f;
                    int kg = kgBase + (e & 1);
                    int qg = (e < 2) ? r0g : r1g;
                    v = (kg <= qg) ? v : -1e30f;
                    s[nt][e] = v;
                    if (e < 2) mx0 = fmaxf(mx0, v); else mx1 = fmaxf(mx1, v);
                }
            }
            mx0 = fmaxf(mx0, __shfl_xor_sync(0xffffffffu, mx0, 1));
            mx0 = fmaxf(mx0, __shfl_xor_sync(0xffffffffu, mx0, 2));
            mx1 = fmaxf(mx1, __shfl_xor_sync(0xffffffffu, mx1, 1));
            mx1 = fmaxf(mx1, __shfl_xor_sync(0xffffffffu, mx1, 2));
            float mn0 = fmaxf(mst0, mx0), mn1 = fmaxf(mst1, mx1);
            float a0 = __expf(mst0 - mn0), a1 = __expf(mst1 - mn1);
            mst0 = mn0; mst1 = mn1;
            float s0 = 0.0f, s1 = 0.0f;
            #pragma unroll
            for (int nt = 0; nt < 8; nt++) {
                float p0 = __expf(s[nt][0] - mn0);
                float p1 = __expf(s[nt][1] - mn0);
                float p2 = __expf(s[nt][2] - mn1);
                float p3 = __expf(s[nt][3] - mn1);
                s[nt][0] = p0; s[nt][1] = p1; s[nt][2] = p2; s[nt][3] = p3;
                s0 += p0 + p1; s1 += p2 + p3;
            }
            s0 += __shfl_xor_sync(0xffffffffu, s0, 1);
            s0 += __shfl_xor_sync(0xffffffffu, s0, 2);
            s1 += __shfl_xor_sync(0xffffffffu, s1, 1);
            s1 += __shfl_xor_sync(0xffffffffu, s1, 2);
            lst0 = lst0*a0 + s0;
            lst1 = lst1*a1 + s1;
            #pragma unroll
            for (int nt = 0; nt < 8; nt++) {
                o[nt][0] *= a0; o[nt][1] *= a0;
                o[nt][2] *= a1; o[nt][3] *= a1;
            }

            // ---- O += P @ (Vhi + Vlo), P single fp16 ----
            #pragma unroll
            for (int kk = 0; kk < 4; kk++) {
                uint32_t ph[4];
                ph[0] = pack_h(__float2half_rn(s[2*kk][0]),   __float2half_rn(s[2*kk][1]));
                ph[1] = pack_h(__float2half_rn(s[2*kk][2]),   __float2half_rn(s[2*kk][3]));
                ph[2] = pack_h(__float2half_rn(s[2*kk+1][0]), __float2half_rn(s[2*kk+1][1]));
                ph[3] = pack_h(__float2half_rn(s[2*kk+1][2]), __float2half_rn(s[2*kk+1][3]));
                #pragma unroll
                for (int nv = 0; nv < 4; nv++) {
                    uint32_t off = SWZ((uint32_t)((kk*16 + (lane & 15))*128 + (nv*16 + 8*(lane >> 4))*2));
                    uint32_t rh[4], rl[4];
                    ldsm4t(rh, vhB + off);
                    ldsm4t(rl, vlB + off);
                    uint32_t b0h[2] = { rh[0], rh[1] }, b1h[2] = { rh[2], rh[3] };
                    uint32_t b0l[2] = { rl[0], rl[1] }, b1l[2] = { rl[2], rl[3] };
                    mma_f16(o[2*nv],   ph, b0h);
                    mma_f16(o[2*nv],   ph, b0l);
                    mma_f16(o[2*nv+1], ph, b1h);
                    mma_f16(o[2*nv+1], ph, b1l);
                }
            }
        }
        __syncthreads();
    }

    // ---- epilogue: O/l -> fp16 hi/lo ctx ----
    float li0 = 1.0f / lst0, li1 = 1.0f / lst1;
    int colB = h*64 + ((lane & 3) << 1);
    size_t row0 = rowOff + r0g, row1 = rowOff + r1g;
    #pragma unroll
    for (int nt = 0; nt < 8; nt++) {
        int col = colB + nt*8;
        uint32_t lo0, lo1;
        uint32_t hi0 = cvt2h(o[nt][0]*li0, o[nt][1]*li0, lo0);
        uint32_t hi1 = cvt2h(o[nt][2]*li1, o[nt][3]*li1, lo1);
        *(uint32_t*)(Ch + row0*EMB + col) = hi0;
        *(uint32_t*)(Cl + row0*EMB + col) = lo0;
        *(uint32_t*)(Ch + row1*EMB + col) = hi1;
        *(uint32_t*)(Cl + row1*EMB + col) = lo1;
    }
}

// ---------------- launch ----------------
extern "C" void kernel_launch(void* const* d_in, const int* in_sizes, int n_in,
                              void* d_out, int out_size)
{
    const float* x  = (const float*)d_in[0];
    const float* Wq = (const float*)d_in[1];
    const float* Wk = (const float*)d_in[2];
    const float* Wv = (const float*)d_in[3];
    const float* Wo = (const float*)d_in[4];
    const float* bo = (const float*)d_in[5];
    const float* W1 = (const float*)d_in[6];
    const float* b1 = (const float*)d_in[7];
    const float* W2 = (const float*)d_in[8];
    const float* b2 = (const float*)d_in[9];
    const float* g1 = (const float*)d_in[10];
    const float* s1 = (const float*)d_in[11];
    const float* g2 = (const float*)d_in[12];
    const float* s2 = (const float*)d_in[13];
    float* out = (float*)d_out;

    __half *ln1h, *ln1l, *qkvh, *qkvl, *ctxh, *ctxl, *yh, *yl, *ffh, *ffl;
    __half *wqkvt, *wot, *w1t, *w2t;
    float *h;
    cudaGetSymbolAddress((void**)&ln1h, g_ln1h);
    cudaGetSymbolAddress((void**)&ln1l, g_ln1l);
    cudaGetSymbolAddress((void**)&qkvh, g_qkvh);
    cudaGetSymbolAddress((void**)&qkvl, g_qkvl);
    cudaGetSymbolAddress((void**)&ctxh, g_ctxh);
    cudaGetSymbolAddress((void**)&ctxl, g_ctxl);
    cudaGetSymbolAddress((void**)&h,    g_h);
    cudaGetSymbolAddress((void**)&yh,   g_yh);
    cudaGetSymbolAddress((void**)&yl,   g_yl);
    cudaGetSymbolAddress((void**)&ffh,  g_ffh);
    cudaGetSymbolAddress((void**)&ffl,  g_ffl);
    cudaGetSymbolAddress((void**)&wqkvt, g_wqkvt);
    cudaGetSymbolAddress((void**)&wot,  g_wot);
    cudaGetSymbolAddress((void**)&w1t,  g_w1t);
    cudaGetSymbolAddress((void**)&w2t,  g_w2t);

    cudaFuncSetAttribute(gemm_mma, cudaFuncAttributeMaxDynamicSharedMemorySize, SMEM_GEMM);
    cudaFuncSetAttribute(attn_kernel, cudaFuncAttributeMaxDynamicSharedMemorySize, SMEM_ATTN);

    dim3 blk(256);

    // Launch order chosen so slot 5 (ncu -s 5 -c 1) is gemm_mma(qkv).
    wconv_kernel<<<dim3(EMB/32, EMB/32), blk>>>(Wq, wqkvt,                     EMB, EMB);  // 0
    wconv_kernel<<<dim3(EMB/32, EMB/32), blk>>>(Wk, wqkvt + (size_t)EMB*EMB,   EMB, EMB);  // 1
    wconv_kernel<<<dim3(EMB/32, EMB/32), blk>>>(Wv, wqkvt + (size_t)2*EMB*EMB, EMB, EMB);  // 2
    ln_kernel<<<ROWS, blk>>>(x, g1, s1, ln1h, ln1l);                                       // 3
    wconv_kernel<<<dim3(EMB/32, EMB/32), blk>>>(Wo, wot, EMB, EMB);                        // 4
    // 5: qkv = ln1 @ [Wq|Wk|Wv]  <-- profiled
    gemm_mma<<<dim3(QKV_STR/256, ROWS/128), blk, SMEM_GEMM>>>(
        ln1h, ln1l, wqkvt, nullptr, nullptr, nullptr, qkvh, qkvl, ROWS, QKV_STR, EMB, 0);
    wconv_kernel<<<dim3(DFF/32, EMB/32), blk>>>(W1, w1t, EMB, DFF);                        // 6
    wconv_kernel<<<dim3(EMB/32, DFF/32), blk>>>(W2, w2t, DFF, EMB);                        // 7
    // ctx = causal softmax(qk^T/8) v
    attn_kernel<<<dim3(SEQ/128, BATCH*NHEADS), blk, SMEM_ATTN>>>(qkvh, qkvl, ctxh, ctxl);
    // h = x + ctx @ Wo + bo (fp32)
    gemm_mma<<<dim3(EMB/256, ROWS/128), blk, SMEM_GEMM>>>(
        ctxh, ctxl, wot, bo, x, h, nullptr, nullptr, ROWS, EMB, EMB, 0);
    // y = LN(h) -> fp16 hi/lo
    ln_kernel<<<ROWS, blk>>>(h, g2, s2, yh, yl);
    // ff = gelu(y @ W1 + b1) -> fp16 hi/lo
    gemm_mma<<<dim3(DFF/256, ROWS/128), blk, SMEM_GEMM>>>(
        yh, yl, w1t, b1, nullptr, nullptr, ffh, ffl, ROWS, DFF, EMB, 1);
    // out = h + ff @ W2 + b2 (fp32)
    gemm_mma<<<dim3(EMB/256, ROWS/128), blk, SMEM_GEMM>>>(
        ffh, ffl, w2t, b2, h, out, nullptr, nullptr, ROWS, EMB, DFF, 0);
}

// round 7
// speedup vs baseline: 6.4021x; 1.5564x over previous
#include <cuda_runtime.h>
#include <cuda_fp16.h>
#include <math.h>
#include <stdint.h>

#define EMB 1024
#define SEQ 2048
#define BATCH 2
#define ROWS (BATCH*SEQ)   /* 4096 */
#define DFF (4*EMB)        /* 4096 */
#define NHEADS 16
#define HD 64
#define QKV_STR (3*EMB)    /* 3072 */

// ---------------- scratch (device globals: no allocation allowed) ----------------
__device__ __half g_ln1[ROWS*EMB];
__device__ __half g_qkv[(size_t)ROWS*QKV_STR];
__device__ __half g_ctx[ROWS*EMB];
__device__ float  g_h  [ROWS*EMB];
__device__ __half g_y  [ROWS*EMB];
__device__ __half g_ff [(size_t)ROWS*DFF];
// transposed fp16 weights: Wt[N,K]
__device__ __half g_wqkvt[3*EMB*EMB];
__device__ __half g_wot[EMB*EMB];
__device__ __half g_w1t[EMB*DFF];
__device__ __half g_w2t[DFF*EMB];

// ---------------- helpers ----------------
__device__ __forceinline__ uint32_t smem_to_u32(const void* p) {
    uint32_t a;
    asm("{ .reg .u64 t; cvta.to.shared.u64 t, %1; cvt.u32.u64 %0, t; }" : "=r"(a) : "l"(p));
    return a;
}
#define SWZ(off) ((off) ^ (((off) >> 3) & 0x70))

__device__ __forceinline__ void ldsm4(uint32_t* r, uint32_t addr) {
    asm volatile("ldmatrix.sync.aligned.m8n8.x4.shared.b16 {%0,%1,%2,%3}, [%4];"
        : "=r"(r[0]), "=r"(r[1]), "=r"(r[2]), "=r"(r[3]) : "r"(addr));
}
__device__ __forceinline__ void ldsm4t(uint32_t* r, uint32_t addr) {
    asm volatile("ldmatrix.sync.aligned.m8n8.x4.trans.shared.b16 {%0,%1,%2,%3}, [%4];"
        : "=r"(r[0]), "=r"(r[1]), "=r"(r[2]), "=r"(r[3]) : "r"(addr));
}
__device__ __forceinline__ void mma_f16(float* d, const uint32_t* a, const uint32_t* b) {
    asm volatile("mma.sync.aligned.m16n8k16.row.col.f32.f16.f16.f32 "
        "{%0,%1,%2,%3}, {%4,%5,%6,%7}, {%8,%9}, {%0,%1,%2,%3};"
        : "+f"(d[0]), "+f"(d[1]), "+f"(d[2]), "+f"(d[3])
        : "r"(a[0]), "r"(a[1]), "r"(a[2]), "r"(a[3]), "r"(b[0]), "r"(b[1]));
}
__device__ __forceinline__ void cp16(uint32_t s, const void* g) {
    asm volatile("cp.async.cg.shared.global [%0], [%1], 16;" :: "r"(s), "l"(g));
}
#define CP_COMMIT() asm volatile("cp.async.commit_group;" ::: "memory")
#define CP_WAIT(n)  asm volatile("cp.async.wait_group %0;" :: "n"(n) : "memory")

__device__ __forceinline__ uint32_t pack_h(__half a, __half b) {
    return (uint32_t)__half_as_ushort(a) | ((uint32_t)__half_as_ushort(b) << 16);
}
__device__ __forceinline__ uint32_t cvt2h1(float a, float b) {
    return pack_h(__float2half_rn(a), __float2half_rn(b));
}
__device__ __forceinline__ float gelu_f(float x)
{
    float u = 0.7978845608028654f * (x + 0.044715f * x * x * x);
    return 0.5f * x * (1.0f + tanhf(u));
}

// ---------------- layernorm: fp32 in -> fp16 out ----------------
__global__ __launch_bounds__(256) void ln_kernel(const float* __restrict__ x,
    const float* __restrict__ g, const float* __restrict__ s,
    __half* __restrict__ o)
{
    __shared__ float red[16];
    int row = blockIdx.x;
    int t = threadIdx.x;
    const float4* xr = reinterpret_cast<const float4*>(x + (size_t)row*EMB);
    float4 v = xr[t];
    float sum = v.x+v.y+v.z+v.w;
    float sq  = v.x*v.x+v.y*v.y+v.z*v.z+v.w*v.w;
    #pragma unroll
    for (int off = 16; off > 0; off >>= 1) {
        sum += __shfl_xor_sync(0xffffffffu, sum, off);
        sq  += __shfl_xor_sync(0xffffffffu, sq,  off);
    }
    int warp = t >> 5, lane = t & 31;
    if (lane == 0) { red[warp] = sum; red[warp+8] = sq; }
    __syncthreads();
    if (t < 32) {
        float a  = (lane < 8) ? red[lane]   : 0.0f;
        float b2 = (lane < 8) ? red[lane+8] : 0.0f;
        #pragma unroll
        for (int off = 4; off > 0; off >>= 1) {
            a  += __shfl_xor_sync(0xffffffffu, a,  off);
            b2 += __shfl_xor_sync(0xffffffffu, b2, off);
        }
        if (lane == 0) { red[0] = a; red[1] = b2; }
    }
    __syncthreads();
    float mean = red[0] * (1.0f/EMB);
    float var  = red[1] * (1.0f/EMB) - mean*mean;
    float inv  = rsqrtf(var + 1e-5f);
    float4 gv = reinterpret_cast<const float4*>(g)[t];
    float4 sv = reinterpret_cast<const float4*>(s)[t];
    float o0 = (v.x - mean)*inv*gv.x + sv.x;
    float o1 = (v.y - mean)*inv*gv.y + sv.y;
    float o2 = (v.z - mean)*inv*gv.z + sv.z;
    float o3 = (v.w - mean)*inv*gv.w + sv.w;
    *(uint2*)(o + (size_t)row*EMB + t*4) = make_uint2(cvt2h1(o0, o1), cvt2h1(o2, o3));
}

// ---------------- weight transpose: W[K,N] fp32 -> Wt[N,K] fp16 ----------------
__global__ __launch_bounds__(256) void wconv_kernel(const float* __restrict__ W,
    __half* __restrict__ O, int K, int N)
{
    __shared__ float tile[32][33];
    int n0 = blockIdx.x*32, k0 = blockIdx.y*32;
    int tx = threadIdx.x & 31, ty = threadIdx.x >> 5;   // 32 x 8
    #pragma unroll
    for (int i = 0; i < 4; i++)
        tile[ty + 8*i][tx] = W[(size_t)(k0 + ty + 8*i)*N + n0 + tx];
    __syncthreads();
    #pragma unroll
    for (int i = 0; i < 4; i++) {
        float x = tile[tx][ty + 8*i];
        O[(size_t)(n0 + ty + 8*i)*K + k0 + tx] = __float2half_rn(x);
    }
}

// ---------------- mma.sync fp16 GEMM (single-pass, 3-stage cp.async) ----------------
// Tile 128(M) x 256(N), KC=64. Warp grid 2m x 4n -> 64x64 warp tile.
// C = A[M,K] @ Bt[N,K]^T. outF != null -> fp32 out (+res); else fp16 out.
#define KC 64
#define STAGE 49152
#define SMEM_GEMM (3*STAGE)
__global__ __launch_bounds__(256) void gemm_mma(
    const __half* __restrict__ A, const __half* __restrict__ Bt,
    const float* __restrict__ bias, const float* __restrict__ res,
    float* __restrict__ outF, __half* __restrict__ outH,
    int M, int N, int K, int dogelu)
{
    extern __shared__ char smem[];
    uint32_t sb = smem_to_u32(smem);
    int t = threadIdx.x, w = t >> 5, lane = t & 31;
    int wm = w >> 2, wn = w & 3;               // warp grid 2(m) x 4(n)
    int m0 = blockIdx.y*128, n0 = blockIdx.x*256;

    const __half* srcA = A + (size_t)m0*K;
    const __half* srcB = Bt + (size_t)n0*K;

    float acc[4][8][4];
    #pragma unroll
    for (int mt = 0; mt < 4; mt++)
        #pragma unroll
        for (int nt = 0; nt < 8; nt++)
            #pragma unroll
            for (int e = 0; e < 4; e++) acc[mt][nt][e] = 0.0f;

    int nc = K / KC;

    // stage layout: A @0 (16KB), B @16384 (32KB)
    auto issue = [&](int c, int buf) {
        uint32_t stb = sb + buf*STAGE;
        #pragma unroll
        for (int i = 0; i < 12; i++) {
            int id = t + 256*i;
            if (id < 1024) {           // A: 1024 chunks
                int row = id >> 3, c16 = id & 7;
                const __half* gp = srcA + (size_t)row*K + c*KC + c16*8;
                cp16(stb + SWZ((uint32_t)(row*128 + c16*16)), gp);
            } else {                   // B: 2048 chunks
                int cid = id - 1024;
                int row = cid >> 3, c16 = cid & 7;
                const __half* gp = srcB + (size_t)row*K + c*KC + c16*8;
                cp16(stb + 16384 + SWZ((uint32_t)(row*128 + c16*16)), gp);
            }
        }
    };

    issue(0, 0);
    CP_COMMIT();
    if (nc > 1) { issue(1, 1); CP_COMMIT(); }

    int arow = lane & 15;
    int acol = (lane >> 4) << 4;
    int brow = ((lane >> 4) << 3) + (lane & 7);
    int bcol = ((lane >> 3) & 1) << 4;

    for (int c = 0; c < nc; c++) {
        int buf = c % 3;
        if (c + 2 < nc) { issue(c+2, (c+2) % 3); CP_COMMIT(); CP_WAIT(2); }
        else if (c + 1 < nc) { CP_WAIT(1); }
        else { CP_WAIT(0); }
        __syncthreads();

        {
            uint32_t aB = sb + buf*STAGE;
            uint32_t bB = aB + 16384;
            #pragma unroll
            for (int ks = 0; ks < 4; ks++) {
                int kb = ks * 32;
                uint32_t ah[4][4];
                #pragma unroll
                for (int mt = 0; mt < 4; mt++) {
                    uint32_t off = SWZ((uint32_t)((wm*64 + mt*16 + arow)*128 + kb + acol));
                    ldsm4(ah[mt], aB + off);
                }
                #pragma unroll
                for (int nh = 0; nh < 4; nh++) {
                    uint32_t off = SWZ((uint32_t)((wn*64 + nh*16 + brow)*128 + kb + bcol));
                    uint32_t rb[4];
                    ldsm4(rb, bB + off);
                    uint32_t b0[2] = { rb[0], rb[1] }, b1[2] = { rb[2], rb[3] };
                    #pragma unroll
                    for (int mt = 0; mt < 4; mt++) {
                        mma_f16(acc[mt][2*nh],   ah[mt], b0);
                        mma_f16(acc[mt][2*nh+1], ah[mt], b1);
                    }
                }
            }
        }
        __syncthreads();
    }

    // ---- epilogue ----
    int mBase = m0 + wm*64;
    int nBase = n0 + wn*64;
    #pragma unroll
    for (int mt = 0; mt < 4; mt++) {
        #pragma unroll
        for (int nt = 0; nt < 8; nt++) {
            int row = mBase + mt*16 + (lane >> 2);
            int col = nBase + nt*8 + ((lane & 3) << 1);
            float v0 = acc[mt][nt][0], v1 = acc[mt][nt][1];
            float v2 = acc[mt][nt][2], v3 = acc[mt][nt][3];
            if (bias) {
                float2 bb = *(const float2*)(bias + col);
                v0 += bb.x; v1 += bb.y; v2 += bb.x; v3 += bb.y;
            }
            if (dogelu) {
                v0 = gelu_f(v0); v1 = gelu_f(v1);
                v2 = gelu_f(v2); v3 = gelu_f(v3);
            }
            if (outF) {
                if (res) {
                    float2 r0 = *(const float2*)(res + (size_t)row*N + col);
                    float2 r1 = *(const float2*)(res + (size_t)(row+8)*N + col);
                    v0 += r0.x; v1 += r0.y; v2 += r1.x; v3 += r1.y;
                }
                *(float2*)(outF + (size_t)row*N + col) = make_float2(v0, v1);
                *(float2*)(outF + (size_t)(row+8)*N + col) = make_float2(v2, v3);
            } else {
                *(uint32_t*)(outH + (size_t)row*N + col) = cvt2h1(v0, v1);
                *(uint32_t*)(outH + (size_t)(row+8)*N + col) = cvt2h1(v2, v3);
            }
        }
    }
}

// ---------------- causal flash attention, fp16 mma single-pass ----------------
// QKV packed fp16 [ROWS, 3072]; out ctx fp16 [ROWS, 1024].
// Block: 256 thr (8 warps), q-tile 128 (warp w owns rows w*16..+15), kv-tile 64.
#define STAGE_ATT 16384
#define SMEM_ATTN (16384 + 2*STAGE_ATT)
__global__ __launch_bounds__(256) void attn_kernel(
    const __half* __restrict__ Q, __half* __restrict__ C)
{
    extern __shared__ char smem[];
    uint32_t sb = smem_to_u32(smem);
    int t = threadIdx.x, w = t >> 5, lane = t & 31;
    int qt = gridDim.x - 1 - blockIdx.x;
    int bh_ = blockIdx.y;
    int h = bh_ & 15;
    size_t rowOff = (size_t)(bh_ >> 4) * SEQ;      // batch row offset
    int q0 = qt * 128;
    int colQ = h*64, colK = 1024 + h*64, colV = 2048 + h*64;

    // ---- async load Q ----
    #pragma unroll
    for (int i = 0; i < 4; i++) {
        int id = t + 256*i;
        int row = id >> 3, c16 = id & 7;
        const __half* gp = Q + (rowOff + q0 + row)*QKV_STR + colQ + c16*8;
        cp16(sb + SWZ((uint32_t)(row*128 + c16*16)), gp);
    }
    CP_COMMIT();

    int nkt = 2*qt + 2;

    // issue K/V stage: K @0, V @8192
    auto issue = [&](int kt, int buf) {
        uint32_t stb = sb + 16384 + buf*STAGE_ATT;
        int k0 = kt*64;
        #pragma unroll
        for (int i = 0; i < 4; i++) {
            int id = t + 256*i;
            int arr = id >> 9;           // 0 K, 1 V
            int cid = id & 511;
            int row = cid >> 3, c16 = cid & 7;
            int col = (arr == 0) ? colK : colV;
            const __half* gp = Q + (rowOff + k0 + row)*QKV_STR + col + c16*8;
            cp16(stb + arr*8192 + SWZ((uint32_t)(row*128 + c16*16)), gp);
        }
    };
    issue(0, 0);
    CP_COMMIT();
    CP_WAIT(1);          // Q ready
    __syncthreads();

    // ---- Q fragments to registers ----
    uint32_t qh[4][4];
    {
        int arow = lane & 15;
        int acol = (lane >> 4) << 4;
        #pragma unroll
        for (int kf = 0; kf < 4; kf++) {
            uint32_t off = SWZ((uint32_t)((w*16 + arow)*128 + kf*32 + acol));
            ldsm4(qh[kf], sb + off);
        }
    }

    float o[8][4];
    #pragma unroll
    for (int nt = 0; nt < 8; nt++)
        #pragma unroll
        for (int e = 0; e < 4; e++) o[nt][e] = 0.0f;
    float mst0 = -1e30f, mst1 = -1e30f, lst0 = 0.0f, lst1 = 0.0f;

    int r0g = q0 + w*16 + (lane >> 2);
    int r1g = r0g + 8;

    for (int kt = 0; kt < nkt; kt++) {
        int buf = kt & 1;
        if (kt + 1 < nkt) issue(kt+1, buf^1);
        CP_COMMIT();
        if (kt + 1 < nkt) { CP_WAIT(1); } else { CP_WAIT(0); }
        __syncthreads();

        int k0 = kt*64;
        if (k0 <= q0 + w*16 + 15) {     // at least one unmasked element for this warp
            uint32_t stb = sb + 16384 + buf*STAGE_ATT;
            uint32_t kB = stb, vB = stb + 8192;

            // ---- S = Q @ K^T ----
            float s[8][4];
            #pragma unroll
            for (int nt = 0; nt < 8; nt++)
                #pragma unroll
                for (int e = 0; e < 4; e++) s[nt][e] = 0.0f;
            {
                int brow = ((lane >> 4) << 3) + (lane & 7);
                int bcol = ((lane >> 3) & 1) << 4;
                #pragma unroll
                for (int ks = 0; ks < 4; ks++) {
                    int kb = ks*32;
                    #pragma unroll
                    for (int nh = 0; nh < 4; nh++) {
                        uint32_t off = SWZ((uint32_t)((nh*16 + brow)*128 + kb + bcol));
                        uint32_t rb[4];
                        ldsm4(rb, kB + off);
                        uint32_t b0[2] = { rb[0], rb[1] }, b1[2] = { rb[2], rb[3] };
                        mma_f16(s[2*nh],   qh[ks], b0);
                        mma_f16(s[2*nh+1], qh[ks], b1);
                    }
                }
            }

            // ---- scale + causal mask + online softmax ----
            float mx0 = -1e30f, mx1 = -1e30f;
            #pragma unroll
            for (int nt = 0; nt < 8; nt++) {
                int kgBase = k0 + nt*8 + ((lane & 3) << 1);
                #pragma unroll
                for (int e = 0; e < 4; e++) {
                    float v = s[nt][e] * 0.125f;
                    int kg = kgBase + (e & 1);
                    int qg = (e < 2) ? r0g : r1g;
                    v = (kg <= qg) ? v : -1e30f;
                    s[nt][e] = v;
                    if (e < 2) mx0 = fmaxf(mx0, v); else mx1 = fmaxf(mx1, v);
                }
            }
            mx0 = fmaxf(mx0, __shfl_xor_sync(0xffffffffu, mx0, 1));
            mx0 = fmaxf(mx0, __shfl_xor_sync(0xffffffffu, mx0, 2));
            mx1 = fmaxf(mx1, __shfl_xor_sync(0xffffffffu, mx1, 1));
            mx1 = fmaxf(mx1, __shfl_xor_sync(0xffffffffu, mx1, 2));
            float mn0 = fmaxf(mst0, mx0), mn1 = fmaxf(mst1, mx1);
            float a0 = __expf(mst0 - mn0), a1 = __expf(mst1 - mn1);
            mst0 = mn0; mst1 = mn1;
            float s0 = 0.0f, s1 = 0.0f;
            #pragma unroll
            for (int nt = 0; nt < 8; nt++) {
                float p0 = __expf(s[nt][0] - mn0);
                float p1 = __expf(s[nt][1] - mn0);
                float p2 = __expf(s[nt][2] - mn1);
                float p3 = __expf(s[nt][3] - mn1);
                s[nt][0] = p0; s[nt][1] = p1; s[nt][2] = p2; s[nt][3] = p3;
                s0 += p0 + p1; s1 += p2 + p3;
            }
            s0 += __shfl_xor_sync(0xffffffffu, s0, 1);
            s0 += __shfl_xor_sync(0xffffffffu, s0, 2);
            s1 += __shfl_xor_sync(0xffffffffu, s1, 1);
            s1 += __shfl_xor_sync(0xffffffffu, s1, 2);
            lst0 = lst0*a0 + s0;
            lst1 = lst1*a1 + s1;
            #pragma unroll
            for (int nt = 0; nt < 8; nt++) {
                o[nt][0] *= a0; o[nt][1] *= a0;
                o[nt][2] *= a1; o[nt][3] *= a1;
            }

            // ---- O += P @ V, P single fp16 ----
            #pragma unroll
            for (int kk = 0; kk < 4; kk++) {
                uint32_t ph[4];
                ph[0] = cvt2h1(s[2*kk][0],   s[2*kk][1]);
                ph[1] = cvt2h1(s[2*kk][2],   s[2*kk][3]);
                ph[2] = cvt2h1(s[2*kk+1][0], s[2*kk+1][1]);
                ph[3] = cvt2h1(s[2*kk+1][2], s[2*kk+1][3]);
                #pragma unroll
                for (int nv = 0; nv < 4; nv++) {
                    uint32_t off = SWZ((uint32_t)((kk*16 + (lane & 15))*128 + (nv*16 + 8*(lane >> 4))*2));
                    uint32_t rh[4];
                    ldsm4t(rh, vB + off);
                    uint32_t b0[2] = { rh[0], rh[1] }, b1[2] = { rh[2], rh[3] };
                    mma_f16(o[2*nv],   ph, b0);
                    mma_f16(o[2*nv+1], ph, b1);
                }
            }
        }
        __syncthreads();
    }

    // ---- epilogue: O/l -> fp16 ctx ----
    float li0 = 1.0f / lst0, li1 = 1.0f / lst1;
    int colB = h*64 + ((lane & 3) << 1);
    size_t row0 = rowOff + r0g, row1 = rowOff + r1g;
    #pragma unroll
    for (int nt = 0; nt < 8; nt++) {
        int col = colB + nt*8;
        *(uint32_t*)(C + row0*EMB + col) = cvt2h1(o[nt][0]*li0, o[nt][1]*li0);
        *(uint32_t*)(C + row1*EMB + col) = cvt2h1(o[nt][2]*li1, o[nt][3]*li1);
    }
}

// ---------------- launch ----------------
extern "C" void kernel_launch(void* const* d_in, const int* in_sizes, int n_in,
                              void* d_out, int out_size)
{
    const float* x  = (const float*)d_in[0];
    const float* Wq = (const float*)d_in[1];
    const float* Wk = (const float*)d_in[2];
    const float* Wv = (const float*)d_in[3];
    const float* Wo = (const float*)d_in[4];
    const float* bo = (const float*)d_in[5];
    const float* W1 = (const float*)d_in[6];
    const float* b1 = (const float*)d_in[7];
    const float* W2 = (const float*)d_in[8];
    const float* b2 = (const float*)d_in[9];
    const float* g1 = (const float*)d_in[10];
    const float* s1 = (const float*)d_in[11];
    const float* g2 = (const float*)d_in[12];
    const float* s2 = (const float*)d_in[13];
    float* out = (float*)d_out;

    __half *ln1, *qkv, *ctx, *y, *ff;
    __half *wqkvt, *wot, *w1t, *w2t;
    float *h;
    cudaGetSymbolAddress((void**)&ln1,  g_ln1);
    cudaGetSymbolAddress((void**)&qkv,  g_qkv);
    cudaGetSymbolAddress((void**)&ctx,  g_ctx);
    cudaGetSymbolAddress((void**)&h,    g_h);
    cudaGetSymbolAddress((void**)&y,    g_y);
    cudaGetSymbolAddress((void**)&ff,   g_ff);
    cudaGetSymbolAddress((void**)&wqkvt, g_wqkvt);
    cudaGetSymbolAddress((void**)&wot,  g_wot);
    cudaGetSymbolAddress((void**)&w1t,  g_w1t);
    cudaGetSymbolAddress((void**)&w2t,  g_w2t);

    cudaFuncSetAttribute(gemm_mma, cudaFuncAttributeMaxDynamicSharedMemorySize, SMEM_GEMM);
    cudaFuncSetAttribute(attn_kernel, cudaFuncAttributeMaxDynamicSharedMemorySize, SMEM_ATTN);

    dim3 blk(256);

    wconv_kernel<<<dim3(EMB/32, EMB/32), blk>>>(Wq, wqkvt,                     EMB, EMB);
    wconv_kernel<<<dim3(EMB/32, EMB/32), blk>>>(Wk, wqkvt + (size_t)EMB*EMB,   EMB, EMB);
    wconv_kernel<<<dim3(EMB/32, EMB/32), blk>>>(Wv, wqkvt + (size_t)2*EMB*EMB, EMB, EMB);
    ln_kernel<<<ROWS, blk>>>(x, g1, s1, ln1);
    wconv_kernel<<<dim3(EMB/32, EMB/32), blk>>>(Wo, wot, EMB, EMB);
    // qkv = ln1 @ [Wq|Wk|Wv]
    gemm_mma<<<dim3(QKV_STR/256, ROWS/128), blk, SMEM_GEMM>>>(
        ln1, wqkvt, nullptr, nullptr, nullptr, qkv, ROWS, QKV_STR, EMB, 0);
    wconv_kernel<<<dim3(DFF/32, EMB/32), blk>>>(W1, w1t, EMB, DFF);
    wconv_kernel<<<dim3(EMB/32, DFF/32), blk>>>(W2, w2t, DFF, EMB);
    // ctx = causal softmax(qk^T/8) v
    attn_kernel<<<dim3(SEQ/128, BATCH*NHEADS), blk, SMEM_ATTN>>>(qkv, ctx);
    // h = x + ctx @ Wo + bo (fp32)
    gemm_mma<<<dim3(EMB/256, ROWS/128), blk, SMEM_GEMM>>>(
        ctx, wot, bo, x, h, nullptr, ROWS, EMB, EMB, 0);
    // y = LN(h) -> fp16
    ln_kernel<<<ROWS, blk>>>(h, g2, s2, y);
    // ff = gelu(y @ W1 + b1) -> fp16
    gemm_mma<<<dim3(DFF/256, ROWS/128), blk, SMEM_GEMM>>>(
        y, w1t, b1, nullptr, nullptr, ff, ROWS, DFF, EMB, 1);
    // out = h + ff @ W2 + b2 (fp32)
    gemm_mma<<<dim3(EMB/256, ROWS/128), blk, SMEM_GEMM>>>(
        ff, w2t, b2, h, out, nullptr, ROWS, EMB, DFF, 0);
}

// round 8
// speedup vs baseline: 6.9650x; 1.0879x over previous
#include <cuda_runtime.h>
#include <cuda_fp16.h>
#include <math.h>
#include <stdint.h>

#define EMB 1024
#define SEQ 2048
#define BATCH 2
#define ROWS (BATCH*SEQ)   /* 4096 */
#define DFF (4*EMB)        /* 4096 */
#define NHEADS 16
#define HD 64
#define QKV_STR (3*EMB)    /* 3072 */

// ---------------- scratch (device globals: no allocation allowed) ----------------
__device__ __half g_ln1[ROWS*EMB];
__device__ __half g_qkv[(size_t)ROWS*QKV_STR];
__device__ __half g_ctx[ROWS*EMB];
__device__ float  g_h  [ROWS*EMB];
__device__ __half g_y  [ROWS*EMB];
__device__ __half g_ff [(size_t)ROWS*DFF];
// transposed fp16 weights: Wt[N,K]
__device__ __half g_wqkvt[3*EMB*EMB];
__device__ __half g_wot[EMB*EMB];
__device__ __half g_w1t[EMB*DFF];
__device__ __half g_w2t[DFF*EMB];

// ---------------- helpers ----------------
__device__ __forceinline__ uint32_t smem_to_u32(const void* p) {
    uint32_t a;
    asm("{ .reg .u64 t; cvta.to.shared.u64 t, %1; cvt.u32.u64 %0, t; }" : "=r"(a) : "l"(p));
    return a;
}
#define SWZ(off) ((off) ^ (((off) >> 3) & 0x70))

__device__ __forceinline__ void ldsm4(uint32_t* r, uint32_t addr) {
    asm volatile("ldmatrix.sync.aligned.m8n8.x4.shared.b16 {%0,%1,%2,%3}, [%4];"
        : "=r"(r[0]), "=r"(r[1]), "=r"(r[2]), "=r"(r[3]) : "r"(addr));
}
__device__ __forceinline__ void ldsm4t(uint32_t* r, uint32_t addr) {
    asm volatile("ldmatrix.sync.aligned.m8n8.x4.trans.shared.b16 {%0,%1,%2,%3}, [%4];"
        : "=r"(r[0]), "=r"(r[1]), "=r"(r[2]), "=r"(r[3]) : "r"(addr));
}
__device__ __forceinline__ void mma_f16(float* d, const uint32_t* a, const uint32_t* b) {
    asm volatile("mma.sync.aligned.m16n8k16.row.col.f32.f16.f16.f32 "
        "{%0,%1,%2,%3}, {%4,%5,%6,%7}, {%8,%9}, {%0,%1,%2,%3};"
        : "+f"(d[0]), "+f"(d[1]), "+f"(d[2]), "+f"(d[3])
        : "r"(a[0]), "r"(a[1]), "r"(a[2]), "r"(a[3]), "r"(b[0]), "r"(b[1]));
}
__device__ __forceinline__ void cp16(uint32_t s, const void* g) {
    asm volatile("cp.async.cg.shared.global [%0], [%1], 16;" :: "r"(s), "l"(g));
}
#define CP_COMMIT() asm volatile("cp.async.commit_group;" ::: "memory")
#define CP_WAIT(n)  asm volatile("cp.async.wait_group %0;" :: "n"(n) : "memory")

__device__ __forceinline__ uint32_t pack_h(__half a, __half b) {
    return (uint32_t)__half_as_ushort(a) | ((uint32_t)__half_as_ushort(b) << 16);
}
__device__ __forceinline__ uint32_t cvt2h1(float a, float b) {
    return pack_h(__float2half_rn(a), __float2half_rn(b));
}
__device__ __forceinline__ float gelu_f(float x)
{
    float u = 0.7978845608028654f * (x + 0.044715f * x * x * x);
    return 0.5f * x * (1.0f + tanhf(u));
}

// ---------------- layernorm: fp32 in -> fp16 out ----------------
__global__ __launch_bounds__(256) void ln_kernel(const float* __restrict__ x,
    const float* __restrict__ g, const float* __restrict__ s,
    __half* __restrict__ o)
{
    __shared__ float red[16];
    int row = blockIdx.x;
    int t = threadIdx.x;
    const float4* xr = reinterpret_cast<const float4*>(x + (size_t)row*EMB);
    float4 v = xr[t];
    float sum = v.x+v.y+v.z+v.w;
    float sq  = v.x*v.x+v.y*v.y+v.z*v.z+v.w*v.w;
    #pragma unroll
    for (int off = 16; off > 0; off >>= 1) {
        sum += __shfl_xor_sync(0xffffffffu, sum, off);
        sq  += __shfl_xor_sync(0xffffffffu, sq,  off);
    }
    int warp = t >> 5, lane = t & 31;
    if (lane == 0) { red[warp] = sum; red[warp+8] = sq; }
    __syncthreads();
    if (t < 32) {
        float a  = (lane < 8) ? red[lane]   : 0.0f;
        float b2 = (lane < 8) ? red[lane+8] : 0.0f;
        #pragma unroll
        for (int off = 4; off > 0; off >>= 1) {
            a  += __shfl_xor_sync(0xffffffffu, a,  off);
            b2 += __shfl_xor_sync(0xffffffffu, b2, off);
        }
        if (lane == 0) { red[0] = a; red[1] = b2; }
    }
    __syncthreads();
    float mean = red[0] * (1.0f/EMB);
    float var  = red[1] * (1.0f/EMB) - mean*mean;
    float inv  = rsqrtf(var + 1e-5f);
    float4 gv = reinterpret_cast<const float4*>(g)[t];
    float4 sv = reinterpret_cast<const float4*>(s)[t];
    float o0 = (v.x - mean)*inv*gv.x + sv.x;
    float o1 = (v.y - mean)*inv*gv.y + sv.y;
    float o2 = (v.z - mean)*inv*gv.z + sv.z;
    float o3 = (v.w - mean)*inv*gv.w + sv.w;
    *(uint2*)(o + (size_t)row*EMB + t*4) = make_uint2(cvt2h1(o0, o1), cvt2h1(o2, o3));
}

// ---------------- fused weight transposes: W[K,N] fp32 -> Wt[N,K] fp16 ----------------
__device__ __forceinline__ void wtile(const float* __restrict__ W, __half* __restrict__ O,
                                      int K, int N, int n0, int k0)
{
    __shared__ float tile[32][33];
    int tx = threadIdx.x & 31, ty = threadIdx.x >> 5;   // 32 x 8
    #pragma unroll
    for (int i = 0; i < 4; i++)
        tile[ty + 8*i][tx] = W[(size_t)(k0 + ty + 8*i)*N + n0 + tx];
    __syncthreads();
    #pragma unroll
    for (int i = 0; i < 4; i++) {
        float x = tile[tx][ty + 8*i];
        O[(size_t)(n0 + ty + 8*i)*K + k0 + tx] = __float2half_rn(x);
    }
}

__global__ __launch_bounds__(256) void wconv_qkv_kernel(
    const float* __restrict__ Wq, const float* __restrict__ Wk, const float* __restrict__ Wv,
    __half* __restrict__ O)
{
    int z = blockIdx.z;
    const float* W = (z == 0) ? Wq : (z == 1) ? Wk : Wv;
    wtile(W, O + (size_t)z*EMB*EMB, EMB, EMB, blockIdx.x*32, blockIdx.y*32);
}

__global__ __launch_bounds__(256) void wconv_rest_kernel(
    const float* __restrict__ Wo, const float* __restrict__ W1, const float* __restrict__ W2,
    __half* __restrict__ wot, __half* __restrict__ w1t, __half* __restrict__ w2t)
{
    int z = blockIdx.z;
    if (z == 0) {
        wtile(Wo, wot, EMB, EMB, blockIdx.x*32, blockIdx.y*32);
    } else if (z < 5) {
        wtile(W1, w1t, EMB, DFF, (z-1)*1024 + blockIdx.x*32, blockIdx.y*32);
    } else {
        wtile(W2, w2t, DFF, EMB, blockIdx.x*32, (z-5)*1024 + blockIdx.y*32);
    }
}

// ---------------- mma.sync fp16 GEMM (single-pass, KC=128, double-buffered) ----------------
// Tile 128(M) x 256(N). Warp grid 2m x 4n -> 64x64 warp tile.
// Stage = 2 sub-chunks of KC=64 layout (A 16KB + B 32KB each) = 96KB; 2 stages = 192KB.
#define SUBCH 49152
#define STAGE (2*SUBCH)
#define SMEM_GEMM (2*STAGE)
__global__ __launch_bounds__(256) void gemm_mma(
    const __half* __restrict__ A, const __half* __restrict__ Bt,
    const float* __restrict__ bias, const float* __restrict__ res,
    float* __restrict__ outF, __half* __restrict__ outH,
    int M, int N, int K, int dogelu)
{
    extern __shared__ char smem[];
    uint32_t sb = smem_to_u32(smem);
    int t = threadIdx.x, w = t >> 5, lane = t & 31;
    int wm = w >> 2, wn = w & 3;               // warp grid 2(m) x 4(n)
    int m0 = blockIdx.y*128, n0 = blockIdx.x*256;

    const __half* srcA = A + (size_t)m0*K;
    const __half* srcB = Bt + (size_t)n0*K;

    float acc[4][8][4];
    #pragma unroll
    for (int mt = 0; mt < 4; mt++)
        #pragma unroll
        for (int nt = 0; nt < 8; nt++)
            #pragma unroll
            for (int e = 0; e < 4; e++) acc[mt][nt][e] = 0.0f;

    int nc2 = K / 128;

    // sub-chunk layout: A @0 (16KB, 128 rows x 64 cols), B @16384 (32KB, 256 rows x 64 cols)
    auto issue = [&](int c2, int buf) {
        uint32_t stb = sb + buf*STAGE;
        #pragma unroll
        for (int i = 0; i < 24; i++) {
            int id  = t + 256*i;
            int sub = (i < 12) ? 0 : 1;          // id<3072 exactly when i<12
            int id2 = id - sub*3072;
            int kc  = (2*c2 + sub)*64;
            uint32_t base = stb + sub*SUBCH;
            if (id2 < 1024) {           // A: 1024 chunks
                int row = id2 >> 3, c16 = id2 & 7;
                cp16(base + SWZ((uint32_t)(row*128 + c16*16)),
                     srcA + (size_t)row*K + kc + c16*8);
            } else {                    // B: 2048 chunks
                int cid = id2 - 1024;
                int row = cid >> 3, c16 = cid & 7;
                cp16(base + 16384 + SWZ((uint32_t)(row*128 + c16*16)),
                     srcB + (size_t)row*K + kc + c16*8);
            }
        }
    };

    issue(0, 0);
    CP_COMMIT();

    int arow = lane & 15;
    int acol = (lane >> 4) << 4;
    int brow = ((lane >> 4) << 3) + (lane & 7);
    int bcol = ((lane >> 3) & 1) << 4;

    for (int c2 = 0; c2 < nc2; c2++) {
        int buf = c2 & 1;
        if (c2 + 1 < nc2) { issue(c2+1, buf^1); CP_COMMIT(); CP_WAIT(1); }
        else { CP_WAIT(0); }
        __syncthreads();

        #pragma unroll
        for (int sub = 0; sub < 2; sub++) {
            uint32_t aB = sb + buf*STAGE + sub*SUBCH;
            uint32_t bB = aB + 16384;
            #pragma unroll
            for (int ks = 0; ks < 4; ks++) {
                int kb = ks * 32;
                uint32_t ah[4][4];
                #pragma unroll
                for (int mt = 0; mt < 4; mt++) {
                    uint32_t off = SWZ((uint32_t)((wm*64 + mt*16 + arow)*128 + kb + acol));
                    ldsm4(ah[mt], aB + off);
                }
                #pragma unroll
                for (int nh = 0; nh < 4; nh++) {
                    uint32_t off = SWZ((uint32_t)((wn*64 + nh*16 + brow)*128 + kb + bcol));
                    uint32_t rb[4];
                    ldsm4(rb, bB + off);
                    uint32_t b0[2] = { rb[0], rb[1] }, b1[2] = { rb[2], rb[3] };
                    #pragma unroll
                    for (int mt = 0; mt < 4; mt++) {
                        mma_f16(acc[mt][2*nh],   ah[mt], b0);
                        mma_f16(acc[mt][2*nh+1], ah[mt], b1);
                    }
                }
            }
        }
        __syncthreads();
    }

    // ---- epilogue ----
    int mBase = m0 + wm*64;
    int nBase = n0 + wn*64;
    #pragma unroll
    for (int mt = 0; mt < 4; mt++) {
        #pragma unroll
        for (int nt = 0; nt < 8; nt++) {
            int row = mBase + mt*16 + (lane >> 2);
            int col = nBase + nt*8 + ((lane & 3) << 1);
            float v0 = acc[mt][nt][0], v1 = acc[mt][nt][1];
            float v2 = acc[mt][nt][2], v3 = acc[mt][nt][3];
            if (bias) {
                float2 bb = *(const float2*)(bias + col);
                v0 += bb.x; v1 += bb.y; v2 += bb.x; v3 += bb.y;
            }
            if (dogelu) {
                v0 = gelu_f(v0); v1 = gelu_f(v1);
                v2 = gelu_f(v2); v3 = gelu_f(v3);
            }
            if (outF) {
                if (res) {
                    float2 r0 = *(const float2*)(res + (size_t)row*N + col);
                    float2 r1 = *(const float2*)(res + (size_t)(row+8)*N + col);
                    v0 += r0.x; v1 += r0.y; v2 += r1.x; v3 += r1.y;
                }
                *(float2*)(outF + (size_t)row*N + col) = make_float2(v0, v1);
                *(float2*)(outF + (size_t)(row+8)*N + col) = make_float2(v2, v3);
            } else {
                *(uint32_t*)(outH + (size_t)row*N + col) = cvt2h1(v0, v1);
                *(uint32_t*)(outH + (size_t)(row+8)*N + col) = cvt2h1(v2, v3);
            }
        }
    }
}

// ---------------- causal flash attention, fp16 mma single-pass ----------------
// QKV packed fp16 [ROWS, 3072]; out ctx fp16 [ROWS, 1024].
// Block: 256 thr (8 warps), q-tile 128 (warp w owns rows w*16..+15), kv-tile 64.
#define STAGE_ATT 16384
#define SMEM_ATTN (16384 + 2*STAGE_ATT)
__global__ __launch_bounds__(256) void attn_kernel(
    const __half* __restrict__ Q, __half* __restrict__ C)
{
    extern __shared__ char smem[];
    uint32_t sb = smem_to_u32(smem);
    int t = threadIdx.x, w = t >> 5, lane = t & 31;
    int qt = gridDim.x - 1 - blockIdx.x;
    int bh_ = blockIdx.y;
    int h = bh_ & 15;
    size_t rowOff = (size_t)(bh_ >> 4) * SEQ;      // batch row offset
    int q0 = qt * 128;
    int colQ = h*64, colK = 1024 + h*64, colV = 2048 + h*64;

    // ---- async load Q ----
    #pragma unroll
    for (int i = 0; i < 4; i++) {
        int id = t + 256*i;
        int row = id >> 3, c16 = id & 7;
        const __half* gp = Q + (rowOff + q0 + row)*QKV_STR + colQ + c16*8;
        cp16(sb + SWZ((uint32_t)(row*128 + c16*16)), gp);
    }
    CP_COMMIT();

    int nkt = 2*qt + 2;

    // issue K/V stage: K @0, V @8192
    auto issue = [&](int kt, int buf) {
        uint32_t stb = sb + 16384 + buf*STAGE_ATT;
        int k0 = kt*64;
        #pragma unroll
        for (int i = 0; i < 4; i++) {
            int id = t + 256*i;
            int arr = id >> 9;           // 0 K, 1 V
            int cid = id & 511;
            int row = cid >> 3, c16 = cid & 7;
            int col = (arr == 0) ? colK : colV;
            const __half* gp = Q + (rowOff + k0 + row)*QKV_STR + col + c16*8;
            cp16(stb + arr*8192 + SWZ((uint32_t)(row*128 + c16*16)), gp);
        }
    };
    issue(0, 0);
    CP_COMMIT();
    CP_WAIT(1);          // Q ready
    __syncthreads();

    // ---- Q fragments to registers ----
    uint32_t qh[4][4];
    {
        int arow = lane & 15;
        int acol = (lane >> 4) << 4;
        #pragma unroll
        for (int kf = 0; kf < 4; kf++) {
            uint32_t off = SWZ((uint32_t)((w*16 + arow)*128 + kf*32 + acol));
            ldsm4(qh[kf], sb + off);
        }
    }

    float o[8][4];
    #pragma unroll
    for (int nt = 0; nt < 8; nt++)
        #pragma unroll
        for (int e = 0; e < 4; e++) o[nt][e] = 0.0f;
    float mst0 = -1e30f, mst1 = -1e30f, lst0 = 0.0f, lst1 = 0.0f;

    int r0g = q0 + w*16 + (lane >> 2);
    int r1g = r0g + 8;

    for (int kt = 0; kt < nkt; kt++) {
        int buf = kt & 1;
        if (kt + 1 < nkt) issue(kt+1, buf^1);
        CP_COMMIT();
        if (kt + 1 < nkt) { CP_WAIT(1); } else { CP_WAIT(0); }
        __syncthreads();

        int k0 = kt*64;
        if (k0 <= q0 + w*16 + 15) {     // at least one unmasked element for this warp
            uint32_t stb = sb + 16384 + buf*STAGE_ATT;
            uint32_t kB = stb, vB = stb + 8192;

            // ---- S = Q @ K^T ----
            float s[8][4];
            #pragma unroll
            for (int nt = 0; nt < 8; nt++)
                #pragma unroll
                for (int e = 0; e < 4; e++) s[nt][e] = 0.0f;
            {
                int brow = ((lane >> 4) << 3) + (lane & 7);
                int bcol = ((lane >> 3) & 1) << 4;
                #pragma unroll
                for (int ks = 0; ks < 4; ks++) {
                    int kb = ks*32;
                    #pragma unroll
                    for (int nh = 0; nh < 4; nh++) {
                        uint32_t off = SWZ((uint32_t)((nh*16 + brow)*128 + kb + bcol));
                        uint32_t rb[4];
                        ldsm4(rb, kB + off);
                        uint32_t b0[2] = { rb[0], rb[1] }, b1[2] = { rb[2], rb[3] };
                        mma_f16(s[2*nh],   qh[ks], b0);
                        mma_f16(s[2*nh+1], qh[ks], b1);
                    }
                }
            }

            // ---- scale + causal mask + online softmax ----
            float mx0 = -1e30f, mx1 = -1e30f;
            #pragma unroll
            for (int nt = 0; nt < 8; nt++) {
                int kgBase = k0 + nt*8 + ((lane & 3) << 1);
                #pragma unroll
                for (int e = 0; e < 4; e++) {
                    float v = s[nt][e] * 0.125f;
                    int kg = kgBase + (e & 1);
                    int qg = (e < 2) ? r0g : r1g;
                    v = (kg <= qg) ? v : -1e30f;
                    s[nt][e] = v;
                    if (e < 2) mx0 = fmaxf(mx0, v); else mx1 = fmaxf(mx1, v);
                }
            }
            mx0 = fmaxf(mx0, __shfl_xor_sync(0xffffffffu, mx0, 1));
            mx0 = fmaxf(mx0, __shfl_xor_sync(0xffffffffu, mx0, 2));
            mx1 = fmaxf(mx1, __shfl_xor_sync(0xffffffffu, mx1, 1));
            mx1 = fmaxf(mx1, __shfl_xor_sync(0xffffffffu, mx1, 2));
            float mn0 = fmaxf(mst0, mx0), mn1 = fmaxf(mst1, mx1);
            float a0 = __expf(mst0 - mn0), a1 = __expf(mst1 - mn1);
            mst0 = mn0; mst1 = mn1;
            float s0 = 0.0f, s1 = 0.0f;
            #pragma unroll
            for (int nt = 0; nt < 8; nt++) {
                float p0 = __expf(s[nt][0] - mn0);
                float p1 = __expf(s[nt][1] - mn0);
                float p2 = __expf(s[nt][2] - mn1);
                float p3 = __expf(s[nt][3] - mn1);
                s[nt][0] = p0; s[nt][1] = p1; s[nt][2] = p2; s[nt][3] = p3;
                s0 += p0 + p1; s1 += p2 + p3;
            }
            s0 += __shfl_xor_sync(0xffffffffu, s0, 1);
            s0 += __shfl_xor_sync(0xffffffffu, s0, 2);
            s1 += __shfl_xor_sync(0xffffffffu, s1, 1);
            s1 += __shfl_xor_sync(0xffffffffu, s1, 2);
            lst0 = lst0*a0 + s0;
            lst1 = lst1*a1 + s1;
            #pragma unroll
            for (int nt = 0; nt < 8; nt++) {
                o[nt][0] *= a0; o[nt][1] *= a0;
                o[nt][2] *= a1; o[nt][3] *= a1;
            }

            // ---- O += P @ V, P single fp16 ----
            #pragma unroll
            for (int kk = 0; kk < 4; kk++) {
                uint32_t ph[4];
                ph[0] = cvt2h1(s[2*kk][0],   s[2*kk][1]);
                ph[1] = cvt2h1(s[2*kk][2],   s[2*kk][3]);
                ph[2] = cvt2h1(s[2*kk+1][0], s[2*kk+1][1]);
                ph[3] = cvt2h1(s[2*kk+1][2], s[2*kk+1][3]);
                #pragma unroll
                for (int nv = 0; nv < 4; nv++) {
                    uint32_t off = SWZ((uint32_t)((kk*16 + (lane & 15))*128 + (nv*16 + 8*(lane >> 4))*2));
                    uint32_t rh[4];
                    ldsm4t(rh, vB + off);
                    uint32_t b0[2] = { rh[0], rh[1] }, b1[2] = { rh[2], rh[3] };
                    mma_f16(o[2*nv],   ph, b0);
                    mma_f16(o[2*nv+1], ph, b1);
                }
            }
        }
        __syncthreads();
    }

    // ---- epilogue: O/l -> fp16 ctx ----
    float li0 = 1.0f / lst0, li1 = 1.0f / lst1;
    int colB = h*64 + ((lane & 3) << 1);
    size_t row0 = rowOff + r0g, row1 = rowOff + r1g;
    #pragma unroll
    for (int nt = 0; nt < 8; nt++) {
        int col = colB + nt*8;
        *(uint32_t*)(C + row0*EMB + col) = cvt2h1(o[nt][0]*li0, o[nt][1]*li0);
        *(uint32_t*)(C + row1*EMB + col) = cvt2h1(o[nt][2]*li1, o[nt][3]*li1);
    }
}

// ---------------- launch ----------------
extern "C" void kernel_launch(void* const* d_in, const int* in_sizes, int n_in,
                              void* d_out, int out_size)
{
    const float* x  = (const float*)d_in[0];
    const float* Wq = (const float*)d_in[1];
    const float* Wk = (const float*)d_in[2];
    const float* Wv = (const float*)d_in[3];
    const float* Wo = (const float*)d_in[4];
    const float* bo = (const float*)d_in[5];
    const float* W1 = (const float*)d_in[6];
    const float* b1 = (const float*)d_in[7];
    const float* W2 = (const float*)d_in[8];
    const float* b2 = (const float*)d_in[9];
    const float* g1 = (const float*)d_in[10];
    const float* s1 = (const float*)d_in[11];
    const float* g2 = (const float*)d_in[12];
    const float* s2 = (const float*)d_in[13];
    float* out = (float*)d_out;

    __half *ln1, *qkv, *ctx, *y, *ff;
    __half *wqkvt, *wot, *w1t, *w2t;
    float *h;
    cudaGetSymbolAddress((void**)&ln1,  g_ln1);
    cudaGetSymbolAddress((void**)&qkv,  g_qkv);
    cudaGetSymbolAddress((void**)&ctx,  g_ctx);
    cudaGetSymbolAddress((void**)&h,    g_h);
    cudaGetSymbolAddress((void**)&y,    g_y);
    cudaGetSymbolAddress((void**)&ff,   g_ff);
    cudaGetSymbolAddress((void**)&wqkvt, g_wqkvt);
    cudaGetSymbolAddress((void**)&wot,  g_wot);
    cudaGetSymbolAddress((void**)&w1t,  g_w1t);
    cudaGetSymbolAddress((void**)&w2t,  g_w2t);

    cudaFuncSetAttribute(gemm_mma, cudaFuncAttributeMaxDynamicSharedMemorySize, SMEM_GEMM);
    cudaFuncSetAttribute(attn_kernel, cudaFuncAttributeMaxDynamicSharedMemorySize, SMEM_ATTN);

    dim3 blk(256);

    // launch order: my idx 3 = gemm_mma(qkv) -> lands in ncu's capture slot (-s 5 with 2 harness pre-launches)
    wconv_qkv_kernel<<<dim3(32, 32, 3), blk>>>(Wq, Wk, Wv, wqkvt);                   // 0
    wconv_rest_kernel<<<dim3(32, 32, 9), blk>>>(Wo, W1, W2, wot, w1t, w2t);          // 1
    ln_kernel<<<ROWS, blk>>>(x, g1, s1, ln1);                                        // 2
    gemm_mma<<<dim3(QKV_STR/256, ROWS/128), blk, SMEM_GEMM>>>(                       // 3 <- profiled
        ln1, wqkvt, nullptr, nullptr, nullptr, qkv, ROWS, QKV_STR, EMB, 0);
    attn_kernel<<<dim3(SEQ/128, BATCH*NHEADS), blk, SMEM_ATTN>>>(qkv, ctx);          // 4
    gemm_mma<<<dim3(EMB/256, ROWS/128), blk, SMEM_GEMM>>>(                           // 5
        ctx, wot, bo, x, h, nullptr, ROWS, EMB, EMB, 0);
    ln_kernel<<<ROWS, blk>>>(h, g2, s2, y);                                          // 6
    gemm_mma<<<dim3(DFF/256, ROWS/128), blk, SMEM_GEMM>>>(                           // 7
        y, w1t, b1, nullptr, nullptr, ff, ROWS, DFF, EMB, 1);
    gemm_mma<<<dim3(EMB/256, ROWS/128), blk, SMEM_GEMM>>>(                           // 8
        ff, w2t, b2, h, out, nullptr, ROWS, EMB, DFF, 0);
}

// round 9
// speedup vs baseline: 7.3781x; 1.0593x over previous
#include <cuda_runtime.h>
#include <cuda_fp16.h>
#include <math.h>
#include <stdint.h>

#define EMB 1024
#define SEQ 2048
#define BATCH 2
#define ROWS (BATCH*SEQ)   /* 4096 */
#define DFF (4*EMB)        /* 4096 */
#define NHEADS 16
#define HD 64
#define QKV_STR (3*EMB)    /* 3072 */

// ---------------- scratch (device globals: no allocation allowed) ----------------
__device__ __half g_ln1[ROWS*EMB];
__device__ __half g_qkv[(size_t)ROWS*QKV_STR];
__device__ __half g_ctx[ROWS*EMB];
__device__ float  g_h  [ROWS*EMB];
__device__ __half g_y  [ROWS*EMB];
__device__ __half g_ff [(size_t)ROWS*DFF];
// transposed fp16 weights: Wt[N,K]
__device__ __half g_wqkvt[3*EMB*EMB];
__device__ __half g_wot[EMB*EMB];
__device__ __half g_w1t[EMB*DFF];
__device__ __half g_w2t[DFF*EMB];

// ---------------- helpers ----------------
__device__ __forceinline__ uint32_t smem_to_u32(const void* p) {
    uint32_t a;
    asm("{ .reg .u64 t; cvta.to.shared.u64 t, %1; cvt.u32.u64 %0, t; }" : "=r"(a) : "l"(p));
    return a;
}
#define SWZ(off) ((off) ^ (((off) >> 3) & 0x70))

__device__ __forceinline__ void ldsm4(uint32_t* r, uint32_t addr) {
    asm volatile("ldmatrix.sync.aligned.m8n8.x4.shared.b16 {%0,%1,%2,%3}, [%4];"
        : "=r"(r[0]), "=r"(r[1]), "=r"(r[2]), "=r"(r[3]) : "r"(addr));
}
__device__ __forceinline__ void ldsm4t(uint32_t* r, uint32_t addr) {
    asm volatile("ldmatrix.sync.aligned.m8n8.x4.trans.shared.b16 {%0,%1,%2,%3}, [%4];"
        : "=r"(r[0]), "=r"(r[1]), "=r"(r[2]), "=r"(r[3]) : "r"(addr));
}
__device__ __forceinline__ void mma_f16(float* d, const uint32_t* a, const uint32_t* b) {
    asm volatile("mma.sync.aligned.m16n8k16.row.col.f32.f16.f16.f32 "
        "{%0,%1,%2,%3}, {%4,%5,%6,%7}, {%8,%9}, {%0,%1,%2,%3};"
        : "+f"(d[0]), "+f"(d[1]), "+f"(d[2]), "+f"(d[3])
        : "r"(a[0]), "r"(a[1]), "r"(a[2]), "r"(a[3]), "r"(b[0]), "r"(b[1]));
}
__device__ __forceinline__ void cp16(uint32_t s, const void* g) {
    asm volatile("cp.async.cg.shared.global [%0], [%1], 16;" :: "r"(s), "l"(g));
}
#define CP_COMMIT() asm volatile("cp.async.commit_group;" ::: "memory")
#define CP_WAIT(n)  asm volatile("cp.async.wait_group %0;" :: "n"(n) : "memory")

__device__ __forceinline__ uint32_t pack_h(__half a, __half b) {
    return (uint32_t)__half_as_ushort(a) | ((uint32_t)__half_as_ushort(b) << 16);
}
__device__ __forceinline__ uint32_t cvt2h1(float a, float b) {
    return pack_h(__float2half_rn(a), __float2half_rn(b));
}
__device__ __forceinline__ float gelu_f(float x)
{
    float u = 0.7978845608028654f * (x + 0.044715f * x * x * x);
    return 0.5f * x * (1.0f + tanhf(u));
}

// ---------------- layernorm: fp32 in -> fp16 out ----------------
__global__ __launch_bounds__(256) void ln_kernel(const float* __restrict__ x,
    const float* __restrict__ g, const float* __restrict__ s,
    __half* __restrict__ o)
{
    __shared__ float red[16];
    int row = blockIdx.x;
    int t = threadIdx.x;
    const float4* xr = reinterpret_cast<const float4*>(x + (size_t)row*EMB);
    float4 v = xr[t];
    float sum = v.x+v.y+v.z+v.w;
    float sq  = v.x*v.x+v.y*v.y+v.z*v.z+v.w*v.w;
    #pragma unroll
    for (int off = 16; off > 0; off >>= 1) {
        sum += __shfl_xor_sync(0xffffffffu, sum, off);
        sq  += __shfl_xor_sync(0xffffffffu, sq,  off);
    }
    int warp = t >> 5, lane = t & 31;
    if (lane == 0) { red[warp] = sum; red[warp+8] = sq; }
    __syncthreads();
    if (t < 32) {
        float a  = (lane < 8) ? red[lane]   : 0.0f;
        float b2 = (lane < 8) ? red[lane+8] : 0.0f;
        #pragma unroll
        for (int off = 4; off > 0; off >>= 1) {
            a  += __shfl_xor_sync(0xffffffffu, a,  off);
            b2 += __shfl_xor_sync(0xffffffffu, b2, off);
        }
        if (lane == 0) { red[0] = a; red[1] = b2; }
    }
    __syncthreads();
    float mean = red[0] * (1.0f/EMB);
    float var  = red[1] * (1.0f/EMB) - mean*mean;
    float inv  = rsqrtf(var + 1e-5f);
    float4 gv = reinterpret_cast<const float4*>(g)[t];
    float4 sv = reinterpret_cast<const float4*>(s)[t];
    float o0 = (v.x - mean)*inv*gv.x + sv.x;
    float o1 = (v.y - mean)*inv*gv.y + sv.y;
    float o2 = (v.z - mean)*inv*gv.z + sv.z;
    float o3 = (v.w - mean)*inv*gv.w + sv.w;
    *(uint2*)(o + (size_t)row*EMB + t*4) = make_uint2(cvt2h1(o0, o1), cvt2h1(o2, o3));
}

// ---------------- fused weight transposes: W[K,N] fp32 -> Wt[N,K] fp16 ----------------
__device__ __forceinline__ void wtile(const float* __restrict__ W, __half* __restrict__ O,
                                      int K, int N, int n0, int k0)
{
    __shared__ float tile[32][33];
    int tx = threadIdx.x & 31, ty = threadIdx.x >> 5;   // 32 x 8
    #pragma unroll
    for (int i = 0; i < 4; i++)
        tile[ty + 8*i][tx] = W[(size_t)(k0 + ty + 8*i)*N + n0 + tx];
    __syncthreads();
    #pragma unroll
    for (int i = 0; i < 4; i++) {
        float x = tile[tx][ty + 8*i];
        O[(size_t)(n0 + ty + 8*i)*K + k0 + tx] = __float2half_rn(x);
    }
}

__global__ __launch_bounds__(256) void wconv_qkv_kernel(
    const float* __restrict__ Wq, const float* __restrict__ Wk, const float* __restrict__ Wv,
    __half* __restrict__ O)
{
    int z = blockIdx.z;
    const float* W = (z == 0) ? Wq : (z == 1) ? Wk : Wv;
    wtile(W, O + (size_t)z*EMB*EMB, EMB, EMB, blockIdx.x*32, blockIdx.y*32);
}

__global__ __launch_bounds__(256) void wconv_rest_kernel(
    const float* __restrict__ Wo, const float* __restrict__ W1, const float* __restrict__ W2,
    __half* __restrict__ wot, __half* __restrict__ w1t, __half* __restrict__ w2t)
{
    int z = blockIdx.z;
    if (z == 0) {
        wtile(Wo, wot, EMB, EMB, blockIdx.x*32, blockIdx.y*32);
    } else if (z < 5) {
        wtile(W1, w1t, EMB, DFF, (z-1)*1024 + blockIdx.x*32, blockIdx.y*32);
    } else {
        wtile(W2, w2t, DFF, EMB, blockIdx.x*32, (z-5)*1024 + blockIdx.y*32);
    }
}

// ---------------- mma.sync fp16 GEMM (128x128 tile, 3-stage, 2 CTAs/SM) ----------------
// Warp grid 2m x 4n -> 64x32 warp tile. acc = 64 regs/thread.
#define KC 64
#define STAGE 32768
#define SMEM_GEMM (3*STAGE)
__global__ __launch_bounds__(256, 2) void gemm_mma(
    const __half* __restrict__ A, const __half* __restrict__ Bt,
    const float* __restrict__ bias, const float* __restrict__ res,
    float* __restrict__ outF, __half* __restrict__ outH,
    int M, int N, int K, int dogelu)
{
    extern __shared__ char smem[];
    uint32_t sb = smem_to_u32(smem);
    int t = threadIdx.x, w = t >> 5, lane = t & 31;
    int wm = w >> 2, wn = w & 3;               // warp grid 2(m) x 4(n)
    int m0 = blockIdx.y*128, n0 = blockIdx.x*128;

    const __half* srcA = A + (size_t)m0*K;
    const __half* srcB = Bt + (size_t)n0*K;

    float acc[4][4][4];
    #pragma unroll
    for (int mt = 0; mt < 4; mt++)
        #pragma unroll
        for (int nt = 0; nt < 4; nt++)
            #pragma unroll
            for (int e = 0; e < 4; e++) acc[mt][nt][e] = 0.0f;

    int nc = K / KC;

    // stage layout: A @0 (16KB), B @16384 (16KB)
    auto issue = [&](int c, int buf) {
        uint32_t stb = sb + buf*STAGE;
        #pragma unroll
        for (int i = 0; i < 8; i++) {
            int id = t + 256*i;
            if (id < 1024) {           // A: 1024 chunks
                int row = id >> 3, c16 = id & 7;
                cp16(stb + SWZ((uint32_t)(row*128 + c16*16)),
                     srcA + (size_t)row*K + c*KC + c16*8);
            } else {                   // B: 1024 chunks
                int cid = id - 1024;
                int row = cid >> 3, c16 = cid & 7;
                cp16(stb + 16384 + SWZ((uint32_t)(row*128 + c16*16)),
                     srcB + (size_t)row*K + c*KC + c16*8);
            }
        }
    };

    issue(0, 0);
    CP_COMMIT();
    if (nc > 1) { issue(1, 1); CP_COMMIT(); }

    int arow = lane & 15;
    int acol = (lane >> 4) << 4;
    int brow = ((lane >> 4) << 3) + (lane & 7);
    int bcol = ((lane >> 3) & 1) << 4;

    for (int c = 0; c < nc; c++) {
        int buf = c % 3;
        if (c + 2 < nc) { issue(c+2, (c+2) % 3); CP_COMMIT(); CP_WAIT(2); }
        else if (c + 1 < nc) { CP_WAIT(1); }
        else { CP_WAIT(0); }
        __syncthreads();

        {
            uint32_t aB = sb + buf*STAGE;
            uint32_t bB = aB + 16384;
            #pragma unroll
            for (int ks = 0; ks < 4; ks++) {
                int kb = ks * 32;
                uint32_t ah[4][4];
                #pragma unroll
                for (int mt = 0; mt < 4; mt++) {
                    uint32_t off = SWZ((uint32_t)((wm*64 + mt*16 + arow)*128 + kb + acol));
                    ldsm4(ah[mt], aB + off);
                }
                #pragma unroll
                for (int nh = 0; nh < 2; nh++) {
                    uint32_t off = SWZ((uint32_t)((wn*32 + nh*16 + brow)*128 + kb + bcol));
                    uint32_t rb[4];
                    ldsm4(rb, bB + off);
                    uint32_t b0[2] = { rb[0], rb[1] }, b1[2] = { rb[2], rb[3] };
                    #pragma unroll
                    for (int mt = 0; mt < 4; mt++) {
                        mma_f16(acc[mt][2*nh],   ah[mt], b0);
                        mma_f16(acc[mt][2*nh+1], ah[mt], b1);
                    }
                }
            }
        }
        __syncthreads();
    }

    // ---- epilogue ----
    int mBase = m0 + wm*64;
    int nBase = n0 + wn*32;
    #pragma unroll
    for (int mt = 0; mt < 4; mt++) {
        #pragma unroll
        for (int nt = 0; nt < 4; nt++) {
            int row = mBase + mt*16 + (lane >> 2);
            int col = nBase + nt*8 + ((lane & 3) << 1);
            float v0 = acc[mt][nt][0], v1 = acc[mt][nt][1];
            float v2 = acc[mt][nt][2], v3 = acc[mt][nt][3];
            if (bias) {
                float2 bb = *(const float2*)(bias + col);
                v0 += bb.x; v1 += bb.y; v2 += bb.x; v3 += bb.y;
            }
            if (dogelu) {
                v0 = gelu_f(v0); v1 = gelu_f(v1);
                v2 = gelu_f(v2); v3 = gelu_f(v3);
            }
            if (outF) {
                if (res) {
                    float2 r0 = *(const float2*)(res + (size_t)row*N + col);
                    float2 r1 = *(const float2*)(res + (size_t)(row+8)*N + col);
                    v0 += r0.x; v1 += r0.y; v2 += r1.x; v3 += r1.y;
                }
                *(float2*)(outF + (size_t)row*N + col) = make_float2(v0, v1);
                *(float2*)(outF + (size_t)(row+8)*N + col) = make_float2(v2, v3);
            } else {
                *(uint32_t*)(outH + (size_t)row*N + col) = cvt2h1(v0, v1);
                *(uint32_t*)(outH + (size_t)(row+8)*N + col) = cvt2h1(v2, v3);
            }
        }
    }
}

// ---------------- causal flash attention, fp16 mma single-pass ----------------
// QKV packed fp16 [ROWS, 3072]; out ctx fp16 [ROWS, 1024].
// Block: 256 thr (8 warps), q-tile 128 (warp w owns rows w*16..+15), kv-tile 64.
#define STAGE_ATT 16384
#define SMEM_ATTN (16384 + 2*STAGE_ATT)
__global__ __launch_bounds__(256) void attn_kernel(
    const __half* __restrict__ Q, __half* __restrict__ C)
{
    extern __shared__ char smem[];
    uint32_t sb = smem_to_u32(smem);
    int t = threadIdx.x, w = t >> 5, lane = t & 31;
    int qt = gridDim.x - 1 - blockIdx.x;
    int bh_ = blockIdx.y;
    int h = bh_ & 15;
    size_t rowOff = (size_t)(bh_ >> 4) * SEQ;      // batch row offset
    int q0 = qt * 128;
    int colQ = h*64, colK = 1024 + h*64, colV = 2048 + h*64;

    // ---- async load Q ----
    #pragma unroll
    for (int i = 0; i < 4; i++) {
        int id = t + 256*i;
        int row = id >> 3, c16 = id & 7;
        const __half* gp = Q + (rowOff + q0 + row)*QKV_STR + colQ + c16*8;
        cp16(sb + SWZ((uint32_t)(row*128 + c16*16)), gp);
    }
    CP_COMMIT();

    int nkt = 2*qt + 2;

    // issue K/V stage: K @0, V @8192
    auto issue = [&](int kt, int buf) {
        uint32_t stb = sb + 16384 + buf*STAGE_ATT;
        int k0 = kt*64;
        #pragma unroll
        for (int i = 0; i < 4; i++) {
            int id = t + 256*i;
            int arr = id >> 9;           // 0 K, 1 V
            int cid = id & 511;
            int row = cid >> 3, c16 = cid & 7;
            int col = (arr == 0) ? colK : colV;
            const __half* gp = Q + (rowOff + k0 + row)*QKV_STR + col + c16*8;
            cp16(stb + arr*8192 + SWZ((uint32_t)(row*128 + c16*16)), gp);
        }
    };
    issue(0, 0);
    CP_COMMIT();
    CP_WAIT(1);          // Q ready
    __syncthreads();

    // ---- Q fragments to registers ----
    uint32_t qh[4][4];
    {
        int arow = lane & 15;
        int acol = (lane >> 4) << 4;
        #pragma unroll
        for (int kf = 0; kf < 4; kf++) {
            uint32_t off = SWZ((uint32_t)((w*16 + arow)*128 + kf*32 + acol));
            ldsm4(qh[kf], sb + off);
        }
    }

    float o[8][4];
    #pragma unroll
    for (int nt = 0; nt < 8; nt++)
        #pragma unroll
        for (int e = 0; e < 4; e++) o[nt][e] = 0.0f;
    float mst0 = -1e30f, mst1 = -1e30f, lst0 = 0.0f, lst1 = 0.0f;

    int r0g = q0 + w*16 + (lane >> 2);
    int r1g = r0g + 8;

    for (int kt = 0; kt < nkt; kt++) {
        int buf = kt & 1;
        if (kt + 1 < nkt) issue(kt+1, buf^1);
        CP_COMMIT();
        if (kt + 1 < nkt) { CP_WAIT(1); } else { CP_WAIT(0); }
        __syncthreads();

        int k0 = kt*64;
        if (k0 <= q0 + w*16 + 15) {     // at least one unmasked element for this warp
            uint32_t stb = sb + 16384 + buf*STAGE_ATT;
            uint32_t kB = stb, vB = stb + 8192;

            // ---- S = Q @ K^T ----
            float s[8][4];
            #pragma unroll
            for (int nt = 0; nt < 8; nt++)
                #pragma unroll
                for (int e = 0; e < 4; e++) s[nt][e] = 0.0f;
            {
                int brow = ((lane >> 4) << 3) + (lane & 7);
                int bcol = ((lane >> 3) & 1) << 4;
                #pragma unroll
                for (int ks = 0; ks < 4; ks++) {
                    int kb = ks*32;
                    #pragma unroll
                    for (int nh = 0; nh < 4; nh++) {
                        uint32_t off = SWZ((uint32_t)((nh*16 + brow)*128 + kb + bcol));
                        uint32_t rb[4];
                        ldsm4(rb, kB + off);
                        uint32_t b0[2] = { rb[0], rb[1] }, b1[2] = { rb[2], rb[3] };
                        mma_f16(s[2*nh],   qh[ks], b0);
                        mma_f16(s[2*nh+1], qh[ks], b1);
                    }
                }
            }

            // ---- scale + causal mask + online softmax ----
            float mx0 = -1e30f, mx1 = -1e30f;
            #pragma unroll
            for (int nt = 0; nt < 8; nt++) {
                int kgBase = k0 + nt*8 + ((lane & 3) << 1);
                #pragma unroll
                for (int e = 0; e < 4; e++) {
                    float v = s[nt][e] * 0.125f;
                    int kg = kgBase + (e & 1);
                    int qg = (e < 2) ? r0g : r1g;
                    v = (kg <= qg) ? v : -1e30f;
                    s[nt][e] = v;
                    if (e < 2) mx0 = fmaxf(mx0, v); else mx1 = fmaxf(mx1, v);
                }
            }
            mx0 = fmaxf(mx0, __shfl_xor_sync(0xffffffffu, mx0, 1));
            mx0 = fmaxf(mx0, __shfl_xor_sync(0xffffffffu, mx0, 2));
            mx1 = fmaxf(mx1, __shfl_xor_sync(0xffffffffu, mx1, 1));
            mx1 = fmaxf(mx1, __shfl_xor_sync(0xffffffffu, mx1, 2));
            float mn0 = fmaxf(mst0, mx0), mn1 = fmaxf(mst1, mx1);
            float a0 = __expf(mst0 - mn0), a1 = __expf(mst1 - mn1);
            mst0 = mn0; mst1 = mn1;
            float s0 = 0.0f, s1 = 0.0f;
            #pragma unroll
            for (int nt = 0; nt < 8; nt++) {
                float p0 = __expf(s[nt][0] - mn0);
                float p1 = __expf(s[nt][1] - mn0);
                float p2 = __expf(s[nt][2] - mn1);
                float p3 = __expf(s[nt][3] - mn1);
                s[nt][0] = p0; s[nt][1] = p1; s[nt][2] = p2; s[nt][3] = p3;
                s0 += p0 + p1; s1 += p2 + p3;
            }
            s0 += __shfl_xor_sync(0xffffffffu, s0, 1);
            s0 += __shfl_xor_sync(0xffffffffu, s0, 2);
            s1 += __shfl_xor_sync(0xffffffffu, s1, 1);
            s1 += __shfl_xor_sync(0xffffffffu, s1, 2);
            lst0 = lst0*a0 + s0;
            lst1 = lst1*a1 + s1;
            #pragma unroll
            for (int nt = 0; nt < 8; nt++) {
                o[nt][0] *= a0; o[nt][1] *= a0;
                o[nt][2] *= a1; o[nt][3] *= a1;
            }

            // ---- O += P @ V, P single fp16 ----
            #pragma unroll
            for (int kk = 0; kk < 4; kk++) {
                uint32_t ph[4];
                ph[0] = cvt2h1(s[2*kk][0],   s[2*kk][1]);
                ph[1] = cvt2h1(s[2*kk][2],   s[2*kk][3]);
                ph[2] = cvt2h1(s[2*kk+1][0], s[2*kk+1][1]);
                ph[3] = cvt2h1(s[2*kk+1][2], s[2*kk+1][3]);
                #pragma unroll
                for (int nv = 0; nv < 4; nv++) {
                    uint32_t off = SWZ((uint32_t)((kk*16 + (lane & 15))*128 + (nv*16 + 8*(lane >> 4))*2));
                    uint32_t rh[4];
                    ldsm4t(rh, vB + off);
                    uint32_t b0[2] = { rh[0], rh[1] }, b1[2] = { rh[2], rh[3] };
                    mma_f16(o[2*nv],   ph, b0);
                    mma_f16(o[2*nv+1], ph, b1);
                }
            }
        }
        __syncthreads();
    }

    // ---- epilogue: O/l -> fp16 ctx ----
    float li0 = 1.0f / lst0, li1 = 1.0f / lst1;
    int colB = h*64 + ((lane & 3) << 1);
    size_t row0 = rowOff + r0g, row1 = rowOff + r1g;
    #pragma unroll
    for (int nt = 0; nt < 8; nt++) {
        int col = colB + nt*8;
        *(uint32_t*)(C + row0*EMB + col) = cvt2h1(o[nt][0]*li0, o[nt][1]*li0);
        *(uint32_t*)(C + row1*EMB + col) = cvt2h1(o[nt][2]*li1, o[nt][3]*li1);
    }
}

// ---------------- launch ----------------
extern "C" void kernel_launch(void* const* d_in, const int* in_sizes, int n_in,
                              void* d_out, int out_size)
{
    const float* x  = (const float*)d_in[0];
    const float* Wq = (const float*)d_in[1];
    const float* Wk = (const float*)d_in[2];
    const float* Wv = (const float*)d_in[3];
    const float* Wo = (const float*)d_in[4];
    const float* bo = (const float*)d_in[5];
    const float* W1 = (const float*)d_in[6];
    const float* b1 = (const float*)d_in[7];
    const float* W2 = (const float*)d_in[8];
    const float* b2 = (const float*)d_in[9];
    const float* g1 = (const float*)d_in[10];
    const float* s1 = (const float*)d_in[11];
    const float* g2 = (const float*)d_in[12];
    const float* s2 = (const float*)d_in[13];
    float* out = (float*)d_out;

    __half *ln1, *qkv, *ctx, *y, *ff;
    __half *wqkvt, *wot, *w1t, *w2t;
    float *h;
    cudaGetSymbolAddress((void**)&ln1,  g_ln1);
    cudaGetSymbolAddress((void**)&qkv,  g_qkv);
    cudaGetSymbolAddress((void**)&ctx,  g_ctx);
    cudaGetSymbolAddress((void**)&h,    g_h);
    cudaGetSymbolAddress((void**)&y,    g_y);
    cudaGetSymbolAddress((void**)&ff,   g_ff);
    cudaGetSymbolAddress((void**)&wqkvt, g_wqkvt);
    cudaGetSymbolAddress((void**)&wot,  g_wot);
    cudaGetSymbolAddress((void**)&w1t,  g_w1t);
    cudaGetSymbolAddress((void**)&w2t,  g_w2t);

    cudaFuncSetAttribute(gemm_mma, cudaFuncAttributeMaxDynamicSharedMemorySize, SMEM_GEMM);
    cudaFuncSetAttribute(attn_kernel, cudaFuncAttributeMaxDynamicSharedMemorySize, SMEM_ATTN);

    dim3 blk(256);

    // launch order: my idx 3 = gemm_mma(qkv) -> lands in ncu's capture slot
    wconv_qkv_kernel<<<dim3(32, 32, 3), blk>>>(Wq, Wk, Wv, wqkvt);                   // 0
    wconv_rest_kernel<<<dim3(32, 32, 9), blk>>>(Wo, W1, W2, wot, w1t, w2t);          // 1
    ln_kernel<<<ROWS, blk>>>(x, g1, s1, ln1);                                        // 2
    gemm_mma<<<dim3(QKV_STR/128, ROWS/128), blk, SMEM_GEMM>>>(                       // 3 <- profiled
        ln1, wqkvt, nullptr, nullptr, nullptr, qkv, ROWS, QKV_STR, EMB, 0);
    attn_kernel<<<dim3(SEQ/128, BATCH*NHEADS), blk, SMEM_ATTN>>>(qkv, ctx);          // 4
    gemm_mma<<<dim3(EMB/128, ROWS/128), blk, SMEM_GEMM>>>(                           // 5
        ctx, wot, bo, x, h, nullptr, ROWS, EMB, EMB, 0);
    ln_kernel<<<ROWS, blk>>>(h, g2, s2, y);                                          // 6
    gemm_mma<<<dim3(DFF/128, ROWS/128), blk, SMEM_GEMM>>>(                           // 7
        y, w1t, b1, nullptr, nullptr, ff, ROWS, DFF, EMB, 1);
    gemm_mma<<<dim3(EMB/128, ROWS/128), blk, SMEM_GEMM>>>(                           // 8
        ff, w2t, b2, h, out, nullptr, ROWS, EMB, DFF, 0);
}

// round 10
// speedup vs baseline: 7.4501x; 1.0097x over previous
#include <cuda_runtime.h>
#include <cuda_fp16.h>
#include <math.h>
#include <stdint.h>

#define EMB 1024
#define SEQ 2048
#define BATCH 2
#define ROWS (BATCH*SEQ)   /* 4096 */
#define DFF (4*EMB)        /* 4096 */
#define NHEADS 16
#define HD 64
#define QKV_STR (3*EMB)    /* 3072 */

// ---------------- scratch (device globals: no allocation allowed) ----------------
__device__ __half g_ln1[ROWS*EMB];
__device__ __half g_qkv[(size_t)ROWS*QKV_STR];
__device__ __half g_ctx[ROWS*EMB];
__device__ float  g_h  [ROWS*EMB];
__device__ __half g_y  [ROWS*EMB];
__device__ __half g_ff [(size_t)ROWS*DFF];
// transposed fp16 weights: Wt[N,K]
__device__ __half g_wqkvt[3*EMB*EMB];
__device__ __half g_wot[EMB*EMB];
__device__ __half g_w1t[EMB*DFF];
__device__ __half g_w2t[DFF*EMB];

// ---------------- helpers ----------------
__device__ __forceinline__ uint32_t smem_to_u32(const void* p) {
    uint32_t a;
    asm("{ .reg .u64 t; cvta.to.shared.u64 t, %1; cvt.u32.u64 %0, t; }" : "=r"(a) : "l"(p));
    return a;
}
#define SWZ(off) ((off) ^ (((off) >> 3) & 0x70))

__device__ __forceinline__ void ldsm4(uint32_t* r, uint32_t addr) {
    asm volatile("ldmatrix.sync.aligned.m8n8.x4.shared.b16 {%0,%1,%2,%3}, [%4];"
        : "=r"(r[0]), "=r"(r[1]), "=r"(r[2]), "=r"(r[3]) : "r"(addr));
}
__device__ __forceinline__ void ldsm4t(uint32_t* r, uint32_t addr) {
    asm volatile("ldmatrix.sync.aligned.m8n8.x4.trans.shared.b16 {%0,%1,%2,%3}, [%4];"
        : "=r"(r[0]), "=r"(r[1]), "=r"(r[2]), "=r"(r[3]) : "r"(addr));
}
__device__ __forceinline__ void mma_f16(float* d, const uint32_t* a, const uint32_t* b) {
    asm volatile("mma.sync.aligned.m16n8k16.row.col.f32.f16.f16.f32 "
        "{%0,%1,%2,%3}, {%4,%5,%6,%7}, {%8,%9}, {%0,%1,%2,%3};"
        : "+f"(d[0]), "+f"(d[1]), "+f"(d[2]), "+f"(d[3])
        : "r"(a[0]), "r"(a[1]), "r"(a[2]), "r"(a[3]), "r"(b[0]), "r"(b[1]));
}
__device__ __forceinline__ void cp16(uint32_t s, const void* g) {
    asm volatile("cp.async.cg.shared.global [%0], [%1], 16;" :: "r"(s), "l"(g));
}
#define CP_COMMIT() asm volatile("cp.async.commit_group;" ::: "memory")
#define CP_WAIT(n)  asm volatile("cp.async.wait_group %0;" :: "n"(n) : "memory")

__device__ __forceinline__ uint32_t pack_h(__half a, __half b) {
    return (uint32_t)__half_as_ushort(a) | ((uint32_t)__half_as_ushort(b) << 16);
}
__device__ __forceinline__ uint32_t cvt2h1(float a, float b) {
    return pack_h(__float2half_rn(a), __float2half_rn(b));
}
__device__ __forceinline__ float gelu_f(float x)
{
    float u = 0.7978845608028654f * (x + 0.044715f * x * x * x);
    return 0.5f * x * (1.0f + tanhf(u));
}

// ---------------- layernorm: fp32 in -> fp16 out ----------------
__global__ __launch_bounds__(256) void ln_kernel(const float* __restrict__ x,
    const float* __restrict__ g, const float* __restrict__ s,
    __half* __restrict__ o)
{
    __shared__ float red[16];
    int row = blockIdx.x;
    int t = threadIdx.x;
    const float4* xr = reinterpret_cast<const float4*>(x + (size_t)row*EMB);
    float4 v = xr[t];
    float sum = v.x+v.y+v.z+v.w;
    float sq  = v.x*v.x+v.y*v.y+v.z*v.z+v.w*v.w;
    #pragma unroll
    for (int off = 16; off > 0; off >>= 1) {
        sum += __shfl_xor_sync(0xffffffffu, sum, off);
        sq  += __shfl_xor_sync(0xffffffffu, sq,  off);
    }
    int warp = t >> 5, lane = t & 31;
    if (lane == 0) { red[warp] = sum; red[warp+8] = sq; }
    __syncthreads();
    if (t < 32) {
        float a  = (lane < 8) ? red[lane]   : 0.0f;
        float b2 = (lane < 8) ? red[lane+8] : 0.0f;
        #pragma unroll
        for (int off = 4; off > 0; off >>= 1) {
            a  += __shfl_xor_sync(0xffffffffu, a,  off);
            b2 += __shfl_xor_sync(0xffffffffu, b2, off);
        }
        if (lane == 0) { red[0] = a; red[1] = b2; }
    }
    __syncthreads();
    float mean = red[0] * (1.0f/EMB);
    float var  = red[1] * (1.0f/EMB) - mean*mean;
    float inv  = rsqrtf(var + 1e-5f);
    float4 gv = reinterpret_cast<const float4*>(g)[t];
    float4 sv = reinterpret_cast<const float4*>(s)[t];
    float o0 = (v.x - mean)*inv*gv.x + sv.x;
    float o1 = (v.y - mean)*inv*gv.y + sv.y;
    float o2 = (v.z - mean)*inv*gv.z + sv.z;
    float o3 = (v.w - mean)*inv*gv.w + sv.w;
    *(uint2*)(o + (size_t)row*EMB + t*4) = make_uint2(cvt2h1(o0, o1), cvt2h1(o2, o3));
}

// ---------------- fused weight transposes: W[K,N] fp32 -> Wt[N,K] fp16 ----------------
__device__ __forceinline__ void wtile(const float* __restrict__ W, __half* __restrict__ O,
                                      int K, int N, int n0, int k0)
{
    __shared__ float tile[32][33];
    int tx = threadIdx.x & 31, ty = threadIdx.x >> 5;   // 32 x 8
    #pragma unroll
    for (int i = 0; i < 4; i++)
        tile[ty + 8*i][tx] = W[(size_t)(k0 + ty + 8*i)*N + n0 + tx];
    __syncthreads();
    #pragma unroll
    for (int i = 0; i < 4; i++) {
        float x = tile[tx][ty + 8*i];
        O[(size_t)(n0 + ty + 8*i)*K + k0 + tx] = __float2half_rn(x);
    }
}

__global__ __launch_bounds__(256) void wconv_qkv_kernel(
    const float* __restrict__ Wq, const float* __restrict__ Wk, const float* __restrict__ Wv,
    __half* __restrict__ O)
{
    int z = blockIdx.z;
    const float* W = (z == 0) ? Wq : (z == 1) ? Wk : Wv;
    wtile(W, O + (size_t)z*EMB*EMB, EMB, EMB, blockIdx.x*32, blockIdx.y*32);
}

__global__ __launch_bounds__(256) void wconv_rest_kernel(
    const float* __restrict__ Wo, const float* __restrict__ W1, const float* __restrict__ W2,
    __half* __restrict__ wot, __half* __restrict__ w1t, __half* __restrict__ w2t)
{
    int z = blockIdx.z;
    if (z == 0) {
        wtile(Wo, wot, EMB, EMB, blockIdx.x*32, blockIdx.y*32);
    } else if (z < 5) {
        wtile(W1, w1t, EMB, DFF, (z-1)*1024 + blockIdx.x*32, blockIdx.y*32);
    } else {
        wtile(W2, w2t, DFF, EMB, blockIdx.x*32, (z-5)*1024 + blockIdx.y*32);
    }
}

// ---------------- mma.sync fp16 GEMM (128x128 tile, 3-stage, 2 CTAs/SM) ----------------
// Warp grid 2m x 4n -> 64x32 warp tile. Fragments double-buffered across ks
// so each ks's 6 ldsm are issued BEFORE the previous ks's 16 mma retire.
#define KC 64
#define STAGE 32768
#define SMEM_GEMM (3*STAGE)
__global__ __launch_bounds__(256, 2) void gemm_mma(
    const __half* __restrict__ A, const __half* __restrict__ Bt,
    const float* __restrict__ bias, const float* __restrict__ res,
    float* __restrict__ outF, __half* __restrict__ outH,
    int M, int N, int K, int dogelu)
{
    extern __shared__ char smem[];
    uint32_t sb = smem_to_u32(smem);
    int t = threadIdx.x, w = t >> 5, lane = t & 31;
    int wm = w >> 2, wn = w & 3;               // warp grid 2(m) x 4(n)
    int m0 = blockIdx.y*128, n0 = blockIdx.x*128;

    const __half* srcA = A + (size_t)m0*K;
    const __half* srcB = Bt + (size_t)n0*K;

    float acc[4][4][4];
    #pragma unroll
    for (int mt = 0; mt < 4; mt++)
        #pragma unroll
        for (int nt = 0; nt < 4; nt++)
            #pragma unroll
            for (int e = 0; e < 4; e++) acc[mt][nt][e] = 0.0f;

    int nc = K / KC;

    // stage layout: A @0 (16KB), B @16384 (16KB)
    auto issue = [&](int c, int buf) {
        uint32_t stb = sb + buf*STAGE;
        #pragma unroll
        for (int i = 0; i < 8; i++) {
            int id = t + 256*i;
            if (id < 1024) {           // A: 1024 chunks
                int row = id >> 3, c16 = id & 7;
                cp16(stb + SWZ((uint32_t)(row*128 + c16*16)),
                     srcA + (size_t)row*K + c*KC + c16*8);
            } else {                   // B: 1024 chunks
                int cid = id - 1024;
                int row = cid >> 3, c16 = cid & 7;
                cp16(stb + 16384 + SWZ((uint32_t)(row*128 + c16*16)),
                     srcB + (size_t)row*K + c*KC + c16*8);
            }
        }
    };

    issue(0, 0);
    CP_COMMIT();
    if (nc > 1) { issue(1, 1); CP_COMMIT(); }

    int arow = lane & 15;
    int acol = (lane >> 4) << 4;
    int brow = ((lane >> 4) << 3) + (lane & 7);
    int bcol = ((lane >> 3) & 1) << 4;

    for (int c = 0; c < nc; c++) {
        int buf = c % 3;
        if (c + 2 < nc) { issue(c+2, (c+2) % 3); CP_COMMIT(); CP_WAIT(2); }
        else if (c + 1 < nc) { CP_WAIT(1); }
        else { CP_WAIT(0); }
        __syncthreads();

        {
            uint32_t aB = sb + buf*STAGE;
            uint32_t bB = aB + 16384;
            uint32_t ah[2][4][4], bb[2][2][4];

            // prologue: fragments for ks=0
            #pragma unroll
            for (int mt = 0; mt < 4; mt++)
                ldsm4(ah[0][mt], aB + SWZ((uint32_t)((wm*64 + mt*16 + arow)*128 + acol)));
            #pragma unroll
            for (int nh = 0; nh < 2; nh++)
                ldsm4(bb[0][nh], bB + SWZ((uint32_t)((wn*32 + nh*16 + brow)*128 + bcol)));

            #pragma unroll
            for (int ks = 0; ks < 4; ks++) {
                int cur = ks & 1, nxt = cur ^ 1;
                if (ks < 3) {
                    int kb = (ks+1) * 32;
                    #pragma unroll
                    for (int mt = 0; mt < 4; mt++)
                        ldsm4(ah[nxt][mt], aB + SWZ((uint32_t)((wm*64 + mt*16 + arow)*128 + kb + acol)));
                    #pragma unroll
                    for (int nh = 0; nh < 2; nh++)
                        ldsm4(bb[nxt][nh], bB + SWZ((uint32_t)((wn*32 + nh*16 + brow)*128 + kb + bcol)));
                }
                #pragma unroll
                for (int nh = 0; nh < 2; nh++) {
                    uint32_t b0[2] = { bb[cur][nh][0], bb[cur][nh][1] };
                    uint32_t b1[2] = { bb[cur][nh][2], bb[cur][nh][3] };
                    #pragma unroll
                    for (int mt = 0; mt < 4; mt++) {
                        mma_f16(acc[mt][2*nh],   ah[cur][mt], b0);
                        mma_f16(acc[mt][2*nh+1], ah[cur][mt], b1);
                    }
                }
            }
        }
        __syncthreads();
    }

    // ---- epilogue ----
    int mBase = m0 + wm*64;
    int nBase = n0 + wn*32;
    #pragma unroll
    for (int mt = 0; mt < 4; mt++) {
        #pragma unroll
        for (int nt = 0; nt < 4; nt++) {
            int row = mBase + mt*16 + (lane >> 2);
            int col = nBase + nt*8 + ((lane & 3) << 1);
            float v0 = acc[mt][nt][0], v1 = acc[mt][nt][1];
            float v2 = acc[mt][nt][2], v3 = acc[mt][nt][3];
            if (bias) {
                float2 bb2 = *(const float2*)(bias + col);
                v0 += bb2.x; v1 += bb2.y; v2 += bb2.x; v3 += bb2.y;
            }
            if (dogelu) {
                v0 = gelu_f(v0); v1 = gelu_f(v1);
                v2 = gelu_f(v2); v3 = gelu_f(v3);
            }
            if (outF) {
                if (res) {
                    float2 r0 = *(const float2*)(res + (size_t)row*N + col);
                    float2 r1 = *(const float2*)(res + (size_t)(row+8)*N + col);
                    v0 += r0.x; v1 += r0.y; v2 += r1.x; v3 += r1.y;
                }
                *(float2*)(outF + (size_t)row*N + col) = make_float2(v0, v1);
                *(float2*)(outF + (size_t)(row+8)*N + col) = make_float2(v2, v3);
            } else {
                *(uint32_t*)(outH + (size_t)row*N + col) = cvt2h1(v0, v1);
                *(uint32_t*)(outH + (size_t)(row+8)*N + col) = cvt2h1(v2, v3);
            }
        }
    }
}

// ---------------- causal flash attention, fp16 mma single-pass ----------------
// QKV packed fp16 [ROWS, 3072]; out ctx fp16 [ROWS, 1024].
// Block: 256 thr (8 warps), q-tile 128 (warp w owns rows w*16..+15), kv-tile 64.
#define STAGE_ATT 16384
#define SMEM_ATTN (16384 + 2*STAGE_ATT)
__global__ __launch_bounds__(256) void attn_kernel(
    const __half* __restrict__ Q, __half* __restrict__ C)
{
    extern __shared__ char smem[];
    uint32_t sb = smem_to_u32(smem);
    int t = threadIdx.x, w = t >> 5, lane = t & 31;
    int qt = gridDim.x - 1 - blockIdx.x;
    int bh_ = blockIdx.y;
    int h = bh_ & 15;
    size_t rowOff = (size_t)(bh_ >> 4) * SEQ;      // batch row offset
    int q0 = qt * 128;
    int colQ = h*64, colK = 1024 + h*64, colV = 2048 + h*64;

    // ---- async load Q ----
    #pragma unroll
    for (int i = 0; i < 4; i++) {
        int id = t + 256*i;
        int row = id >> 3, c16 = id & 7;
        const __half* gp = Q + (rowOff + q0 + row)*QKV_STR + colQ + c16*8;
        cp16(sb + SWZ((uint32_t)(row*128 + c16*16)), gp);
    }
    CP_COMMIT();

    int nkt = 2*qt + 2;

    // issue K/V stage: K @0, V @8192
    auto issue = [&](int kt, int buf) {
        uint32_t stb = sb + 16384 + buf*STAGE_ATT;
        int k0 = kt*64;
        #pragma unroll
        for (int i = 0; i < 4; i++) {
            int id = t + 256*i;
            int arr = id >> 9;           // 0 K, 1 V
            int cid = id & 511;
            int row = cid >> 3, c16 = cid & 7;
            int col = (arr == 0) ? colK : colV;
            const __half* gp = Q + (rowOff + k0 + row)*QKV_STR + col + c16*8;
            cp16(stb + arr*8192 + SWZ((uint32_t)(row*128 + c16*16)), gp);
        }
    };
    issue(0, 0);
    CP_COMMIT();
    CP_WAIT(1);          // Q ready
    __syncthreads();

    // ---- Q fragments to registers ----
    uint32_t qh[4][4];
    {
        int arow = lane & 15;
        int acol = (lane >> 4) << 4;
        #pragma unroll
        for (int kf = 0; kf < 4; kf++) {
            uint32_t off = SWZ((uint32_t)((w*16 + arow)*128 + kf*32 + acol));
            ldsm4(qh[kf], sb + off);
        }
    }

    float o[8][4];
    #pragma unroll
    for (int nt = 0; nt < 8; nt++)
        #pragma unroll
        for (int e = 0; e < 4; e++) o[nt][e] = 0.0f;
    float mst0 = -1e30f, mst1 = -1e30f, lst0 = 0.0f, lst1 = 0.0f;

    int r0g = q0 + w*16 + (lane >> 2);
    int r1g = r0g + 8;

    for (int kt = 0; kt < nkt; kt++) {
        int buf = kt & 1;
        if (kt + 1 < nkt) issue(kt+1, buf^1);
        CP_COMMIT();
        if (kt + 1 < nkt) { CP_WAIT(1); } else { CP_WAIT(0); }
        __syncthreads();

        int k0 = kt*64;
        if (k0 <= q0 + w*16 + 15) {     // at least one unmasked element for this warp
            uint32_t stb = sb + 16384 + buf*STAGE_ATT;
            uint32_t kB = stb, vB = stb + 8192;

            // ---- S = Q @ K^T ----
            float s[8][4];
            #pragma unroll
            for (int nt = 0; nt < 8; nt++)
                #pragma unroll
                for (int e = 0; e < 4; e++) s[nt][e] = 0.0f;
            {
                int brow = ((lane >> 4) << 3) + (lane & 7);
                int bcol = ((lane >> 3) & 1) << 4;
                #pragma unroll
                for (int ks = 0; ks < 4; ks++) {
                    int kb = ks*32;
                    #pragma unroll
                    for (int nh = 0; nh < 4; nh++) {
                        uint32_t off = SWZ((uint32_t)((nh*16 + brow)*128 + kb + bcol));
                        uint32_t rb[4];
                        ldsm4(rb, kB + off);
                        uint32_t b0[2] = { rb[0], rb[1] }, b1[2] = { rb[2], rb[3] };
                        mma_f16(s[2*nh],   qh[ks], b0);
                        mma_f16(s[2*nh+1], qh[ks], b1);
                    }
                }
            }

            // ---- scale + causal mask + online softmax ----
            float mx0 = -1e30f, mx1 = -1e30f;
            #pragma unroll
            for (int nt = 0; nt < 8; nt++) {
                int kgBase = k0 + nt*8 + ((lane & 3) << 1);
                #pragma unroll
                for (int e = 0; e < 4; e++) {
                    float v = s[nt][e] * 0.125f;
                    int kg = kgBase + (e & 1);
                    int qg = (e < 2) ? r0g : r1g;
                    v = (kg <= qg) ? v : -1e30f;
                    s[nt][e] = v;
                    if (e < 2) mx0 = fmaxf(mx0, v); else mx1 = fmaxf(mx1, v);
                }
            }
            mx0 = fmaxf(mx0, __shfl_xor_sync(0xffffffffu, mx0, 1));
            mx0 = fmaxf(mx0, __shfl_xor_sync(0xffffffffu, mx0, 2));
            mx1 = fmaxf(mx1, __shfl_xor_sync(0xffffffffu, mx1, 1));
            mx1 = fmaxf(mx1, __shfl_xor_sync(0xffffffffu, mx1, 2));
            float mn0 = fmaxf(mst0, mx0), mn1 = fmaxf(mst1, mx1);
            float a0 = __expf(mst0 - mn0), a1 = __expf(mst1 - mn1);
            mst0 = mn0; mst1 = mn1;
            float s0 = 0.0f, s1 = 0.0f;
            #pragma unroll
            for (int nt = 0; nt < 8; nt++) {
                float p0 = __expf(s[nt][0] - mn0);
                float p1 = __expf(s[nt][1] - mn0);
                float p2 = __expf(s[nt][2] - mn1);
                float p3 = __expf(s[nt][3] - mn1);
                s[nt][0] = p0; s[nt][1] = p1; s[nt][2] = p2; s[nt][3] = p3;
                s0 += p0 + p1; s1 += p2 + p3;
            }
            s0 += __shfl_xor_sync(0xffffffffu, s0, 1);
            s0 += __shfl_xor_sync(0xffffffffu, s0, 2);
            s1 += __shfl_xor_sync(0xffffffffu, s1, 1);
            s1 += __shfl_xor_sync(0xffffffffu, s1, 2);
            lst0 = lst0*a0 + s0;
            lst1 = lst1*a1 + s1;
            #pragma unroll
            for (int nt = 0; nt < 8; nt++) {
                o[nt][0] *= a0; o[nt][1] *= a0;
                o[nt][2] *= a1; o[nt][3] *= a1;
            }

            // ---- O += P @ V, P single fp16 ----
            #pragma unroll
            for (int kk = 0; kk < 4; kk++) {
                uint32_t ph[4];
                ph[0] = cvt2h1(s[2*kk][0],   s[2*kk][1]);
                ph[1] = cvt2h1(s[2*kk][2],   s[2*kk][3]);
                ph[2] = cvt2h1(s[2*kk+1][0], s[2*kk+1][1]);
                ph[3] = cvt2h1(s[2*kk+1][2], s[2*kk+1][3]);
                #pragma unroll
                for (int nv = 0; nv < 4; nv++) {
                    uint32_t off = SWZ((uint32_t)((kk*16 + (lane & 15))*128 + (nv*16 + 8*(lane >> 4))*2));
                    uint32_t rh[4];
                    ldsm4t(rh, vB + off);
                    uint32_t b0[2] = { rh[0], rh[1] }, b1[2] = { rh[2], rh[3] };
                    mma_f16(o[2*nv],   ph, b0);
                    mma_f16(o[2*nv+1], ph, b1);
                }
            }
        }
        __syncthreads();
    }

    // ---- epilogue: O/l -> fp16 ctx ----
    float li0 = 1.0f / lst0, li1 = 1.0f / lst1;
    int colB = h*64 + ((lane & 3) << 1);
    size_t row0 = rowOff + r0g, row1 = rowOff + r1g;
    #pragma unroll
    for (int nt = 0; nt < 8; nt++) {
        int col = colB + nt*8;
        *(uint32_t*)(C + row0*EMB + col) = cvt2h1(o[nt][0]*li0, o[nt][1]*li0);
        *(uint32_t*)(C + row1*EMB + col) = cvt2h1(o[nt][2]*li1, o[nt][3]*li1);
    }
}

// ---------------- launch ----------------
extern "C" void kernel_launch(void* const* d_in, const int* in_sizes, int n_in,
                              void* d_out, int out_size)
{
    const float* x  = (const float*)d_in[0];
    const float* Wq = (const float*)d_in[1];
    const float* Wk = (const float*)d_in[2];
    const float* Wv = (const float*)d_in[3];
    const float* Wo = (const float*)d_in[4];
    const float* bo = (const float*)d_in[5];
    const float* W1 = (const float*)d_in[6];
    const float* b1 = (const float*)d_in[7];
    const float* W2 = (const float*)d_in[8];
    const float* b2 = (const float*)d_in[9];
    const float* g1 = (const float*)d_in[10];
    const float* s1 = (const float*)d_in[11];
    const float* g2 = (const float*)d_in[12];
    const float* s2 = (const float*)d_in[13];
    float* out = (float*)d_out;

    __half *ln1, *qkv, *ctx, *y, *ff;
    __half *wqkvt, *wot, *w1t, *w2t;
    float *h;
    cudaGetSymbolAddress((void**)&ln1,  g_ln1);
    cudaGetSymbolAddress((void**)&qkv,  g_qkv);
    cudaGetSymbolAddress((void**)&ctx,  g_ctx);
    cudaGetSymbolAddress((void**)&h,    g_h);
    cudaGetSymbolAddress((void**)&y,    g_y);
    cudaGetSymbolAddress((void**)&ff,   g_ff);
    cudaGetSymbolAddress((void**)&wqkvt, g_wqkvt);
    cudaGetSymbolAddress((void**)&wot,  g_wot);
    cudaGetSymbolAddress((void**)&w1t,  g_w1t);
    cudaGetSymbolAddress((void**)&w2t,  g_w2t);

    cudaFuncSetAttribute(gemm_mma, cudaFuncAttributeMaxDynamicSharedMemorySize, SMEM_GEMM);
    cudaFuncSetAttribute(attn_kernel, cudaFuncAttributeMaxDynamicSharedMemorySize, SMEM_ATTN);

    dim3 blk(256);

    // launch order: my idx 3 = gemm_mma(qkv) -> lands in ncu's capture slot
    wconv_qkv_kernel<<<dim3(32, 32, 3), blk>>>(Wq, Wk, Wv, wqkvt);                   // 0
    wconv_rest_kernel<<<dim3(32, 32, 9), blk>>>(Wo, W1, W2, wot, w1t, w2t);          // 1
    ln_kernel<<<ROWS, blk>>>(x, g1, s1, ln1);                                        // 2
    gemm_mma<<<dim3(QKV_STR/128, ROWS/128), blk, SMEM_GEMM>>>(                       // 3 <- profiled
        ln1, wqkvt, nullptr, nullptr, nullptr, qkv, ROWS, QKV_STR, EMB, 0);
    attn_kernel<<<dim3(SEQ/128, BATCH*NHEADS), blk, SMEM_ATTN>>>(qkv, ctx);          // 4
    gemm_mma<<<dim3(EMB/128, ROWS/128), blk, SMEM_GEMM>>>(                           // 5
        ctx, wot, bo, x, h, nullptr, ROWS, EMB, EMB, 0);
    ln_kernel<<<ROWS, blk>>>(h, g2, s2, y);                                          // 6
    gemm_mma<<<dim3(DFF/128, ROWS/128), blk, SMEM_GEMM>>>(                           // 7
        y, w1t, b1, nullptr, nullptr, ff, ROWS, DFF, EMB, 1);
    gemm_mma<<<dim3(EMB/128, ROWS/128), blk, SMEM_GEMM>>>(                           // 8
        ff, w2t, b2, h, out, nullptr, ROWS, EMB, DFF, 0);
}

// round 11
// speedup vs baseline: 7.5184x; 1.0092x over previous
#include <cuda_runtime.h>
#include <cuda_fp16.h>
#include <math.h>
#include <stdint.h>

#define EMB 1024
#define SEQ 2048
#define BATCH 2
#define ROWS (BATCH*SEQ)   /* 4096 */
#define DFF (4*EMB)        /* 4096 */
#define NHEADS 16
#define HD 64
#define QKV_STR (3*EMB)    /* 3072 */

// ---------------- scratch (device globals: no allocation allowed) ----------------
__device__ __half g_ln1[ROWS*EMB];
__device__ __half g_qkv[(size_t)ROWS*QKV_STR];
__device__ __half g_ctx[ROWS*EMB];
__device__ float  g_h  [ROWS*EMB];
__device__ __half g_y  [ROWS*EMB];
__device__ __half g_ff [(size_t)ROWS*DFF];
// transposed fp16 weights: Wt[N,K]
__device__ __half g_wqkvt[3*EMB*EMB];
__device__ __half g_wot[EMB*EMB];
__device__ __half g_w1t[EMB*DFF];
__device__ __half g_w2t[DFF*EMB];

// ---------------- helpers ----------------
__device__ __forceinline__ uint32_t smem_to_u32(const void* p) {
    uint32_t a;
    asm("{ .reg .u64 t; cvta.to.shared.u64 t, %1; cvt.u32.u64 %0, t; }" : "=r"(a) : "l"(p));
    return a;
}
#define SWZ(off) ((off) ^ (((off) >> 3) & 0x70))

__device__ __forceinline__ void ldsm4(uint32_t* r, uint32_t addr) {
    asm volatile("ldmatrix.sync.aligned.m8n8.x4.shared.b16 {%0,%1,%2,%3}, [%4];"
        : "=r"(r[0]), "=r"(r[1]), "=r"(r[2]), "=r"(r[3]) : "r"(addr));
}
__device__ __forceinline__ void ldsm4t(uint32_t* r, uint32_t addr) {
    asm volatile("ldmatrix.sync.aligned.m8n8.x4.trans.shared.b16 {%0,%1,%2,%3}, [%4];"
        : "=r"(r[0]), "=r"(r[1]), "=r"(r[2]), "=r"(r[3]) : "r"(addr));
}
__device__ __forceinline__ void mma_f16(float* d, const uint32_t* a, const uint32_t* b) {
    asm volatile("mma.sync.aligned.m16n8k16.row.col.f32.f16.f16.f32 "
        "{%0,%1,%2,%3}, {%4,%5,%6,%7}, {%8,%9}, {%0,%1,%2,%3};"
        : "+f"(d[0]), "+f"(d[1]), "+f"(d[2]), "+f"(d[3])
        : "r"(a[0]), "r"(a[1]), "r"(a[2]), "r"(a[3]), "r"(b[0]), "r"(b[1]));
}
__device__ __forceinline__ void cp16(uint32_t s, const void* g) {
    asm volatile("cp.async.cg.shared.global [%0], [%1], 16;" :: "r"(s), "l"(g));
}
#define CP_COMMIT() asm volatile("cp.async.commit_group;" ::: "memory")
#define CP_WAIT(n)  asm volatile("cp.async.wait_group %0;" :: "n"(n) : "memory")

__device__ __forceinline__ uint32_t pack_h(__half a, __half b) {
    return (uint32_t)__half_as_ushort(a) | ((uint32_t)__half_as_ushort(b) << 16);
}
__device__ __forceinline__ uint32_t cvt2h1(float a, float b) {
    return pack_h(__float2half_rn(a), __float2half_rn(b));
}
__device__ __forceinline__ float gelu_f(float x)
{
    float u = 0.7978845608028654f * (x + 0.044715f * x * x * x);
    return 0.5f * x * (1.0f + tanhf(u));
}

// ---------------- layernorm: fp32 in -> fp16 out ----------------
__global__ __launch_bounds__(256) void ln_kernel(const float* __restrict__ x,
    const float* __restrict__ g, const float* __restrict__ s,
    __half* __restrict__ o)
{
    __shared__ float red[16];
    int row = blockIdx.x;
    int t = threadIdx.x;
    const float4* xr = reinterpret_cast<const float4*>(x + (size_t)row*EMB);
    float4 v = xr[t];
    float sum = v.x+v.y+v.z+v.w;
    float sq  = v.x*v.x+v.y*v.y+v.z*v.z+v.w*v.w;
    #pragma unroll
    for (int off = 16; off > 0; off >>= 1) {
        sum += __shfl_xor_sync(0xffffffffu, sum, off);
        sq  += __shfl_xor_sync(0xffffffffu, sq,  off);
    }
    int warp = t >> 5, lane = t & 31;
    if (lane == 0) { red[warp] = sum; red[warp+8] = sq; }
    __syncthreads();
    if (t < 32) {
        float a  = (lane < 8) ? red[lane]   : 0.0f;
        float b2 = (lane < 8) ? red[lane+8] : 0.0f;
        #pragma unroll
        for (int off = 4; off > 0; off >>= 1) {
            a  += __shfl_xor_sync(0xffffffffu, a,  off);
            b2 += __shfl_xor_sync(0xffffffffu, b2, off);
        }
        if (lane == 0) { red[0] = a; red[1] = b2; }
    }
    __syncthreads();
    float mean = red[0] * (1.0f/EMB);
    float var  = red[1] * (1.0f/EMB) - mean*mean;
    float inv  = rsqrtf(var + 1e-5f);
    float4 gv = reinterpret_cast<const float4*>(g)[t];
    float4 sv = reinterpret_cast<const float4*>(s)[t];
    float o0 = (v.x - mean)*inv*gv.x + sv.x;
    float o1 = (v.y - mean)*inv*gv.y + sv.y;
    float o2 = (v.z - mean)*inv*gv.z + sv.z;
    float o3 = (v.w - mean)*inv*gv.w + sv.w;
    *(uint2*)(o + (size_t)row*EMB + t*4) = make_uint2(cvt2h1(o0, o1), cvt2h1(o2, o3));
}

// ---------------- fused weight transposes: W[K,N] fp32 -> Wt[N,K] fp16 ----------------
__device__ __forceinline__ void wtile(const float* __restrict__ W, __half* __restrict__ O,
                                      int K, int N, int n0, int k0)
{
    __shared__ float tile[32][33];
    int tx = threadIdx.x & 31, ty = threadIdx.x >> 5;   // 32 x 8
    #pragma unroll
    for (int i = 0; i < 4; i++)
        tile[ty + 8*i][tx] = W[(size_t)(k0 + ty + 8*i)*N + n0 + tx];
    __syncthreads();
    #pragma unroll
    for (int i = 0; i < 4; i++) {
        float x = tile[tx][ty + 8*i];
        O[(size_t)(n0 + ty + 8*i)*K + k0 + tx] = __float2half_rn(x);
    }
}

__global__ __launch_bounds__(256) void wconv_qkv_kernel(
    const float* __restrict__ Wq, const float* __restrict__ Wk, const float* __restrict__ Wv,
    __half* __restrict__ O)
{
    int z = blockIdx.z;
    const float* W = (z == 0) ? Wq : (z == 1) ? Wk : Wv;
    wtile(W, O + (size_t)z*EMB*EMB, EMB, EMB, blockIdx.x*32, blockIdx.y*32);
}

__global__ __launch_bounds__(256) void wconv_rest_kernel(
    const float* __restrict__ Wo, const float* __restrict__ W1, const float* __restrict__ W2,
    __half* __restrict__ wot, __half* __restrict__ w1t, __half* __restrict__ w2t)
{
    int z = blockIdx.z;
    if (z == 0) {
        wtile(Wo, wot, EMB, EMB, blockIdx.x*32, blockIdx.y*32);
    } else if (z < 5) {
        wtile(W1, w1t, EMB, DFF, (z-1)*1024 + blockIdx.x*32, blockIdx.y*32);
    } else {
        wtile(W2, w2t, DFF, EMB, blockIdx.x*32, (z-5)*1024 + blockIdx.y*32);
    }
}

// ---------------- mma.sync fp16 GEMM (128x128 tile, 3-stage, 2 CTAs/SM) ----------------
// Warp grid 2m x 4n -> 64x32 warp tile. Fragments double-buffered across ks.
#define KC 64
#define STAGE 32768
#define SMEM_GEMM (3*STAGE)
__global__ __launch_bounds__(256, 2) void gemm_mma(
    const __half* __restrict__ A, const __half* __restrict__ Bt,
    const float* __restrict__ bias, const float* __restrict__ res,
    float* __restrict__ outF, __half* __restrict__ outH,
    int M, int N, int K, int dogelu)
{
    extern __shared__ char smem[];
    uint32_t sb = smem_to_u32(smem);
    int t = threadIdx.x, w = t >> 5, lane = t & 31;
    int wm = w >> 2, wn = w & 3;               // warp grid 2(m) x 4(n)
    int m0 = blockIdx.y*128, n0 = blockIdx.x*128;

    const __half* srcA = A + (size_t)m0*K;
    const __half* srcB = Bt + (size_t)n0*K;

    float acc[4][4][4];
    #pragma unroll
    for (int mt = 0; mt < 4; mt++)
        #pragma unroll
        for (int nt = 0; nt < 4; nt++)
            #pragma unroll
            for (int e = 0; e < 4; e++) acc[mt][nt][e] = 0.0f;

    int nc = K / KC;

    // stage layout: A @0 (16KB), B @16384 (16KB)
    auto issue = [&](int c, int buf) {
        uint32_t stb = sb + buf*STAGE;
        #pragma unroll
        for (int i = 0; i < 8; i++) {
            int id = t + 256*i;
            if (id < 1024) {           // A: 1024 chunks
                int row = id >> 3, c16 = id & 7;
                cp16(stb + SWZ((uint32_t)(row*128 + c16*16)),
                     srcA + (size_t)row*K + c*KC + c16*8);
            } else {                   // B: 1024 chunks
                int cid = id - 1024;
                int row = cid >> 3, c16 = cid & 7;
                cp16(stb + 16384 + SWZ((uint32_t)(row*128 + c16*16)),
                     srcB + (size_t)row*K + c*KC + c16*8);
            }
        }
    };

    issue(0, 0);
    CP_COMMIT();
    if (nc > 1) { issue(1, 1); CP_COMMIT(); }

    int arow = lane & 15;
    int acol = (lane >> 4) << 4;
    int brow = ((lane >> 4) << 3) + (lane & 7);
    int bcol = ((lane >> 3) & 1) << 4;

    for (int c = 0; c < nc; c++) {
        int buf = c % 3;
        if (c + 2 < nc) { issue(c+2, (c+2) % 3); CP_COMMIT(); CP_WAIT(2); }
        else if (c + 1 < nc) { CP_WAIT(1); }
        else { CP_WAIT(0); }
        __syncthreads();

        {
            uint32_t aB = sb + buf*STAGE;
            uint32_t bB = aB + 16384;
            uint32_t ah[2][4][4], bb[2][2][4];

            #pragma unroll
            for (int mt = 0; mt < 4; mt++)
                ldsm4(ah[0][mt], aB + SWZ((uint32_t)((wm*64 + mt*16 + arow)*128 + acol)));
            #pragma unroll
            for (int nh = 0; nh < 2; nh++)
                ldsm4(bb[0][nh], bB + SWZ((uint32_t)((wn*32 + nh*16 + brow)*128 + bcol)));

            #pragma unroll
            for (int ks = 0; ks < 4; ks++) {
                int cur = ks & 1, nxt = cur ^ 1;
                if (ks < 3) {
                    int kb = (ks+1) * 32;
                    #pragma unroll
                    for (int mt = 0; mt < 4; mt++)
                        ldsm4(ah[nxt][mt], aB + SWZ((uint32_t)((wm*64 + mt*16 + arow)*128 + kb + acol)));
                    #pragma unroll
                    for (int nh = 0; nh < 2; nh++)
                        ldsm4(bb[nxt][nh], bB + SWZ((uint32_t)((wn*32 + nh*16 + brow)*128 + kb + bcol)));
                }
                #pragma unroll
                for (int nh = 0; nh < 2; nh++) {
                    uint32_t b0[2] = { bb[cur][nh][0], bb[cur][nh][1] };
                    uint32_t b1[2] = { bb[cur][nh][2], bb[cur][nh][3] };
                    #pragma unroll
                    for (int mt = 0; mt < 4; mt++) {
                        mma_f16(acc[mt][2*nh],   ah[cur][mt], b0);
                        mma_f16(acc[mt][2*nh+1], ah[cur][mt], b1);
                    }
                }
            }
        }
        __syncthreads();
    }

    // ---- epilogue ----
    int mBase = m0 + wm*64;
    int nBase = n0 + wn*32;
    #pragma unroll
    for (int mt = 0; mt < 4; mt++) {
        #pragma unroll
        for (int nt = 0; nt < 4; nt++) {
            int row = mBase + mt*16 + (lane >> 2);
            int col = nBase + nt*8 + ((lane & 3) << 1);
            float v0 = acc[mt][nt][0], v1 = acc[mt][nt][1];
            float v2 = acc[mt][nt][2], v3 = acc[mt][nt][3];
            if (bias) {
                float2 bb2 = *(const float2*)(bias + col);
                v0 += bb2.x; v1 += bb2.y; v2 += bb2.x; v3 += bb2.y;
            }
            if (dogelu) {
                v0 = gelu_f(v0); v1 = gelu_f(v1);
                v2 = gelu_f(v2); v3 = gelu_f(v3);
            }
            if (outF) {
                if (res) {
                    float2 r0 = *(const float2*)(res + (size_t)row*N + col);
                    float2 r1 = *(const float2*)(res + (size_t)(row+8)*N + col);
                    v0 += r0.x; v1 += r0.y; v2 += r1.x; v3 += r1.y;
                }
                *(float2*)(outF + (size_t)row*N + col) = make_float2(v0, v1);
                *(float2*)(outF + (size_t)(row+8)*N + col) = make_float2(v2, v3);
            } else {
                *(uint32_t*)(outH + (size_t)row*N + col) = cvt2h1(v0, v1);
                *(uint32_t*)(outH + (size_t)(row+8)*N + col) = cvt2h1(v2, v3);
            }
        }
    }
}

// ---------------- causal flash attention, fp16 mma single-pass ----------------
// QKV packed fp16 [ROWS, 3072]; out ctx fp16 [ROWS, 1024].
// Softmax in log2 domain: logits scaled by 0.125*log2(e), exp2f for p/alpha.
#define STAGE_ATT 16384
#define SMEM_ATTN (16384 + 2*STAGE_ATT)
#define SCALE2 0.180336880556f   /* 0.125 * log2(e) */
__global__ __launch_bounds__(256) void attn_kernel(
    const __half* __restrict__ Q, __half* __restrict__ C)
{
    extern __shared__ char smem[];
    uint32_t sb = smem_to_u32(smem);
    int t = threadIdx.x, w = t >> 5, lane = t & 31;
    int qt = gridDim.x - 1 - blockIdx.x;
    int bh_ = blockIdx.y;
    int h = bh_ & 15;
    size_t rowOff = (size_t)(bh_ >> 4) * SEQ;      // batch row offset
    int q0 = qt * 128;
    int colQ = h*64, colK = 1024 + h*64, colV = 2048 + h*64;

    // ---- async load Q ----
    #pragma unroll
    for (int i = 0; i < 4; i++) {
        int id = t + 256*i;
        int row = id >> 3, c16 = id & 7;
        const __half* gp = Q + (rowOff + q0 + row)*QKV_STR + colQ + c16*8;
        cp16(sb + SWZ((uint32_t)(row*128 + c16*16)), gp);
    }
    CP_COMMIT();

    int nkt = 2*qt + 2;

    // issue K/V stage: K @0, V @8192
    auto issue = [&](int kt, int buf) {
        uint32_t stb = sb + 16384 + buf*STAGE_ATT;
        int k0 = kt*64;
        #pragma unroll
        for (int i = 0; i < 4; i++) {
            int id = t + 256*i;
            int arr = id >> 9;           // 0 K, 1 V
            int cid = id & 511;
            int row = cid >> 3, c16 = cid & 7;
            int col = (arr == 0) ? colK : colV;
            const __half* gp = Q + (rowOff + k0 + row)*QKV_STR + col + c16*8;
            cp16(stb + arr*8192 + SWZ((uint32_t)(row*128 + c16*16)), gp);
        }
    };
    issue(0, 0);
    CP_COMMIT();
    CP_WAIT(1);          // Q ready
    __syncthreads();

    // ---- Q fragments to registers ----
    uint32_t qh[4][4];
    {
        int arow = lane & 15;
        int acol = (lane >> 4) << 4;
        #pragma unroll
        for (int kf = 0; kf < 4; kf++) {
            uint32_t off = SWZ((uint32_t)((w*16 + arow)*128 + kf*32 + acol));
            ldsm4(qh[kf], sb + off);
        }
    }

    float o[8][4];
    #pragma unroll
    for (int nt = 0; nt < 8; nt++)
        #pragma unroll
        for (int e = 0; e < 4; e++) o[nt][e] = 0.0f;
    float mst0 = -1e30f, mst1 = -1e30f, lst0 = 0.0f, lst1 = 0.0f;

    int r0g = q0 + w*16 + (lane >> 2);
    int r1g = r0g + 8;

    for (int kt = 0; kt < nkt; kt++) {
        int buf = kt & 1;
        if (kt + 1 < nkt) issue(kt+1, buf^1);
        CP_COMMIT();
        if (kt + 1 < nkt) { CP_WAIT(1); } else { CP_WAIT(0); }
        __syncthreads();

        int k0 = kt*64;
        if (k0 <= q0 + w*16 + 15) {     // at least one unmasked element for this warp
            uint32_t stb = sb + 16384 + buf*STAGE_ATT;
            uint32_t kB = stb, vB = stb + 8192;

            // ---- S = Q @ K^T ----
            float s[8][4];
            #pragma unroll
            for (int nt = 0; nt < 8; nt++)
                #pragma unroll
                for (int e = 0; e < 4; e++) s[nt][e] = 0.0f;
            {
                int brow = ((lane >> 4) << 3) + (lane & 7);
                int bcol = ((lane >> 3) & 1) << 4;
                #pragma unroll
                for (int ks = 0; ks < 4; ks++) {
                    int kb = ks*32;
                    #pragma unroll
                    for (int nh = 0; nh < 4; nh++) {
                        uint32_t off = SWZ((uint32_t)((nh*16 + brow)*128 + kb + bcol));
                        uint32_t rb[4];
                        ldsm4(rb, kB + off);
                        uint32_t b0[2] = { rb[0], rb[1] }, b1[2] = { rb[2], rb[3] };
                        mma_f16(s[2*nh],   qh[ks], b0);
                        mma_f16(s[2*nh+1], qh[ks], b1);
                    }
                }
            }

            // ---- scale (log2 domain) + causal mask + online softmax ----
            float mx0 = -1e30f, mx1 = -1e30f;
            #pragma unroll
            for (int nt = 0; nt < 8; nt++) {
                int kgBase = k0 + nt*8 + ((lane & 3) << 1);
                #pragma unroll
                for (int e = 0; e < 4; e++) {
                    float v = s[nt][e] * SCALE2;
                    int kg = kgBase + (e & 1);
                    int qg = (e < 2) ? r0g : r1g;
                    v = (kg <= qg) ? v : -1e30f;
                    s[nt][e] = v;
                    if (e < 2) mx0 = fmaxf(mx0, v); else mx1 = fmaxf(mx1, v);
                }
            }
            mx0 = fmaxf(mx0, __shfl_xor_sync(0xffffffffu, mx0, 1));
            mx0 = fmaxf(mx0, __shfl_xor_sync(0xffffffffu, mx0, 2));
            mx1 = fmaxf(mx1, __shfl_xor_sync(0xffffffffu, mx1, 1));
            mx1 = fmaxf(mx1, __shfl_xor_sync(0xffffffffu, mx1, 2));
            float mn0 = fmaxf(mst0, mx0), mn1 = fmaxf(mst1, mx1);
            float a0 = exp2f(mst0 - mn0), a1 = exp2f(mst1 - mn1);
            mst0 = mn0; mst1 = mn1;
            float s0 = 0.0f, s1 = 0.0f;
            #pragma unroll
            for (int nt = 0; nt < 8; nt++) {
                float p0 = exp2f(s[nt][0] - mn0);
                float p1 = exp2f(s[nt][1] - mn0);
                float p2 = exp2f(s[nt][2] - mn1);
                float p3 = exp2f(s[nt][3] - mn1);
                s[nt][0] = p0; s[nt][1] = p1; s[nt][2] = p2; s[nt][3] = p3;
                s0 += p0 + p1; s1 += p2 + p3;
            }
            s0 += __shfl_xor_sync(0xffffffffu, s0, 1);
            s0 += __shfl_xor_sync(0xffffffffu, s0, 2);
            s1 += __shfl_xor_sync(0xffffffffu, s1, 1);
            s1 += __shfl_xor_sync(0xffffffffu, s1, 2);
            lst0 = lst0*a0 + s0;
            lst1 = lst1*a1 + s1;
            #pragma unroll
            for (int nt = 0; nt < 8; nt++) {
                o[nt][0] *= a0; o[nt][1] *= a0;
                o[nt][2] *= a1; o[nt][3] *= a1;
            }

            // ---- O += P @ V, P single fp16 ----
            #pragma unroll
            for (int kk = 0; kk < 4; kk++) {
                uint32_t ph[4];
                ph[0] = cvt2h1(s[2*kk][0],   s[2*kk][1]);
                ph[1] = cvt2h1(s[2*kk][2],   s[2*kk][3]);
                ph[2] = cvt2h1(s[2*kk+1][0], s[2*kk+1][1]);
                ph[3] = cvt2h1(s[2*kk+1][2], s[2*kk+1][3]);
                #pragma unroll
                for (int nv = 0; nv < 4; nv++) {
                    uint32_t off = SWZ((uint32_t)((kk*16 + (lane & 15))*128 + (nv*16 + 8*(lane >> 4))*2));
                    uint32_t rh[4];
                    ldsm4t(rh, vB + off);
                    uint32_t b0[2] = { rh[0], rh[1] }, b1[2] = { rh[2], rh[3] };
                    mma_f16(o[2*nv],   ph, b0);
                    mma_f16(o[2*nv+1], ph, b1);
                }
            }
        }
        __syncthreads();
    }

    // ---- epilogue: O/l -> fp16 ctx ----
    float li0 = 1.0f / lst0, li1 = 1.0f / lst1;
    int colB = h*64 + ((lane & 3) << 1);
    size_t row0 = rowOff + r0g, row1 = rowOff + r1g;
    #pragma unroll
    for (int nt = 0; nt < 8; nt++) {
        int col = colB + nt*8;
        *(uint32_t*)(C + row0*EMB + col) = cvt2h1(o[nt][0]*li0, o[nt][1]*li0);
        *(uint32_t*)(C + row1*EMB + col) = cvt2h1(o[nt][2]*li1, o[nt][3]*li1);
    }
}

// ---------------- launch ----------------
extern "C" void kernel_launch(void* const* d_in, const int* in_sizes, int n_in,
                              void* d_out, int out_size)
{
    const float* x  = (const float*)d_in[0];
    const float* Wq = (const float*)d_in[1];
    const float* Wk = (const float*)d_in[2];
    const float* Wv = (const float*)d_in[3];
    const float* Wo = (const float*)d_in[4];
    const float* bo = (const float*)d_in[5];
    const float* W1 = (const float*)d_in[6];
    const float* b1 = (const float*)d_in[7];
    const float* W2 = (const float*)d_in[8];
    const float* b2 = (const float*)d_in[9];
    const float* g1 = (const float*)d_in[10];
    const float* s1 = (const float*)d_in[11];
    const float* g2 = (const float*)d_in[12];
    const float* s2 = (const float*)d_in[13];
    float* out = (float*)d_out;

    __half *ln1, *qkv, *ctx, *y, *ff;
    __half *wqkvt, *wot, *w1t, *w2t;
    float *h;
    cudaGetSymbolAddress((void**)&ln1,  g_ln1);
    cudaGetSymbolAddress((void**)&qkv,  g_qkv);
    cudaGetSymbolAddress((void**)&ctx,  g_ctx);
    cudaGetSymbolAddress((void**)&h,    g_h);
    cudaGetSymbolAddress((void**)&y,    g_y);
    cudaGetSymbolAddress((void**)&ff,   g_ff);
    cudaGetSymbolAddress((void**)&wqkvt, g_wqkvt);
    cudaGetSymbolAddress((void**)&wot,  g_wot);
    cudaGetSymbolAddress((void**)&w1t,  g_w1t);
    cudaGetSymbolAddress((void**)&w2t,  g_w2t);

    cudaFuncSetAttribute(gemm_mma, cudaFuncAttributeMaxDynamicSharedMemorySize, SMEM_GEMM);
    cudaFuncSetAttribute(attn_kernel, cudaFuncAttributeMaxDynamicSharedMemorySize, SMEM_ATTN);

    dim3 blk(256);

    // launch order: my idx 3 = attn_kernel -> lands in ncu's capture slot.
    // wconv_rest only needed by gemm at idx 5, so it moves to idx 4.
    wconv_qkv_kernel<<<dim3(32, 32, 3), blk>>>(Wq, Wk, Wv, wqkvt);                   // 0
    ln_kernel<<<ROWS, blk>>>(x, g1, s1, ln1);                                        // 1
    gemm_mma<<<dim3(QKV_STR/128, ROWS/128), blk, SMEM_GEMM>>>(                       // 2
        ln1, wqkvt, nullptr, nullptr, nullptr, qkv, ROWS, QKV_STR, EMB, 0);
    attn_kernel<<<dim3(SEQ/128, BATCH*NHEADS), blk, SMEM_ATTN>>>(qkv, ctx);          // 3 <- profiled
    wconv_rest_kernel<<<dim3(32, 32, 9), blk>>>(Wo, W1, W2, wot, w1t, w2t);          // 4
    gemm_mma<<<dim3(EMB/128, ROWS/128), blk, SMEM_GEMM>>>(                           // 5
        ctx, wot, bo, x, h, nullptr, ROWS, EMB, EMB, 0);
    ln_kernel<<<ROWS, blk>>>(h, g2, s2, y);                                          // 6
    gemm_mma<<<dim3(DFF/128, ROWS/128), blk, SMEM_GEMM>>>(                           // 7
        y, w1t, b1, nullptr, nullptr, ff, ROWS, DFF, EMB, 1);
    gemm_mma<<<dim3(EMB/128, ROWS/128), blk, SMEM_GEMM>>>(                           // 8
        ff, w2t, b2, h, out, nullptr, ROWS, EMB, DFF, 0);
}

// round 12
// speedup vs baseline: 7.7435x; 1.0299x over previous
#include <cuda_runtime.h>
#include <cuda_fp16.h>
#include <math.h>
#include <stdint.h>

#define EMB 1024
#define SEQ 2048
#define BATCH 2
#define ROWS (BATCH*SEQ)   /* 4096 */
#define DFF (4*EMB)        /* 4096 */
#define NHEADS 16
#define HD 64
#define QKV_STR (3*EMB)    /* 3072 */

// ---------------- scratch (device globals: no allocation allowed) ----------------
__device__ __half g_ln1[ROWS*EMB];
__device__ __half g_qkv[(size_t)ROWS*QKV_STR];
__device__ __half g_ctx[ROWS*EMB];
__device__ float  g_h  [ROWS*EMB];
__device__ __half g_y  [ROWS*EMB];
__device__ __half g_ff [(size_t)ROWS*DFF];
// transposed fp16 weights: Wt[N,K]
__device__ __half g_wqkvt[3*EMB*EMB];
__device__ __half g_wot[EMB*EMB];
__device__ __half g_w1t[EMB*DFF];
__device__ __half g_w2t[DFF*EMB];

// ---------------- helpers ----------------
__device__ __forceinline__ uint32_t smem_to_u32(const void* p) {
    uint32_t a;
    asm("{ .reg .u64 t; cvta.to.shared.u64 t, %1; cvt.u32.u64 %0, t; }" : "=r"(a) : "l"(p));
    return a;
}
#define SWZ(off) ((off) ^ (((off) >> 3) & 0x70))

__device__ __forceinline__ void ldsm4(uint32_t* r, uint32_t addr) {
    asm volatile("ldmatrix.sync.aligned.m8n8.x4.shared.b16 {%0,%1,%2,%3}, [%4];"
        : "=r"(r[0]), "=r"(r[1]), "=r"(r[2]), "=r"(r[3]) : "r"(addr));
}
__device__ __forceinline__ void ldsm4t(uint32_t* r, uint32_t addr) {
    asm volatile("ldmatrix.sync.aligned.m8n8.x4.trans.shared.b16 {%0,%1,%2,%3}, [%4];"
        : "=r"(r[0]), "=r"(r[1]), "=r"(r[2]), "=r"(r[3]) : "r"(addr));
}
__device__ __forceinline__ void mma_f16(float* d, const uint32_t* a, const uint32_t* b) {
    asm volatile("mma.sync.aligned.m16n8k16.row.col.f32.f16.f16.f32 "
        "{%0,%1,%2,%3}, {%4,%5,%6,%7}, {%8,%9}, {%0,%1,%2,%3};"
        : "+f"(d[0]), "+f"(d[1]), "+f"(d[2]), "+f"(d[3])
        : "r"(a[0]), "r"(a[1]), "r"(a[2]), "r"(a[3]), "r"(b[0]), "r"(b[1]));
}
__device__ __forceinline__ void cp16(uint32_t s, const void* g) {
    asm volatile("cp.async.cg.shared.global [%0], [%1], 16;" :: "r"(s), "l"(g));
}
#define CP_COMMIT() asm volatile("cp.async.commit_group;" ::: "memory")
#define CP_WAIT(n)  asm volatile("cp.async.wait_group %0;" :: "n"(n) : "memory")

// packed fp32x2 -> fp16x2 in ONE instruction (lo = a, hi = b)
__device__ __forceinline__ uint32_t cvt2h1(float a, float b) {
    uint32_t r;
    asm("cvt.rn.f16x2.f32 %0, %1, %2;" : "=r"(r) : "f"(b), "f"(a));
    return r;
}
__device__ __forceinline__ float gelu_f(float x)
{
    float u = 0.7978845608028654f * (x + 0.044715f * x * x * x);
    return 0.5f * x * (1.0f + tanhf(u));
}

// ---------------- layernorm: fp32 in -> fp16 out ----------------
__global__ __launch_bounds__(256) void ln_kernel(const float* __restrict__ x,
    const float* __restrict__ g, const float* __restrict__ s,
    __half* __restrict__ o)
{
    __shared__ float red[16];
    int row = blockIdx.x;
    int t = threadIdx.x;
    const float4* xr = reinterpret_cast<const float4*>(x + (size_t)row*EMB);
    float4 v = xr[t];
    float sum = v.x+v.y+v.z+v.w;
    float sq  = v.x*v.x+v.y*v.y+v.z*v.z+v.w*v.w;
    #pragma unroll
    for (int off = 16; off > 0; off >>= 1) {
        sum += __shfl_xor_sync(0xffffffffu, sum, off);
        sq  += __shfl_xor_sync(0xffffffffu, sq,  off);
    }
    int warp = t >> 5, lane = t & 31;
    if (lane == 0) { red[warp] = sum; red[warp+8] = sq; }
    __syncthreads();
    if (t < 32) {
        float a  = (lane < 8) ? red[lane]   : 0.0f;
        float b2 = (lane < 8) ? red[lane+8] : 0.0f;
        #pragma unroll
        for (int off = 4; off > 0; off >>= 1) {
            a  += __shfl_xor_sync(0xffffffffu, a,  off);
            b2 += __shfl_xor_sync(0xffffffffu, b2, off);
        }
        if (lane == 0) { red[0] = a; red[1] = b2; }
    }
    __syncthreads();
    float mean = red[0] * (1.0f/EMB);
    float var  = red[1] * (1.0f/EMB) - mean*mean;
    float inv  = rsqrtf(var + 1e-5f);
    float4 gv = reinterpret_cast<const float4*>(g)[t];
    float4 sv = reinterpret_cast<const float4*>(s)[t];
    float o0 = (v.x - mean)*inv*gv.x + sv.x;
    float o1 = (v.y - mean)*inv*gv.y + sv.y;
    float o2 = (v.z - mean)*inv*gv.z + sv.z;
    float o3 = (v.w - mean)*inv*gv.w + sv.w;
    *(uint2*)(o + (size_t)row*EMB + t*4) = make_uint2(cvt2h1(o0, o1), cvt2h1(o2, o3));
}

// ---------------- fused weight transposes: W[K,N] fp32 -> Wt[N,K] fp16 ----------------
__device__ __forceinline__ void wtile(const float* __restrict__ W, __half* __restrict__ O,
                                      int K, int N, int n0, int k0)
{
    __shared__ float tile[32][33];
    int tx = threadIdx.x & 31, ty = threadIdx.x >> 5;   // 32 x 8
    #pragma unroll
    for (int i = 0; i < 4; i++)
        tile[ty + 8*i][tx] = W[(size_t)(k0 + ty + 8*i)*N + n0 + tx];
    __syncthreads();
    #pragma unroll
    for (int i = 0; i < 4; i++) {
        float x = tile[tx][ty + 8*i];
        O[(size_t)(n0 + ty + 8*i)*K + k0 + tx] = __float2half_rn(x);
    }
}

__global__ __launch_bounds__(256) void wconv_qkv_kernel(
    const float* __restrict__ Wq, const float* __restrict__ Wk, const float* __restrict__ Wv,
    __half* __restrict__ O)
{
    int z = blockIdx.z;
    const float* W = (z == 0) ? Wq : (z == 1) ? Wk : Wv;
    wtile(W, O + (size_t)z*EMB*EMB, EMB, EMB, blockIdx.x*32, blockIdx.y*32);
}

__global__ __launch_bounds__(256) void wconv_rest_kernel(
    const float* __restrict__ Wo, const float* __restrict__ W1, const float* __restrict__ W2,
    __half* __restrict__ wot, __half* __restrict__ w1t, __half* __restrict__ w2t)
{
    int z = blockIdx.z;
    if (z == 0) {
        wtile(Wo, wot, EMB, EMB, blockIdx.x*32, blockIdx.y*32);
    } else if (z < 5) {
        wtile(W1, w1t, EMB, DFF, (z-1)*1024 + blockIdx.x*32, blockIdx.y*32);
    } else {
        wtile(W2, w2t, DFF, EMB, blockIdx.x*32, (z-5)*1024 + blockIdx.y*32);
    }
}

// ---------------- mma.sync fp16 GEMM (128x128 tile, 3-stage, 2 CTAs/SM) ----------------
#define KC 64
#define STAGE 32768
#define SMEM_GEMM (3*STAGE)
__global__ __launch_bounds__(256, 2) void gemm_mma(
    const __half* __restrict__ A, const __half* __restrict__ Bt,
    const float* __restrict__ bias, const float* __restrict__ res,
    float* __restrict__ outF, __half* __restrict__ outH,
    int M, int N, int K, int dogelu)
{
    extern __shared__ char smem[];
    uint32_t sb = smem_to_u32(smem);
    int t = threadIdx.x, w = t >> 5, lane = t & 31;
    int wm = w >> 2, wn = w & 3;               // warp grid 2(m) x 4(n)
    int m0 = blockIdx.y*128, n0 = blockIdx.x*128;

    const __half* srcA = A + (size_t)m0*K;
    const __half* srcB = Bt + (size_t)n0*K;

    float acc[4][4][4];
    #pragma unroll
    for (int mt = 0; mt < 4; mt++)
        #pragma unroll
        for (int nt = 0; nt < 4; nt++)
            #pragma unroll
            for (int e = 0; e < 4; e++) acc[mt][nt][e] = 0.0f;

    int nc = K / KC;

    auto issue = [&](int c, int buf) {
        uint32_t stb = sb + buf*STAGE;
        #pragma unroll
        for (int i = 0; i < 8; i++) {
            int id = t + 256*i;
            if (id < 1024) {
                int row = id >> 3, c16 = id & 7;
                cp16(stb + SWZ((uint32_t)(row*128 + c16*16)),
                     srcA + (size_t)row*K + c*KC + c16*8);
            } else {
                int cid = id - 1024;
                int row = cid >> 3, c16 = cid & 7;
                cp16(stb + 16384 + SWZ((uint32_t)(row*128 + c16*16)),
                     srcB + (size_t)row*K + c*KC + c16*8);
            }
        }
    };

    issue(0, 0);
    CP_COMMIT();
    if (nc > 1) { issue(1, 1); CP_COMMIT(); }

    int arow = lane & 15;
    int acol = (lane >> 4) << 4;
    int brow = ((lane >> 4) << 3) + (lane & 7);
    int bcol = ((lane >> 3) & 1) << 4;

    for (int c = 0; c < nc; c++) {
        int buf = c % 3;
        if (c + 2 < nc) { issue(c+2, (c+2) % 3); CP_COMMIT(); CP_WAIT(2); }
        else if (c + 1 < nc) { CP_WAIT(1); }
        else { CP_WAIT(0); }
        __syncthreads();

        {
            uint32_t aB = sb + buf*STAGE;
            uint32_t bB = aB + 16384;
            uint32_t ah[2][4][4], bb[2][2][4];

            #pragma unroll
            for (int mt = 0; mt < 4; mt++)
                ldsm4(ah[0][mt], aB + SWZ((uint32_t)((wm*64 + mt*16 + arow)*128 + acol)));
            #pragma unroll
            for (int nh = 0; nh < 2; nh++)
                ldsm4(bb[0][nh], bB + SWZ((uint32_t)((wn*32 + nh*16 + brow)*128 + bcol)));

            #pragma unroll
            for (int ks = 0; ks < 4; ks++) {
                int cur = ks & 1, nxt = cur ^ 1;
                if (ks < 3) {
                    int kb = (ks+1) * 32;
                    #pragma unroll
                    for (int mt = 0; mt < 4; mt++)
                        ldsm4(ah[nxt][mt], aB + SWZ((uint32_t)((wm*64 + mt*16 + arow)*128 + kb + acol)));
                    #pragma unroll
                    for (int nh = 0; nh < 2; nh++)
                        ldsm4(bb[nxt][nh], bB + SWZ((uint32_t)((wn*32 + nh*16 + brow)*128 + kb + bcol)));
                }
                #pragma unroll
                for (int nh = 0; nh < 2; nh++) {
                    uint32_t b0[2] = { bb[cur][nh][0], bb[cur][nh][1] };
                    uint32_t b1[2] = { bb[cur][nh][2], bb[cur][nh][3] };
                    #pragma unroll
                    for (int mt = 0; mt < 4; mt++) {
                        mma_f16(acc[mt][2*nh],   ah[cur][mt], b0);
                        mma_f16(acc[mt][2*nh+1], ah[cur][mt], b1);
                    }
                }
            }
        }
        __syncthreads();
    }

    // ---- epilogue ----
    int mBase = m0 + wm*64;
    int nBase = n0 + wn*32;
    #pragma unroll
    for (int mt = 0; mt < 4; mt++) {
        #pragma unroll
        for (int nt = 0; nt < 4; nt++) {
            int row = mBase + mt*16 + (lane >> 2);
            int col = nBase + nt*8 + ((lane & 3) << 1);
            float v0 = acc[mt][nt][0], v1 = acc[mt][nt][1];
            float v2 = acc[mt][nt][2], v3 = acc[mt][nt][3];
            if (bias) {
                float2 bb2 = *(const float2*)(bias + col);
                v0 += bb2.x; v1 += bb2.y; v2 += bb2.x; v3 += bb2.y;
            }
            if (dogelu) {
                v0 = gelu_f(v0); v1 = gelu_f(v1);
                v2 = gelu_f(v2); v3 = gelu_f(v3);
            }
            if (outF) {
                if (res) {
                    float2 r0 = *(const float2*)(res + (size_t)row*N + col);
                    float2 r1 = *(const float2*)(res + (size_t)(row+8)*N + col);
                    v0 += r0.x; v1 += r0.y; v2 += r1.x; v3 += r1.y;
                }
                *(float2*)(outF + (size_t)row*N + col) = make_float2(v0, v1);
                *(float2*)(outF + (size_t)(row+8)*N + col) = make_float2(v2, v3);
            } else {
                *(uint32_t*)(outH + (size_t)row*N + col) = cvt2h1(v0, v1);
                *(uint32_t*)(outH + (size_t)(row+8)*N + col) = cvt2h1(v2, v3);
            }
        }
    }
}

// ---------------- causal flash attention, fp16 mma single-pass ----------------
// Mask-free fast path on tiles fully below this warp's diagonal.
#define STAGE_ATT 16384
#define SMEM_ATTN (16384 + 2*STAGE_ATT)
#define SCALE2 0.180336880556f   /* 0.125 * log2(e) */
__global__ __launch_bounds__(256) void attn_kernel(
    const __half* __restrict__ Q, __half* __restrict__ C)
{
    extern __shared__ char smem[];
    uint32_t sb = smem_to_u32(smem);
    int t = threadIdx.x, w = t >> 5, lane = t & 31;
    int qt = gridDim.x - 1 - blockIdx.x;
    int bh_ = blockIdx.y;
    int h = bh_ & 15;
    size_t rowOff = (size_t)(bh_ >> 4) * SEQ;      // batch row offset
    int q0 = qt * 128;
    int colQ = h*64, colK = 1024 + h*64, colV = 2048 + h*64;

    // ---- async load Q ----
    #pragma unroll
    for (int i = 0; i < 4; i++) {
        int id = t + 256*i;
        int row = id >> 3, c16 = id & 7;
        const __half* gp = Q + (rowOff + q0 + row)*QKV_STR + colQ + c16*8;
        cp16(sb + SWZ((uint32_t)(row*128 + c16*16)), gp);
    }
    CP_COMMIT();

    int nkt = 2*qt + 2;

    // issue K/V stage: K @0, V @8192
    auto issue = [&](int kt, int buf) {
        uint32_t stb = sb + 16384 + buf*STAGE_ATT;
        int k0 = kt*64;
        #pragma unroll
        for (int i = 0; i < 4; i++) {
            int id = t + 256*i;
            int arr = id >> 9;           // 0 K, 1 V
            int cid = id & 511;
            int row = cid >> 3, c16 = cid & 7;
            int col = (arr == 0) ? colK : colV;
            const __half* gp = Q + (rowOff + k0 + row)*QKV_STR + col + c16*8;
            cp16(stb + arr*8192 + SWZ((uint32_t)(row*128 + c16*16)), gp);
        }
    };
    issue(0, 0);
    CP_COMMIT();
    CP_WAIT(1);          // Q ready
    __syncthreads();

    // ---- Q fragments to registers ----
    uint32_t qh[4][4];
    {
        int arow = lane & 15;
        int acol = (lane >> 4) << 4;
        #pragma unroll
        for (int kf = 0; kf < 4; kf++) {
            uint32_t off = SWZ((uint32_t)((w*16 + arow)*128 + kf*32 + acol));
            ldsm4(qh[kf], sb + off);
        }
    }

    float o[8][4];
    #pragma unroll
    for (int nt = 0; nt < 8; nt++)
        #pragma unroll
        for (int e = 0; e < 4; e++) o[nt][e] = 0.0f;
    float mst0 = -1e30f, mst1 = -1e30f, lst0 = 0.0f, lst1 = 0.0f;

    int r0g = q0 + w*16 + (lane >> 2);
    int r1g = r0g + 8;
    int wRowMin = q0 + w*16;

    for (int kt = 0; kt < nkt; kt++) {
        int buf = kt & 1;
        if (kt + 1 < nkt) issue(kt+1, buf^1);
        CP_COMMIT();
        if (kt + 1 < nkt) { CP_WAIT(1); } else { CP_WAIT(0); }
        __syncthreads();

        int k0 = kt*64;
        if (k0 <= wRowMin + 15) {       // at least one unmasked element for this warp
            uint32_t stb = sb + 16384 + buf*STAGE_ATT;
            uint32_t kB = stb, vB = stb + 8192;
            bool needMask = (k0 + 63) > wRowMin;   // tile crosses this warp's diagonal?

            // ---- S = Q @ K^T ----
            float s[8][4];
            #pragma unroll
            for (int nt = 0; nt < 8; nt++)
                #pragma unroll
                for (int e = 0; e < 4; e++) s[nt][e] = 0.0f;
            {
                int brow = ((lane >> 4) << 3) + (lane & 7);
                int bcol = ((lane >> 3) & 1) << 4;
                #pragma unroll
                for (int ks = 0; ks < 4; ks++) {
                    int kb = ks*32;
                    #pragma unroll
                    for (int nh = 0; nh < 4; nh++) {
                        uint32_t off = SWZ((uint32_t)((nh*16 + brow)*128 + kb + bcol));
                        uint32_t rb[4];
                        ldsm4(rb, kB + off);
                        uint32_t b0[2] = { rb[0], rb[1] }, b1[2] = { rb[2], rb[3] };
                        mma_f16(s[2*nh],   qh[ks], b0);
                        mma_f16(s[2*nh+1], qh[ks], b1);
                    }
                }
            }

            // ---- scale (log2 domain) (+ causal mask on diagonal tiles) + max ----
            float mx0 = -1e30f, mx1 = -1e30f;
            if (needMask) {
                #pragma unroll
                for (int nt = 0; nt < 8; nt++) {
                    int kgBase = k0 + nt*8 + ((lane & 3) << 1);
                    #pragma unroll
                    for (int e = 0; e < 4; e++) {
                        float v = s[nt][e] * SCALE2;
                        int kg = kgBase + (e & 1);
                        int qg = (e < 2) ? r0g : r1g;
                        v = (kg <= qg) ? v : -1e30f;
                        s[nt][e] = v;
                        if (e < 2) mx0 = fmaxf(mx0, v); else mx1 = fmaxf(mx1, v);
                    }
                }
            } else {
                #pragma unroll
                for (int nt = 0; nt < 8; nt++) {
                    float v0 = s[nt][0] * SCALE2, v1 = s[nt][1] * SCALE2;
                    float v2 = s[nt][2] * SCALE2, v3 = s[nt][3] * SCALE2;
                    s[nt][0] = v0; s[nt][1] = v1; s[nt][2] = v2; s[nt][3] = v3;
                    mx0 = fmaxf(mx0, fmaxf(v0, v1));
                    mx1 = fmaxf(mx1, fmaxf(v2, v3));
                }
            }
            mx0 = fmaxf(mx0, __shfl_xor_sync(0xffffffffu, mx0, 1));
            mx0 = fmaxf(mx0, __shfl_xor_sync(0xffffffffu, mx0, 2));
            mx1 = fmaxf(mx1, __shfl_xor_sync(0xffffffffu, mx1, 1));
            mx1 = fmaxf(mx1, __shfl_xor_sync(0xffffffffu, mx1, 2));
            float mn0 = fmaxf(mst0, mx0), mn1 = fmaxf(mst1, mx1);
            float a0 = exp2f(mst0 - mn0), a1 = exp2f(mst1 - mn1);
            mst0 = mn0; mst1 = mn1;
            float s0 = 0.0f, s1 = 0.0f;
            #pragma unroll
            for (int nt = 0; nt < 8; nt++) {
                float p0 = exp2f(s[nt][0] - mn0);
                float p1 = exp2f(s[nt][1] - mn0);
                float p2 = exp2f(s[nt][2] - mn1);
                float p3 = exp2f(s[nt][3] - mn1);
                s[nt][0] = p0; s[nt][1] = p1; s[nt][2] = p2; s[nt][3] = p3;
                s0 += p0 + p1; s1 += p2 + p3;
            }
            s0 += __shfl_xor_sync(0xffffffffu, s0, 1);
            s0 += __shfl_xor_sync(0xffffffffu, s0, 2);
            s1 += __shfl_xor_sync(0xffffffffu, s1, 1);
            s1 += __shfl_xor_sync(0xffffffffu, s1, 2);
            lst0 = lst0*a0 + s0;
            lst1 = lst1*a1 + s1;
            #pragma unroll
            for (int nt = 0; nt < 8; nt++) {
                o[nt][0] *= a0; o[nt][1] *= a0;
                o[nt][2] *= a1; o[nt][3] *= a1;
            }

            // ---- O += P @ V, P single fp16 ----
            #pragma unroll
            for (int kk = 0; kk < 4; kk++) {
                uint32_t ph[4];
                ph[0] = cvt2h1(s[2*kk][0],   s[2*kk][1]);
                ph[1] = cvt2h1(s[2*kk][2],   s[2*kk][3]);
                ph[2] = cvt2h1(s[2*kk+1][0], s[2*kk+1][1]);
                ph[3] = cvt2h1(s[2*kk+1][2], s[2*kk+1][3]);
                #pragma unroll
                for (int nv = 0; nv < 4; nv++) {
                    uint32_t off = SWZ((uint32_t)((kk*16 + (lane & 15))*128 + (nv*16 + 8*(lane >> 4))*2));
                    uint32_t rh[4];
                    ldsm4t(rh, vB + off);
                    uint32_t b0[2] = { rh[0], rh[1] }, b1[2] = { rh[2], rh[3] };
                    mma_f16(o[2*nv],   ph, b0);
                    mma_f16(o[2*nv+1], ph, b1);
                }
            }
        }
        __syncthreads();
    }

    // ---- epilogue: O/l -> fp16 ctx ----
    float li0 = 1.0f / lst0, li1 = 1.0f / lst1;
    int colB = h*64 + ((lane & 3) << 1);
    size_t row0 = rowOff + r0g, row1 = rowOff + r1g;
    #pragma unroll
    for (int nt = 0; nt < 8; nt++) {
        int col = colB + nt*8;
        *(uint32_t*)(C + row0*EMB + col) = cvt2h1(o[nt][0]*li0, o[nt][1]*li0);
        *(uint32_t*)(C + row1*EMB + col) = cvt2h1(o[nt][2]*li1, o[nt][3]*li1);
    }
}

// ---------------- launch ----------------
extern "C" void kernel_launch(void* const* d_in, const int* in_sizes, int n_in,
                              void* d_out, int out_size)
{
    const float* x  = (const float*)d_in[0];
    const float* Wq = (const float*)d_in[1];
    const float* Wk = (const float*)d_in[2];
    const float* Wv = (const float*)d_in[3];
    const float* Wo = (const float*)d_in[4];
    const float* bo = (const float*)d_in[5];
    const float* W1 = (const float*)d_in[6];
    const float* b1 = (const float*)d_in[7];
    const float* W2 = (const float*)d_in[8];
    const float* b2 = (const float*)d_in[9];
    const float* g1 = (const float*)d_in[10];
    const float* s1 = (const float*)d_in[11];
    const float* g2 = (const float*)d_in[12];
    const float* s2 = (const float*)d_in[13];
    float* out = (float*)d_out;

    __half *ln1, *qkv, *ctx, *y, *ff;
    __half *wqkvt, *wot, *w1t, *w2t;
    float *h;
    cudaGetSymbolAddress((void**)&ln1,  g_ln1);
    cudaGetSymbolAddress((void**)&qkv,  g_qkv);
    cudaGetSymbolAddress((void**)&ctx,  g_ctx);
    cudaGetSymbolAddress((void**)&h,    g_h);
    cudaGetSymbolAddress((void**)&y,    g_y);
    cudaGetSymbolAddress((void**)&ff,   g_ff);
    cudaGetSymbolAddress((void**)&wqkvt, g_wqkvt);
    cudaGetSymbolAddress((void**)&wot,  g_wot);
    cudaGetSymbolAddress((void**)&w1t,  g_w1t);
    cudaGetSymbolAddress((void**)&w2t,  g_w2t);

    cudaFuncSetAttribute(gemm_mma, cudaFuncAttributeMaxDynamicSharedMemorySize, SMEM_GEMM);
    cudaFuncSetAttribute(attn_kernel, cudaFuncAttributeMaxDynamicSharedMemorySize, SMEM_ATTN);

    dim3 blk(256);

    // launch order: my idx 3 = attn_kernel -> ncu capture slot
    wconv_qkv_kernel<<<dim3(32, 32, 3), blk>>>(Wq, Wk, Wv, wqkvt);                   // 0
    ln_kernel<<<ROWS, blk>>>(x, g1, s1, ln1);                                        // 1
    gemm_mma<<<dim3(QKV_STR/128, ROWS/128), blk, SMEM_GEMM>>>(                       // 2
        ln1, wqkvt, nullptr, nullptr, nullptr, qkv, ROWS, QKV_STR, EMB, 0);
    attn_kernel<<<dim3(SEQ/128, BATCH*NHEADS), blk, SMEM_ATTN>>>(qkv, ctx);          // 3 <- profiled
    wconv_rest_kernel<<<dim3(32, 32, 9), blk>>>(Wo, W1, W2, wot, w1t, w2t);          // 4
    gemm_mma<<<dim3(EMB/128, ROWS/128), blk, SMEM_GEMM>>>(                           // 5
        ctx, wot, bo, x, h, nullptr, ROWS, EMB, EMB, 0);
    ln_kernel<<<ROWS, blk>>>(h, g2, s2, y);                                          // 6
    gemm_mma<<<dim3(DFF/128, ROWS/128), blk, SMEM_GEMM>>>(                           // 7
        y, w1t, b1, nullptr, nullptr, ff, ROWS, DFF, EMB, 1);
    gemm_mma<<<dim3(EMB/128, ROWS/128), blk, SMEM_GEMM>>>(                           // 8
        ff, w2t, b2, h, out, nullptr, ROWS, EMB, DFF, 0);
}